// round 1
// baseline (speedup 1.0000x reference)
#include <cuda_runtime.h>
#include <math.h>

#define BATCH 2
#define SEQ   2048
#define HID   4096
#define NHEAD 32
#define HDIM  128
#define TOKENS (BATCH * SEQ)     // 4096
#define QKVN  (3 * HID)          // 12288

// ---------------- scratch (device globals; no allocation allowed) ----------
__device__ float g_qkv[(size_t)TOKENS * QKVN];                 // 192 MB
__device__ float g_q[(size_t)BATCH * NHEAD * SEQ * HDIM];      // 64 MB
__device__ float g_k[(size_t)BATCH * NHEAD * SEQ * HDIM];      // 64 MB
__device__ float g_v[(size_t)BATCH * NHEAD * SEQ * HDIM];      // 64 MB
__device__ float g_attn[(size_t)TOKENS * HID];                 // 64 MB

// ---------------- classic 128x128x16 double-buffered SGEMM -----------------
// C[M,N] = A[M,K] @ B[K,N], all row-major, M%128==0, N%128==0, K%16==0.
__global__ __launch_bounds__(256) void sgemm128(const float* __restrict__ A,
                                                const float* __restrict__ B,
                                                float* __restrict__ C,
                                                int M, int N, int K)
{
    __shared__ float As[2][16][132];   // transposed A tile, padded
    __shared__ float Bs[2][16][128];

    const int tid = threadIdx.x;
    const int bm = blockIdx.y;
    const int bn = blockIdx.x;

    const float* Ag = A + (size_t)bm * 128 * K;
    const float* Bg = B + (size_t)bn * 128;

    const int aRow = tid >> 2;          // 0..63 (and +64)
    const int aCol = (tid & 3) << 2;    // 0,4,8,12
    const int bRow = tid >> 5;          // 0..7 (and +8)
    const int bCol = (tid & 31) << 2;   // 0..124

    const int tr = (tid >> 4) << 2;     // 0..60
    const int tc = (tid & 15) << 2;     // 0..60

    float acc[8][8];
#pragma unroll
    for (int i = 0; i < 8; ++i)
#pragma unroll
        for (int j = 0; j < 8; ++j) acc[i][j] = 0.f;

    // prologue: tile 0
    {
        float4 a0 = *(const float4*)(Ag + (size_t)aRow * K + aCol);
        float4 a1 = *(const float4*)(Ag + (size_t)(aRow + 64) * K + aCol);
        float4 b0 = *(const float4*)(Bg + (size_t)bRow * N + bCol);
        float4 b1 = *(const float4*)(Bg + (size_t)(bRow + 8) * N + bCol);
        As[0][aCol + 0][aRow] = a0.x; As[0][aCol + 1][aRow] = a0.y;
        As[0][aCol + 2][aRow] = a0.z; As[0][aCol + 3][aRow] = a0.w;
        As[0][aCol + 0][aRow + 64] = a1.x; As[0][aCol + 1][aRow + 64] = a1.y;
        As[0][aCol + 2][aRow + 64] = a1.z; As[0][aCol + 3][aRow + 64] = a1.w;
        *(float4*)&Bs[0][bRow][bCol] = b0;
        *(float4*)&Bs[0][bRow + 8][bCol] = b1;
    }
    __syncthreads();

    const int nk = K >> 4;
    for (int kt = 0; kt < nk; ++kt) {
        const int cur = kt & 1;
        float4 na0, na1, nb0, nb1;
        const bool more = (kt + 1 < nk);
        if (more) {
            const float* Ag2 = Ag + (kt + 1) * 16;
            const float* Bg2 = Bg + (size_t)(kt + 1) * 16 * N;
            na0 = *(const float4*)(Ag2 + (size_t)aRow * K + aCol);
            na1 = *(const float4*)(Ag2 + (size_t)(aRow + 64) * K + aCol);
            nb0 = *(const float4*)(Bg2 + (size_t)bRow * N + bCol);
            nb1 = *(const float4*)(Bg2 + (size_t)(bRow + 8) * N + bCol);
        }
#pragma unroll
        for (int kk = 0; kk < 16; ++kk) {
            float4 t0 = *(const float4*)&As[cur][kk][tr];
            float4 t1 = *(const float4*)&As[cur][kk][tr + 64];
            float4 t2 = *(const float4*)&Bs[cur][kk][tc];
            float4 t3 = *(const float4*)&Bs[cur][kk][tc + 64];
            float ra[8] = {t0.x, t0.y, t0.z, t0.w, t1.x, t1.y, t1.z, t1.w};
            float rb[8] = {t2.x, t2.y, t2.z, t2.w, t3.x, t3.y, t3.z, t3.w};
#pragma unroll
            for (int i = 0; i < 8; ++i)
#pragma unroll
                for (int j = 0; j < 8; ++j)
                    acc[i][j] = fmaf(ra[i], rb[j], acc[i][j]);
        }
        if (more) {
            const int nxt = cur ^ 1;
            As[nxt][aCol + 0][aRow] = na0.x; As[nxt][aCol + 1][aRow] = na0.y;
            As[nxt][aCol + 2][aRow] = na0.z; As[nxt][aCol + 3][aRow] = na0.w;
            As[nxt][aCol + 0][aRow + 64] = na1.x; As[nxt][aCol + 1][aRow + 64] = na1.y;
            As[nxt][aCol + 2][aRow + 64] = na1.z; As[nxt][aCol + 3][aRow + 64] = na1.w;
            *(float4*)&Bs[nxt][bRow][bCol] = nb0;
            *(float4*)&Bs[nxt][bRow + 8][bCol] = nb1;
        }
        __syncthreads();
    }

    float* Cg = C + (size_t)bm * 128 * N + bn * 128;
#pragma unroll
    for (int i = 0; i < 4; ++i) {
        float* r0p = Cg + (size_t)(tr + i) * N;
        float* r1p = Cg + (size_t)(tr + 64 + i) * N;
        *(float4*)(r0p + tc)      = make_float4(acc[i][0], acc[i][1], acc[i][2], acc[i][3]);
        *(float4*)(r0p + tc + 64) = make_float4(acc[i][4], acc[i][5], acc[i][6], acc[i][7]);
        *(float4*)(r1p + tc)      = make_float4(acc[i + 4][0], acc[i + 4][1], acc[i + 4][2], acc[i + 4][3]);
        *(float4*)(r1p + tc + 64) = make_float4(acc[i + 4][4], acc[i + 4][5], acc[i + 4][6], acc[i + 4][7]);
    }
}

// ---------------- RoPE (NeoX) + split/transpose to head-major --------------
__global__ __launch_bounds__(128) void rope_split(const float* __restrict__ qkv,
                                                  const int* __restrict__ pos_ids,
                                                  float* __restrict__ Qh,
                                                  float* __restrict__ Kh,
                                                  float* __restrict__ Vh)
{
    const int token = blockIdx.x;         // 0..TOKENS-1
    const int b = token / SEQ;
    const int s = token % SEQ;
    __shared__ float cs[64], sn[64];
    const int tid = threadIdx.x;
    if (tid < 64) {
        // inv_freq = 10000^(-2i/128); compute in double so our error << ref's fp32 error
        double inv = exp(-9.210340371976184 * ((double)(2 * tid) / 128.0));
        double ang = (double)pos_ids[token] * inv;
        cs[tid] = (float)cos(ang);
        sn[tid] = (float)sin(ang);
    }
    __syncthreads();
    const float* base = qkv + (size_t)token * QKVN;

    for (int p = tid; p < NHEAD * 64; p += 128) {
        int h = p >> 6;
        int i = p & 63;
        float c = cs[i], sv = sn[i];
        size_t ob = ((size_t)(b * NHEAD + h) * SEQ + s) * HDIM;
        float q1 = base[h * HDIM + i];
        float q2 = base[h * HDIM + 64 + i];
        Qh[ob + i]      = q1 * c - q2 * sv;
        Qh[ob + 64 + i] = q2 * c + q1 * sv;
        float k1 = base[HID + h * HDIM + i];
        float k2 = base[HID + h * HDIM + 64 + i];
        Kh[ob + i]      = k1 * c - k2 * sv;
        Kh[ob + 64 + i] = k2 * c + k1 * sv;
    }
    for (int p = tid; p < HID; p += 128) {
        int h = p >> 7;
        int d = p & 127;
        Vh[((size_t)(b * NHEAD + h) * SEQ + s) * HDIM + d] = base[2 * HID + p];
    }
}

// ---------------- fp32 flash attention (causal), 64x64 tiles ---------------
__global__ __launch_bounds__(256) void flash_attn_f32(const float* __restrict__ Qg,
                                                      const float* __restrict__ Kg,
                                                      const float* __restrict__ Vg,
                                                      float* __restrict__ Og)
{
    extern __shared__ float smbuf[];
    const int QP = 68;                         // padded row stride (16B-aligned, bank-spread)
    float* Qs = smbuf;                         // [128][68] d-major
    float* Ks = Qs + 128 * QP;                 // [128][68] d-major
    float* Vs = Ks + 128 * QP;                 // [64][128]
    float* Ps = Vs + 64 * HDIM;                // [64][68]  c-major (transposed P)

    const int tid = threadIdx.x;
    const int qt = (int)(gridDim.x - 1 - blockIdx.x);  // biggest workload first
    const int h = blockIdx.y;
    const int b = blockIdx.z;
    const size_t headoff = (size_t)(b * NHEAD + h) * SEQ * HDIM;
    const float* Qh = Qg + headoff;
    const float* Kh = Kg + headoff;
    const float* Vh = Vg + headoff;
    const int qbase = qt * 64;

    // load Q tile transposed: Qs[d][r]
#pragma unroll
    for (int it = 0; it < 8; ++it) {
        int idx = tid + it * 256;
        int r = idx >> 5;
        int d4 = (idx & 31) << 2;
        float4 x = *(const float4*)(Qh + (size_t)(qbase + r) * HDIM + d4);
        Qs[(d4 + 0) * QP + r] = x.x;
        Qs[(d4 + 1) * QP + r] = x.y;
        Qs[(d4 + 2) * QP + r] = x.z;
        Qs[(d4 + 3) * QP + r] = x.w;
    }

    const int sr  = (tid >> 4) << 2;   // this thread's 4 rows (fixed across phases)
    const int sc4 = (tid & 15) << 2;   // 4 score cols
    const int ec  = (tid & 15) << 3;   // 8 output cols

    float m_i[4], l_i[4], o[4][8];
#pragma unroll
    for (int i = 0; i < 4; ++i) {
        m_i[i] = -1e30f; l_i[i] = 0.f;
#pragma unroll
        for (int j = 0; j < 8; ++j) o[i][j] = 0.f;
    }
    const float scale = 0.08838834764831845f;   // 1/sqrt(128)

    __syncthreads();

    for (int kt = 0; kt <= qt; ++kt) {
        const int kbase = kt * 64;
        // load K (transposed) and V tiles
#pragma unroll
        for (int it = 0; it < 8; ++it) {
            int idx = tid + it * 256;
            int r = idx >> 5;
            int d4 = (idx & 31) << 2;
            float4 x = *(const float4*)(Kh + (size_t)(kbase + r) * HDIM + d4);
            Ks[(d4 + 0) * QP + r] = x.x;
            Ks[(d4 + 1) * QP + r] = x.y;
            Ks[(d4 + 2) * QP + r] = x.z;
            Ks[(d4 + 3) * QP + r] = x.w;
            float4 y = *(const float4*)(Vh + (size_t)(kbase + r) * HDIM + d4);
            *(float4*)&Vs[r * HDIM + d4] = y;
        }
        __syncthreads();

        // S = Q K^T (4x4 per thread)
        float s[4][4];
#pragma unroll
        for (int i = 0; i < 4; ++i)
#pragma unroll
            for (int j = 0; j < 4; ++j) s[i][j] = 0.f;

#pragma unroll 8
        for (int d = 0; d < HDIM; ++d) {
            float4 qa = *(const float4*)&Qs[d * QP + sr];
            float4 kb = *(const float4*)&Ks[d * QP + sc4];
            float ra[4] = {qa.x, qa.y, qa.z, qa.w};
            float rb[4] = {kb.x, kb.y, kb.z, kb.w};
#pragma unroll
            for (int i = 0; i < 4; ++i)
#pragma unroll
                for (int j = 0; j < 4; ++j)
                    s[i][j] = fmaf(ra[i], rb[j], s[i][j]);
        }

        // online softmax (rows owned by 16-lane groups; shfl reductions)
#pragma unroll
        for (int i = 0; i < 4; ++i) {
            const int qg = qbase + sr + i;
            float rm = -1e30f;
#pragma unroll
            for (int j = 0; j < 4; ++j) {
                const int kg = kbase + sc4 + j;
                float val = (kg <= qg) ? s[i][j] * scale : -1e30f;
                s[i][j] = val;
                rm = fmaxf(rm, val);
            }
#pragma unroll
            for (int off = 8; off > 0; off >>= 1)
                rm = fmaxf(rm, __shfl_xor_sync(0xffffffffu, rm, off));
            const float mnew = fmaxf(m_i[i], rm);
            const float alpha = __expf(m_i[i] - mnew);
            float acc = 0.f;
#pragma unroll
            for (int j = 0; j < 4; ++j) {
                float p = __expf(s[i][j] - mnew);
                s[i][j] = p;
                acc += p;
            }
#pragma unroll
            for (int off = 8; off > 0; off >>= 1)
                acc += __shfl_xor_sync(0xffffffffu, acc, off);
            l_i[i] = l_i[i] * alpha + acc;
            m_i[i] = mnew;
#pragma unroll
            for (int j = 0; j < 8; ++j) o[i][j] *= alpha;
        }

        // store P transposed: Ps[c][r]
#pragma unroll
        for (int j = 0; j < 4; ++j)
            *(float4*)&Ps[(sc4 + j) * QP + sr] =
                make_float4(s[0][j], s[1][j], s[2][j], s[3][j]);
        __syncthreads();

        // O += P V (same rows sr.., cols ec..ec+7)
#pragma unroll 4
        for (int c = 0; c < 64; ++c) {
            float4 pa = *(const float4*)&Ps[c * QP + sr];
            float pr[4] = {pa.x, pa.y, pa.z, pa.w};
            float4 v0 = *(const float4*)&Vs[c * HDIM + ec];
            float4 v1 = *(const float4*)&Vs[c * HDIM + ec + 4];
            float vv[8] = {v0.x, v0.y, v0.z, v0.w, v1.x, v1.y, v1.z, v1.w};
#pragma unroll
            for (int i = 0; i < 4; ++i)
#pragma unroll
                for (int j = 0; j < 8; ++j)
                    o[i][j] = fmaf(pr[i], vv[j], o[i][j]);
        }
        __syncthreads();
    }

    // normalize + write [B,S,H] layout
#pragma unroll
    for (int i = 0; i < 4; ++i) {
        const float inv = 1.0f / l_i[i];
        size_t off = ((size_t)b * SEQ + qbase + sr + i) * HID + h * HDIM + ec;
        *(float4*)(Og + off)     = make_float4(o[i][0] * inv, o[i][1] * inv, o[i][2] * inv, o[i][3] * inv);
        *(float4*)(Og + off + 4) = make_float4(o[i][4] * inv, o[i][5] * inv, o[i][6] * inv, o[i][7] * inv);
    }
}

// ---------------------------------------------------------------------------
extern "C" void kernel_launch(void* const* d_in, const int* in_sizes, int n_in,
                              void* d_out, int out_size)
{
    (void)in_sizes; (void)n_in; (void)out_size;
    const float* hidden = (const float*)d_in[0];
    const float* w_qkv  = (const float*)d_in[1];
    const float* w_o    = (const float*)d_in[2];
    const int*   pos    = (const int*)d_in[3];
    float* out = (float*)d_out;

    float *qkv, *q, *k, *v, *attn;
    cudaGetSymbolAddress((void**)&qkv,  g_qkv);
    cudaGetSymbolAddress((void**)&q,    g_q);
    cudaGetSymbolAddress((void**)&k,    g_k);
    cudaGetSymbolAddress((void**)&v,    g_v);
    cudaGetSymbolAddress((void**)&attn, g_attn);

    // 1) QKV projection: [4096,4096] @ [4096,12288]
    sgemm128<<<dim3(QKVN / 128, TOKENS / 128), 256>>>(hidden, w_qkv, qkv, TOKENS, QKVN, HID);

    // 2) RoPE + split to head-major Q/K/V
    rope_split<<<TOKENS, 128>>>(qkv, pos, q, k, v);

    // 3) causal flash attention
    const int att_smem = (128 * 68 * 2 + 64 * 128 + 64 * 68) * 4;  // 119808 B
    cudaFuncSetAttribute(flash_attn_f32, cudaFuncAttributeMaxDynamicSharedMemorySize, att_smem);
    flash_attn_f32<<<dim3(SEQ / 64, NHEAD, BATCH), 256, att_smem>>>(q, k, v, attn);

    // 4) output projection: [4096,4096] @ [4096,4096]
    sgemm128<<<dim3(HID / 128, TOKENS / 128), 256>>>(attn, w_o, out, TOKENS, HID, HID);
}

// round 3
// speedup vs baseline: 2.1528x; 2.1528x over previous
#include <cuda_runtime.h>
#include <cuda_bf16.h>
#include <math.h>
#include <stdint.h>

#define BATCH 2
#define SEQ   2048
#define HID   4096
#define NHEAD 32
#define HDIM  128
#define TOKENS (BATCH * SEQ)     // 4096
#define QKVN  (3 * HID)          // 12288

// ---------------- scratch (device globals; no allocation allowed) ----------
__device__ float g_qkv[(size_t)TOKENS * QKVN];                 // 192 MB
__device__ float g_q[(size_t)BATCH * NHEAD * SEQ * HDIM];      // 64 MB
__device__ float g_k[(size_t)BATCH * NHEAD * SEQ * HDIM];      // 64 MB
__device__ float g_v[(size_t)BATCH * NHEAD * SEQ * HDIM];      // 64 MB
__device__ float g_attn[(size_t)TOKENS * HID];                 // 64 MB
__device__ float g_wqkvt[(size_t)QKVN * HID];                  // 192 MB  w_qkv^T [N,K]
__device__ float g_wot[(size_t)HID * HID];                     // 64 MB   w_o^T   [N,K]

// ======================= helpers ==================================
__device__ __forceinline__ uint32_t smem_u32_of(const void* p) {
    uint32_t a;
    asm("{ .reg .u64 t; cvta.to.shared.u64 t, %1; cvt.u32.u64 %0, t; }" : "=r"(a) : "l"(p));
    return a;
}
__device__ __forceinline__ void ldm_x4(uint32_t* r, uint32_t addr) {
    asm volatile("ldmatrix.sync.aligned.m8n8.x4.shared.b16 {%0,%1,%2,%3}, [%4];"
                 : "=r"(r[0]), "=r"(r[1]), "=r"(r[2]), "=r"(r[3]) : "r"(addr));
}
__device__ __forceinline__ void mma_bf16(float* d, const uint32_t* a, uint32_t b0, uint32_t b1) {
    asm volatile(
        "mma.sync.aligned.m16n8k16.row.col.f32.bf16.bf16.f32 "
        "{%0,%1,%2,%3},{%4,%5,%6,%7},{%8,%9},{%0,%1,%2,%3};"
        : "+f"(d[0]), "+f"(d[1]), "+f"(d[2]), "+f"(d[3])
        : "r"(a[0]), "r"(a[1]), "r"(a[2]), "r"(a[3]), "r"(b0), "r"(b1));
}
// split fp32 -> bf16 hi + bf16 lo (residual)
__device__ __forceinline__ void bfsplit(float x, __nv_bfloat16& hi, __nv_bfloat16& lo) {
    hi = __float2bfloat16_rn(x);
    lo = __float2bfloat16_rn(x - __bfloat162float(hi));
}

// ============ bf16x3 compensated tensor-core GEMM ====================
// C[M,N] = A[M,K] @ Bt[N,K]^T. Tile 128x128, K-chunk 32, 8 warps (4M x 2N).
#define KC  32
#define KCP 40    // padded row stride (elements)

__global__ __launch_bounds__(256, 1) void gemm_bf16x3(const float* __restrict__ A,
                                                      const float* __restrict__ Bt,
                                                      float* __restrict__ C,
                                                      int M, int N, int K, int Mtiles)
{
    __shared__ __align__(16) __nv_bfloat16 sAh[128 * KCP];
    __shared__ __align__(16) __nv_bfloat16 sAl[128 * KCP];
    __shared__ __align__(16) __nv_bfloat16 sBh[128 * KCP];
    __shared__ __align__(16) __nv_bfloat16 sBl[128 * KCP];

    const int tid = threadIdx.x;
    const int warp = tid >> 5, lane = tid & 31;
    const int wm = warp & 3;          // 4 warps along M (32 rows each)
    const int wn = warp >> 2;         // 2 warps along N (64 cols each)

    // supertile rasterization: groups of 8 N-tiles, M fastest
    const int bx = blockIdx.x;
    const int group = bx / (Mtiles * 8);
    const int rr = bx % (Mtiles * 8);
    const int bm = rr % Mtiles;
    const int bn = group * 8 + rr / Mtiles;

    const float* Ap = A + (size_t)bm * 128 * K;
    const float* Bp = Bt + (size_t)bn * 128 * K;

    // gmem staging: each thread 4 float4 from A, 4 from B per chunk
    const int grow = tid >> 3;          // 0..31
    const int gcol = (tid & 7) << 2;    // 0..28

    // ldmatrix lane addressing
    const int lrow = lane & 15;
    const int lkh = (lane >> 4) << 3;   // 0 or 8

    const uint32_t uAh = smem_u32_of(sAh);
    const uint32_t uAl = smem_u32_of(sAl);
    const uint32_t uBh = smem_u32_of(sBh);
    const uint32_t uBl = smem_u32_of(sBl);

    float acc[2][8][4];
#pragma unroll
    for (int t = 0; t < 2; ++t)
#pragma unroll
        for (int n = 0; n < 8; ++n)
#pragma unroll
            for (int i = 0; i < 4; ++i) acc[t][n][i] = 0.f;

    float4 pa[4], pb[4];
#pragma unroll
    for (int it = 0; it < 4; ++it) {
        pa[it] = *(const float4*)(Ap + (size_t)(grow + it * 32) * K + gcol);
        pb[it] = *(const float4*)(Bp + (size_t)(grow + it * 32) * K + gcol);
    }

    const int nchunks = K / KC;
    for (int c = 0; c < nchunks; ++c) {
        // split + store to smem (packed as 4 x bf16 = 8B)
#pragma unroll
        for (int it = 0; it < 4; ++it) {
            const int row = grow + it * 32;
            const int eoff = row * KCP + gcol;
            __nv_bfloat16 h[4], l[4];
            bfsplit(pa[it].x, h[0], l[0]); bfsplit(pa[it].y, h[1], l[1]);
            bfsplit(pa[it].z, h[2], l[2]); bfsplit(pa[it].w, h[3], l[3]);
            *(uint2*)(sAh + eoff) = *(uint2*)h;
            *(uint2*)(sAl + eoff) = *(uint2*)l;
            bfsplit(pb[it].x, h[0], l[0]); bfsplit(pb[it].y, h[1], l[1]);
            bfsplit(pb[it].z, h[2], l[2]); bfsplit(pb[it].w, h[3], l[3]);
            *(uint2*)(sBh + eoff) = *(uint2*)h;
            *(uint2*)(sBl + eoff) = *(uint2*)l;
        }
        __syncthreads();

        // prefetch next chunk
        if (c + 1 < nchunks) {
            const int kc = (c + 1) * KC;
#pragma unroll
            for (int it = 0; it < 4; ++it) {
                pa[it] = *(const float4*)(Ap + (size_t)(grow + it * 32) * K + kc + gcol);
                pb[it] = *(const float4*)(Bp + (size_t)(grow + it * 32) * K + kc + gcol);
            }
        }

        // compute: 2 k16 steps
#pragma unroll
        for (int ks = 0; ks < 2; ++ks) {
            uint32_t ah[2][4], al[2][4];
#pragma unroll
            for (int t = 0; t < 2; ++t) {
                const uint32_t aoff =
                    (uint32_t)(((wm * 32 + t * 16 + lrow) * KCP + ks * 16 + lkh) * 2);
                ldm_x4(ah[t], uAh + aoff);
                ldm_x4(al[t], uAl + aoff);
            }
#pragma unroll
            for (int nt = 0; nt < 4; ++nt) {
                uint32_t bh[4], bl[4];
                const uint32_t boff =
                    (uint32_t)(((wn * 64 + nt * 16 + lrow) * KCP + ks * 16 + lkh) * 2);
                ldm_x4(bh, uBh + boff);
                ldm_x4(bl, uBl + boff);
#pragma unroll
                for (int t = 0; t < 2; ++t) {
                    // n8 tile (2*nt): frag {r0, r2}; tile (2*nt+1): {r1, r3}
                    mma_bf16(acc[t][2 * nt],     ah[t], bh[0], bh[2]);
                    mma_bf16(acc[t][2 * nt],     ah[t], bl[0], bl[2]);
                    mma_bf16(acc[t][2 * nt],     al[t], bh[0], bh[2]);
                    mma_bf16(acc[t][2 * nt + 1], ah[t], bh[1], bh[3]);
                    mma_bf16(acc[t][2 * nt + 1], ah[t], bl[1], bl[3]);
                    mma_bf16(acc[t][2 * nt + 1], al[t], bh[1], bh[3]);
                }
            }
        }
        __syncthreads();
    }

    // epilogue: fragment layout -> gmem
    const int g = lane >> 2;
    const int tc2 = (lane & 3) << 1;
#pragma unroll
    for (int t = 0; t < 2; ++t) {
        const int row0 = bm * 128 + wm * 32 + t * 16 + g;
#pragma unroll
        for (int n = 0; n < 8; ++n) {
            const int col = bn * 128 + wn * 64 + n * 8 + tc2;
            *(float2*)(C + (size_t)row0 * N + col) = make_float2(acc[t][n][0], acc[t][n][1]);
            *(float2*)(C + (size_t)(row0 + 8) * N + col) = make_float2(acc[t][n][2], acc[t][n][3]);
        }
    }
}

// ---------------- transpose: out[c][r] = in[r][c] ---------------------------
__global__ __launch_bounds__(256) void transpose_f32(const float* __restrict__ in,
                                                     float* __restrict__ out,
                                                     int R, int Cc)
{
    __shared__ float t[32][33];
    const int c = blockIdx.x * 32 + threadIdx.x;
    const int r0 = blockIdx.y * 32 + threadIdx.y;
#pragma unroll
    for (int i = 0; i < 4; ++i)
        t[threadIdx.y + i * 8][threadIdx.x] = in[(size_t)(r0 + i * 8) * Cc + c];
    __syncthreads();
    const int rc = blockIdx.y * 32 + threadIdx.x;
    const int c0 = blockIdx.x * 32 + threadIdx.y;
#pragma unroll
    for (int i = 0; i < 4; ++i)
        out[(size_t)(c0 + i * 8) * R + rc] = t[threadIdx.x][threadIdx.y + i * 8];
}

// ---------------- RoPE (NeoX) + split/transpose to head-major --------------
__global__ __launch_bounds__(128) void rope_split(const float* __restrict__ qkv,
                                                  const int* __restrict__ pos_ids,
                                                  float* __restrict__ Qh,
                                                  float* __restrict__ Kh,
                                                  float* __restrict__ Vh)
{
    const int token = blockIdx.x;
    const int b = token / SEQ;
    const int s = token % SEQ;
    __shared__ float cs[64], sn[64];
    const int tid = threadIdx.x;
    if (tid < 64) {
        double inv = exp(-9.210340371976184 * ((double)(2 * tid) / 128.0));
        double ang = (double)pos_ids[token] * inv;
        cs[tid] = (float)cos(ang);
        sn[tid] = (float)sin(ang);
    }
    __syncthreads();
    const float* base = qkv + (size_t)token * QKVN;

    for (int p = tid; p < NHEAD * 64; p += 128) {
        int h = p >> 6;
        int i = p & 63;
        float c = cs[i], sv = sn[i];
        size_t ob = ((size_t)(b * NHEAD + h) * SEQ + s) * HDIM;
        float q1 = base[h * HDIM + i];
        float q2 = base[h * HDIM + 64 + i];
        Qh[ob + i]      = q1 * c - q2 * sv;
        Qh[ob + 64 + i] = q2 * c + q1 * sv;
        float k1 = base[HID + h * HDIM + i];
        float k2 = base[HID + h * HDIM + 64 + i];
        Kh[ob + i]      = k1 * c - k2 * sv;
        Kh[ob + 64 + i] = k2 * c + k1 * sv;
    }
    for (int p = tid; p < HID; p += 128) {
        int h = p >> 7;
        int d = p & 127;
        Vh[((size_t)(b * NHEAD + h) * SEQ + s) * HDIM + d] = base[2 * HID + p];
    }
}

// ---------------- fp32 flash attention (causal), 64x64 tiles ---------------
__global__ __launch_bounds__(256) void flash_attn_f32(const float* __restrict__ Qg,
                                                      const float* __restrict__ Kg,
                                                      const float* __restrict__ Vg,
                                                      float* __restrict__ Og)
{
    extern __shared__ float smbuf[];
    const int QP = 68;
    float* Qs = smbuf;
    float* Ks = Qs + 128 * QP;
    float* Vs = Ks + 128 * QP;
    float* Ps = Vs + 64 * HDIM;

    const int tid = threadIdx.x;
    const int qt = (int)(gridDim.x - 1 - blockIdx.x);
    const int h = blockIdx.y;
    const int b = blockIdx.z;
    const size_t headoff = (size_t)(b * NHEAD + h) * SEQ * HDIM;
    const float* Qh = Qg + headoff;
    const float* Kh = Kg + headoff;
    const float* Vh = Vg + headoff;
    const int qbase = qt * 64;

#pragma unroll
    for (int it = 0; it < 8; ++it) {
        int idx = tid + it * 256;
        int r = idx >> 5;
        int d4 = (idx & 31) << 2;
        float4 x = *(const float4*)(Qh + (size_t)(qbase + r) * HDIM + d4);
        Qs[(d4 + 0) * QP + r] = x.x;
        Qs[(d4 + 1) * QP + r] = x.y;
        Qs[(d4 + 2) * QP + r] = x.z;
        Qs[(d4 + 3) * QP + r] = x.w;
    }

    const int sr  = (tid >> 4) << 2;
    const int sc4 = (tid & 15) << 2;
    const int ec  = (tid & 15) << 3;

    float m_i[4], l_i[4], o[4][8];
#pragma unroll
    for (int i = 0; i < 4; ++i) {
        m_i[i] = -1e30f; l_i[i] = 0.f;
#pragma unroll
        for (int j = 0; j < 8; ++j) o[i][j] = 0.f;
    }
    const float scale = 0.08838834764831845f;

    __syncthreads();

    for (int kt = 0; kt <= qt; ++kt) {
        const int kbase = kt * 64;
#pragma unroll
        for (int it = 0; it < 8; ++it) {
            int idx = tid + it * 256;
            int r = idx >> 5;
            int d4 = (idx & 31) << 2;
            float4 x = *(const float4*)(Kh + (size_t)(kbase + r) * HDIM + d4);
            Ks[(d4 + 0) * QP + r] = x.x;
            Ks[(d4 + 1) * QP + r] = x.y;
            Ks[(d4 + 2) * QP + r] = x.z;
            Ks[(d4 + 3) * QP + r] = x.w;
            float4 y = *(const float4*)(Vh + (size_t)(kbase + r) * HDIM + d4);
            *(float4*)&Vs[r * HDIM + d4] = y;
        }
        __syncthreads();

        float s[4][4];
#pragma unroll
        for (int i = 0; i < 4; ++i)
#pragma unroll
            for (int j = 0; j < 4; ++j) s[i][j] = 0.f;

#pragma unroll 8
        for (int d = 0; d < HDIM; ++d) {
            float4 qa = *(const float4*)&Qs[d * QP + sr];
            float4 kb = *(const float4*)&Ks[d * QP + sc4];
            float ra[4] = {qa.x, qa.y, qa.z, qa.w};
            float rb[4] = {kb.x, kb.y, kb.z, kb.w};
#pragma unroll
            for (int i = 0; i < 4; ++i)
#pragma unroll
                for (int j = 0; j < 4; ++j)
                    s[i][j] = fmaf(ra[i], rb[j], s[i][j]);
        }

#pragma unroll
        for (int i = 0; i < 4; ++i) {
            const int qg = qbase + sr + i;
            float rm = -1e30f;
#pragma unroll
            for (int j = 0; j < 4; ++j) {
                const int kg = kbase + sc4 + j;
                float val = (kg <= qg) ? s[i][j] * scale : -1e30f;
                s[i][j] = val;
                rm = fmaxf(rm, val);
            }
#pragma unroll
            for (int off = 8; off > 0; off >>= 1)
                rm = fmaxf(rm, __shfl_xor_sync(0xffffffffu, rm, off));
            const float mnew = fmaxf(m_i[i], rm);
            const float alpha = __expf(m_i[i] - mnew);
            float acc = 0.f;
#pragma unroll
            for (int j = 0; j < 4; ++j) {
                float p = __expf(s[i][j] - mnew);
                s[i][j] = p;
                acc += p;
            }
#pragma unroll
            for (int off = 8; off > 0; off >>= 1)
                acc += __shfl_xor_sync(0xffffffffu, acc, off);
            l_i[i] = l_i[i] * alpha + acc;
            m_i[i] = mnew;
#pragma unroll
            for (int j = 0; j < 8; ++j) o[i][j] *= alpha;
        }

#pragma unroll
        for (int j = 0; j < 4; ++j)
            *(float4*)&Ps[(sc4 + j) * QP + sr] =
                make_float4(s[0][j], s[1][j], s[2][j], s[3][j]);
        __syncthreads();

#pragma unroll 4
        for (int c = 0; c < 64; ++c) {
            float4 pa = *(const float4*)&Ps[c * QP + sr];
            float pr[4] = {pa.x, pa.y, pa.z, pa.w};
            float4 v0 = *(const float4*)&Vs[c * HDIM + ec];
            float4 v1 = *(const float4*)&Vs[c * HDIM + ec + 4];
            float vv[8] = {v0.x, v0.y, v0.z, v0.w, v1.x, v1.y, v1.z, v1.w};
#pragma unroll
            for (int i = 0; i < 4; ++i)
#pragma unroll
                for (int j = 0; j < 8; ++j)
                    o[i][j] = fmaf(pr[i], vv[j], o[i][j]);
        }
        __syncthreads();
    }

#pragma unroll
    for (int i = 0; i < 4; ++i) {
        const float inv = 1.0f / l_i[i];
        size_t off = ((size_t)b * SEQ + qbase + sr + i) * HID + h * HDIM + ec;
        *(float4*)(Og + off)     = make_float4(o[i][0] * inv, o[i][1] * inv, o[i][2] * inv, o[i][3] * inv);
        *(float4*)(Og + off + 4) = make_float4(o[i][4] * inv, o[i][5] * inv, o[i][6] * inv, o[i][7] * inv);
    }
}

// ---------------------------------------------------------------------------
extern "C" void kernel_launch(void* const* d_in, const int* in_sizes, int n_in,
                              void* d_out, int out_size)
{
    (void)in_sizes; (void)n_in; (void)out_size;
    const float* hidden = (const float*)d_in[0];
    const float* w_qkv  = (const float*)d_in[1];
    const float* w_o    = (const float*)d_in[2];
    const int*   pos    = (const int*)d_in[3];
    float* out = (float*)d_out;

    float *qkv, *q, *k, *v, *attn, *wqkvt, *wot;
    cudaGetSymbolAddress((void**)&qkv,   g_qkv);
    cudaGetSymbolAddress((void**)&q,     g_q);
    cudaGetSymbolAddress((void**)&k,     g_k);
    cudaGetSymbolAddress((void**)&v,     g_v);
    cudaGetSymbolAddress((void**)&attn,  g_attn);
    cudaGetSymbolAddress((void**)&wqkvt, g_wqkvt);
    cudaGetSymbolAddress((void**)&wot,   g_wot);

    // 0) transpose weights to [N, K] K-major
    transpose_f32<<<dim3(QKVN / 32, HID / 32), dim3(32, 8)>>>(w_qkv, wqkvt, HID, QKVN);
    transpose_f32<<<dim3(HID / 32, HID / 32), dim3(32, 8)>>>(w_o, wot, HID, HID);

    // 1) QKV projection (tensor cores, bf16x3)
    gemm_bf16x3<<<(TOKENS / 128) * (QKVN / 128), 256>>>(
        hidden, wqkvt, qkv, TOKENS, QKVN, HID, TOKENS / 128);

    // 2) RoPE + split to head-major Q/K/V
    rope_split<<<TOKENS, 128>>>(qkv, pos, q, k, v);

    // 3) causal flash attention (fp32 SIMT)
    const int att_smem = (128 * 68 * 2 + 64 * 128 + 64 * 68) * 4;
    cudaFuncSetAttribute(flash_attn_f32, cudaFuncAttributeMaxDynamicSharedMemorySize, att_smem);
    flash_attn_f32<<<dim3(SEQ / 64, NHEAD, BATCH), 256, att_smem>>>(q, k, v, attn);

    // 4) output projection (tensor cores, bf16x3)
    gemm_bf16x3<<<(TOKENS / 128) * (HID / 128), 256>>>(
        attn, wot, out, TOKENS, HID, HID, TOKENS / 128);
}

// round 4
// speedup vs baseline: 2.7381x; 1.2718x over previous
#include <cuda_runtime.h>
#include <cuda_bf16.h>
#include <math.h>
#include <stdint.h>

#define BATCH 2
#define SEQ   2048
#define HID   4096
#define NHEAD 32
#define HDIM  128
#define TOKENS (BATCH * SEQ)     // 4096
#define QKVN  (3 * HID)          // 12288
#define HEADS (BATCH * NHEAD)    // 64

typedef __nv_bfloat16 bf16;

// ---------------- scratch (device globals; no allocation allowed) ----------
__device__ float g_qkv[(size_t)TOKENS * QKVN];                 // fp32 QKV
__device__ float g_v[(size_t)HEADS * SEQ * HDIM];              // fp32 V head-major
__device__ bf16  g_hidH[(size_t)TOKENS * HID];
__device__ bf16  g_hidL[(size_t)TOKENS * HID];
__device__ bf16  g_wqkvtH[(size_t)QKVN * HID];
__device__ bf16  g_wqkvtL[(size_t)QKVN * HID];
__device__ bf16  g_wotH[(size_t)HID * HID];
__device__ bf16  g_wotL[(size_t)HID * HID];
__device__ bf16  g_QH[(size_t)HEADS * SEQ * HDIM];
__device__ bf16  g_QL[(size_t)HEADS * SEQ * HDIM];
__device__ bf16  g_KH[(size_t)HEADS * SEQ * HDIM];
__device__ bf16  g_KL[(size_t)HEADS * SEQ * HDIM];
__device__ bf16  g_VtH[(size_t)HEADS * HDIM * SEQ];            // V^T per head [d][s]
__device__ bf16  g_VtL[(size_t)HEADS * HDIM * SEQ];
__device__ bf16  g_attnH[(size_t)TOKENS * HID];
__device__ bf16  g_attnL[(size_t)TOKENS * HID];

// ======================= helpers ==================================
__device__ __forceinline__ uint32_t smem_u32_of(const void* p) {
    uint32_t a;
    asm("{ .reg .u64 t; cvta.to.shared.u64 t, %1; cvt.u32.u64 %0, t; }" : "=r"(a) : "l"(p));
    return a;
}
__device__ __forceinline__ void ldm_x4(uint32_t* r, uint32_t addr) {
    asm volatile("ldmatrix.sync.aligned.m8n8.x4.shared.b16 {%0,%1,%2,%3}, [%4];"
                 : "=r"(r[0]), "=r"(r[1]), "=r"(r[2]), "=r"(r[3]) : "r"(addr));
}
__device__ __forceinline__ void mma_bf16(float* d, const uint32_t* a, uint32_t b0, uint32_t b1) {
    asm volatile(
        "mma.sync.aligned.m16n8k16.row.col.f32.bf16.bf16.f32 "
        "{%0,%1,%2,%3},{%4,%5,%6,%7},{%8,%9},{%0,%1,%2,%3};"
        : "+f"(d[0]), "+f"(d[1]), "+f"(d[2]), "+f"(d[3])
        : "r"(a[0]), "r"(a[1]), "r"(a[2]), "r"(a[3]), "r"(b0), "r"(b1));
}
__device__ __forceinline__ void bfsplit(float x, bf16& hi, bf16& lo) {
    hi = __float2bfloat16_rn(x);
    lo = __float2bfloat16_rn(x - __bfloat162float(hi));
}
__device__ __forceinline__ uint32_t pk2(float a, float b) {
    __nv_bfloat162 t = __floats2bfloat162_rn(a, b);   // .x=a (low), .y=b (high)
    return *(uint32_t*)&t;
}
__device__ __forceinline__ void cp16(uint32_t smem, const void* g) {
    asm volatile("cp.async.cg.shared.global [%0], [%1], 16;" :: "r"(smem), "l"(g) : "memory");
}
__device__ __forceinline__ void cp_commit() {
    asm volatile("cp.async.commit_group;" ::: "memory");
}
template <int N> __device__ __forceinline__ void cp_wait() {
    asm volatile("cp.async.wait_group %0;" :: "n"(N) : "memory");
}

// ============ pre-split bf16 tensor-core GEMM (3-term compensated) ==========
// C[M,N] = (Ah+Al)[M,K] @ (Bh+Bl)[N,K]^T, pre-split bf16 inputs, fp32 output.
#define KC  32
#define KCP 40                       // padded smem row stride (bf16 elems)
#define STG_ARR (128 * KCP * 2)      // bytes per array per stage (10240)
#define STG_BYTES (4 * STG_ARR)      // 40960
#define NSTG 3

__global__ __launch_bounds__(256, 1) void gemm_bf3(const bf16* __restrict__ Ah,
                                                   const bf16* __restrict__ Al,
                                                   const bf16* __restrict__ Bh,
                                                   const bf16* __restrict__ Bl,
                                                   float* __restrict__ C,
                                                   int M, int N, int K, int Mtiles)
{
    extern __shared__ char gsm[];
    const uint32_t sbase = smem_u32_of(gsm);

    const int tid = threadIdx.x;
    const int warp = tid >> 5, lane = tid & 31;
    const int wm = warp & 3;
    const int wn = warp >> 2;

    const int bx = blockIdx.x;
    const int group = bx / (Mtiles * 8);
    const int rr = bx % (Mtiles * 8);
    const int bm = rr % Mtiles;
    const int bn = group * 8 + rr / Mtiles;

    const bf16* Aph = Ah + (size_t)bm * 128 * K;
    const bf16* Apl = Al + (size_t)bm * 128 * K;
    const bf16* Bph = Bh + (size_t)bn * 128 * K;
    const bf16* Bpl = Bl + (size_t)bn * 128 * K;

    const int lrow = lane & 15;
    const int lkh = (lane >> 4) << 3;

    float acc[2][8][4];
#pragma unroll
    for (int t = 0; t < 2; ++t)
#pragma unroll
        for (int n = 0; n < 8; ++n)
#pragma unroll
            for (int i = 0; i < 4; ++i) acc[t][n][i] = 0.f;

    const int nc = K / KC;   // 128

    // issue one chunk's cp.asyncs into stage st
    auto issue = [&](int c, int st) {
        const int kc = c * KC;
        const uint32_t sb = sbase + st * STG_BYTES;
#pragma unroll
        for (int q = 0; q < 2; ++q) {
            const int i = tid + q * 256;      // 0..511
            const int row = i >> 2;
            const int seg = (i & 3) << 3;     // element offset
            const uint32_t doff = (uint32_t)(row * KCP + seg) * 2;
            const size_t soff = (size_t)row * K + kc + seg;
            cp16(sb + 0 * STG_ARR + doff, Aph + soff);
            cp16(sb + 1 * STG_ARR + doff, Apl + soff);
            cp16(sb + 2 * STG_ARR + doff, Bph + soff);
            cp16(sb + 3 * STG_ARR + doff, Bpl + soff);
        }
    };

#pragma unroll
    for (int c = 0; c < NSTG; ++c) { issue(c, c); cp_commit(); }

    for (int c = 0; c < nc; ++c) {
        const int rem = nc - 1 - c;
        if (rem >= 2) cp_wait<2>();
        else if (rem == 1) cp_wait<1>();
        else cp_wait<0>();
        __syncthreads();

        const int st = c % NSTG;
        const uint32_t uAh = sbase + st * STG_BYTES;
        const uint32_t uAl = uAh + STG_ARR;
        const uint32_t uBh = uAh + 2 * STG_ARR;
        const uint32_t uBl = uAh + 3 * STG_ARR;

#pragma unroll
        for (int ks = 0; ks < 2; ++ks) {
            uint32_t ah[2][4], al[2][4];
#pragma unroll
            for (int t = 0; t < 2; ++t) {
                const uint32_t aoff =
                    (uint32_t)(((wm * 32 + t * 16 + lrow) * KCP + ks * 16 + lkh) * 2);
                ldm_x4(ah[t], uAh + aoff);
                ldm_x4(al[t], uAl + aoff);
            }
#pragma unroll
            for (int nt = 0; nt < 4; ++nt) {
                uint32_t bh[4], bl[4];
                const uint32_t boff =
                    (uint32_t)(((wn * 64 + nt * 16 + lrow) * KCP + ks * 16 + lkh) * 2);
                ldm_x4(bh, uBh + boff);
                ldm_x4(bl, uBl + boff);
#pragma unroll
                for (int t = 0; t < 2; ++t) {
                    mma_bf16(acc[t][2 * nt],     ah[t], bh[0], bh[2]);
                    mma_bf16(acc[t][2 * nt],     ah[t], bl[0], bl[2]);
                    mma_bf16(acc[t][2 * nt],     al[t], bh[0], bh[2]);
                    mma_bf16(acc[t][2 * nt + 1], ah[t], bh[1], bh[3]);
                    mma_bf16(acc[t][2 * nt + 1], ah[t], bl[1], bl[3]);
                    mma_bf16(acc[t][2 * nt + 1], al[t], bh[1], bh[3]);
                }
            }
        }
        __syncthreads();
        if (c + NSTG < nc) { issue(c + NSTG, st); cp_commit(); }
    }

    const int g = lane >> 2;
    const int tc2 = (lane & 3) << 1;
#pragma unroll
    for (int t = 0; t < 2; ++t) {
        const int row0 = bm * 128 + wm * 32 + t * 16 + g;
#pragma unroll
        for (int n = 0; n < 8; ++n) {
            const int col = bn * 128 + wn * 64 + n * 8 + tc2;
            *(float2*)(C + (size_t)row0 * N + col) = make_float2(acc[t][n][0], acc[t][n][1]);
            *(float2*)(C + (size_t)(row0 + 8) * N + col) = make_float2(acc[t][n][2], acc[t][n][3]);
        }
    }
}

// ---------------- elementwise split fp32 -> bf16 hi/lo ----------------------
__global__ __launch_bounds__(256) void split_f32(const float* __restrict__ in,
                                                 bf16* __restrict__ hi,
                                                 bf16* __restrict__ lo)
{
    const size_t i4 = (size_t)blockIdx.x * 256 + threadIdx.x;
    float4 v = *(const float4*)(in + i4 * 4);
    bf16 h[4], l[4];
    bfsplit(v.x, h[0], l[0]); bfsplit(v.y, h[1], l[1]);
    bfsplit(v.z, h[2], l[2]); bfsplit(v.w, h[3], l[3]);
    *(uint2*)(hi + i4 * 4) = *(uint2*)h;
    *(uint2*)(lo + i4 * 4) = *(uint2*)l;
}

// ---------------- transpose + split: out[c][r] = split(in[r][c]) ------------
__global__ __launch_bounds__(256) void transpose_split(const float* __restrict__ in,
                                                       bf16* __restrict__ outH,
                                                       bf16* __restrict__ outL,
                                                       int R, int Cc)
{
    __shared__ float t[32][33];
    const int c = blockIdx.x * 32 + threadIdx.x;
    const int r0 = blockIdx.y * 32 + threadIdx.y;
#pragma unroll
    for (int i = 0; i < 4; ++i)
        t[threadIdx.y + i * 8][threadIdx.x] = in[(size_t)(r0 + i * 8) * Cc + c];
    __syncthreads();
    const int rc = blockIdx.y * 32 + threadIdx.x;
    const int c0 = blockIdx.x * 32 + threadIdx.y;
#pragma unroll
    for (int i = 0; i < 4; ++i) {
        float v = t[threadIdx.x][threadIdx.y + i * 8];
        bf16 h, l;
        bfsplit(v, h, l);
        outH[(size_t)(c0 + i * 8) * R + rc] = h;
        outL[(size_t)(c0 + i * 8) * R + rc] = l;
    }
}

// ---------------- V transpose + split: Vt[b,h,d,s] -------------------------
__global__ __launch_bounds__(256) void vt_split(const float* __restrict__ Vg,
                                                bf16* __restrict__ VtH,
                                                bf16* __restrict__ VtL)
{
    __shared__ float t[32][33];
    const int bh = blockIdx.z;
    const float* in = Vg + (size_t)bh * SEQ * HDIM;
    const int s0 = blockIdx.x * 32;
    const int d0 = blockIdx.y * 32;
#pragma unroll
    for (int i = 0; i < 4; ++i)
        t[threadIdx.y + i * 8][threadIdx.x] = in[(size_t)(s0 + threadIdx.y + i * 8) * HDIM + d0 + threadIdx.x];
    __syncthreads();
    bf16* oh = VtH + (size_t)bh * HDIM * SEQ;
    bf16* ol = VtL + (size_t)bh * HDIM * SEQ;
#pragma unroll
    for (int i = 0; i < 4; ++i) {
        float v = t[threadIdx.x][threadIdx.y + i * 8];
        bf16 h, l;
        bfsplit(v, h, l);
        oh[(size_t)(d0 + threadIdx.y + i * 8) * SEQ + s0 + threadIdx.x] = h;
        ol[(size_t)(d0 + threadIdx.y + i * 8) * SEQ + s0 + threadIdx.x] = l;
    }
}

// ---------------- RoPE (NeoX) + split to head-major bf16 hi/lo --------------
__global__ __launch_bounds__(128) void rope_split2(const float* __restrict__ qkv,
                                                   const int* __restrict__ pos_ids,
                                                   bf16* __restrict__ QH, bf16* __restrict__ QL,
                                                   bf16* __restrict__ KH, bf16* __restrict__ KL,
                                                   float* __restrict__ Vh)
{
    const int token = blockIdx.x;
    const int b = token / SEQ;
    const int s = token % SEQ;
    __shared__ float cs[64], sn[64];
    const int tid = threadIdx.x;
    if (tid < 64) {
        double inv = exp(-9.210340371976184 * ((double)(2 * tid) / 128.0));
        double ang = (double)pos_ids[token] * inv;
        cs[tid] = (float)cos(ang);
        sn[tid] = (float)sin(ang);
    }
    __syncthreads();
    const float* base = qkv + (size_t)token * QKVN;

    for (int p = tid; p < NHEAD * 64; p += 128) {
        int h = p >> 6;
        int i = p & 63;
        float c = cs[i], sv = sn[i];
        size_t ob = ((size_t)(b * NHEAD + h) * SEQ + s) * HDIM;
        float q1 = base[h * HDIM + i];
        float q2 = base[h * HDIM + 64 + i];
        float r1 = q1 * c - q2 * sv;
        float r2 = q2 * c + q1 * sv;
        bf16 hh, ll;
        bfsplit(r1, hh, ll); QH[ob + i] = hh;      QL[ob + i] = ll;
        bfsplit(r2, hh, ll); QH[ob + 64 + i] = hh; QL[ob + 64 + i] = ll;
        float k1 = base[HID + h * HDIM + i];
        float k2 = base[HID + h * HDIM + 64 + i];
        r1 = k1 * c - k2 * sv;
        r2 = k2 * c + k1 * sv;
        bfsplit(r1, hh, ll); KH[ob + i] = hh;      KL[ob + i] = ll;
        bfsplit(r2, hh, ll); KH[ob + 64 + i] = hh; KL[ob + 64 + i] = ll;
    }
    for (int p = tid; p < HID; p += 128) {
        int h = p >> 7;
        int d = p & 127;
        Vh[((size_t)(b * NHEAD + h) * SEQ + s) * HDIM + d] = base[2 * HID + p];
    }
}

// ---------------- tensor-core flash attention (causal) ----------------------
// CTA: 128 q-rows (8 warps x m16), k-tile 64, HD=128. All operands bf16 hi/lo.
#define QSTR 136   // smem row stride for Q/K (d-dim 128 + pad)
#define VSTR 72    // smem row stride for Vt (kv-dim 64 + pad)
// smem byte offsets
#define oQH 0
#define oQL (oQH + 128 * QSTR * 2)
#define oKH (oQL + 128 * QSTR * 2)             // 2 buffers, 64*QSTR*2 each
#define oKL (oKH + 2 * 64 * QSTR * 2)
#define oVH (oKL + 2 * 64 * QSTR * 2)          // 2 buffers, 128*VSTR*2 each
#define oVL (oVH + 2 * 128 * VSTR * 2)
#define ATT_SMEM (oVL + 2 * 128 * VSTR * 2)    // 212992

__global__ __launch_bounds__(256, 1) void flash_mma(const bf16* __restrict__ QHg,
                                                    const bf16* __restrict__ QLg,
                                                    const bf16* __restrict__ KHg,
                                                    const bf16* __restrict__ KLg,
                                                    const bf16* __restrict__ VtHg,
                                                    const bf16* __restrict__ VtLg,
                                                    bf16* __restrict__ attnH,
                                                    bf16* __restrict__ attnL)
{
    extern __shared__ char asm_buf[];
    const uint32_t sb = smem_u32_of(asm_buf);

    const int tid = threadIdx.x;
    const int warp = tid >> 5, lane = tid & 31;
    const int g = lane >> 2;           // fragment row within 8
    const int lam = lane & 3;          // fragment col pair
    const int lrow = lane & 15;
    const int lkh = (lane >> 4) << 3;

    const int qt = (int)(gridDim.x - 1 - blockIdx.x);
    const int h = blockIdx.y;
    const int b = blockIdx.z;
    const int qb = qt * 128;
    const size_t hoff = (size_t)(b * NHEAD + h) * SEQ * HDIM;     // Q/K base
    const size_t voff = (size_t)(b * NHEAD + h) * HDIM * SEQ;     // Vt base

    // ---- load Q tile (both hi/lo) via cp.async, group 0
#pragma unroll
    for (int j = 0; j < 8; ++j) {
        const int i = tid + j * 256;      // 0..2047
        const int row = i >> 4;
        const int seg = (i & 15) << 3;
        const uint32_t doff = (uint32_t)(row * QSTR + seg) * 2;
        const size_t soff = hoff + (size_t)(qb + row) * HDIM + seg;
        cp16(sb + oQH + doff, QHg + soff);
        cp16(sb + oQL + doff, QLg + soff);
    }
    cp_commit();

    const int ktmax = 2 * qt + 1;

    auto issueKV = [&](int kt, int buf) {
        const int kb = kt * 64;
#pragma unroll
        for (int j = 0; j < 4; ++j) {
            const int i = tid + j * 256;          // 0..1023
            // K: 64 rows x 128 d
            const int krow = i >> 4;
            const int kseg = (i & 15) << 3;
            const uint32_t kdoff = (uint32_t)(krow * QSTR + kseg) * 2;
            const size_t ksoff = hoff + (size_t)(kb + krow) * HDIM + kseg;
            cp16(sb + oKH + buf * (64 * QSTR * 2) + kdoff, KHg + ksoff);
            cp16(sb + oKL + buf * (64 * QSTR * 2) + kdoff, KLg + ksoff);
            // Vt: 128 rows (d) x 64 kv
            const int vrow = i >> 3;
            const int vseg = (i & 7) << 3;
            const uint32_t vdoff = (uint32_t)(vrow * VSTR + vseg) * 2;
            const size_t vsoff = voff + (size_t)vrow * SEQ + kb + vseg;
            cp16(sb + oVH + buf * (128 * VSTR * 2) + vdoff, VtHg + vsoff);
            cp16(sb + oVL + buf * (128 * VSTR * 2) + vdoff, VtLg + vsoff);
        }
    };

    issueKV(0, 0);
    cp_commit();

    float oacc[16][4];
#pragma unroll
    for (int n = 0; n < 16; ++n)
#pragma unroll
        for (int i = 0; i < 4; ++i) oacc[n][i] = 0.f;
    float m0 = -1e30f, m1 = -1e30f, l0 = 0.f, l1 = 0.f;
    const float scale = 0.08838834764831845f;

    const int r0g = qb + warp * 16 + g;     // this thread's global rows
    const int r1g = r0g + 8;

    for (int kt = 0; kt <= ktmax; ++kt) {
        const int kb = kt * 64;
        const int buf = kt & 1;
        if (kt + 1 <= ktmax) {
            issueKV(kt + 1, buf ^ 1);
            cp_commit();
            cp_wait<1>();
        } else {
            cp_wait<0>();
        }
        __syncthreads();

        const uint32_t uQH = sb + oQH, uQL = sb + oQL;
        const uint32_t uKH = sb + oKH + buf * (64 * QSTR * 2);
        const uint32_t uKL = sb + oKL + buf * (64 * QSTR * 2);
        const uint32_t uVH = sb + oVH + buf * (128 * VSTR * 2);
        const uint32_t uVL = sb + oVL + buf * (128 * VSTR * 2);

        // ---- S = Q K^T  (8 n8-tiles of fp32 frags)
        float sacc[8][4];
#pragma unroll
        for (int n = 0; n < 8; ++n)
#pragma unroll
            for (int i = 0; i < 4; ++i) sacc[n][i] = 0.f;

#pragma unroll
        for (int ks = 0; ks < 8; ++ks) {
            uint32_t ah[4], al[4];
            const uint32_t aoff = (uint32_t)(((warp * 16 + lrow) * QSTR + ks * 16 + lkh) * 2);
            ldm_x4(ah, uQH + aoff);
            ldm_x4(al, uQL + aoff);
#pragma unroll
            for (int nt = 0; nt < 4; ++nt) {
                uint32_t bh[4], bl[4];
                const uint32_t boff = (uint32_t)(((nt * 16 + lrow) * QSTR + ks * 16 + lkh) * 2);
                ldm_x4(bh, uKH + boff);
                ldm_x4(bl, uKL + boff);
                mma_bf16(sacc[2 * nt],     ah, bh[0], bh[2]);
                mma_bf16(sacc[2 * nt],     ah, bl[0], bl[2]);
                mma_bf16(sacc[2 * nt],     al, bh[0], bh[2]);
                mma_bf16(sacc[2 * nt + 1], ah, bh[1], bh[3]);
                mma_bf16(sacc[2 * nt + 1], ah, bl[1], bl[3]);
                mma_bf16(sacc[2 * nt + 1], al, bh[1], bh[3]);
            }
        }

        // ---- scale + causal mask + online softmax
        const bool need_mask = (kt >= 2 * qt);
        float rm0 = -1e30f, rm1 = -1e30f;
#pragma unroll
        for (int j = 0; j < 8; ++j) {
            const int cg0 = kb + j * 8 + 2 * lam;
#pragma unroll
            for (int i = 0; i < 4; ++i) {
                float v = sacc[j][i] * scale;
                if (need_mask) {
                    const int cg = cg0 + (i & 1);
                    const int rg = (i < 2) ? r0g : r1g;
                    if (cg > rg) v = -1e30f;
                }
                sacc[j][i] = v;
            }
            rm0 = fmaxf(rm0, fmaxf(sacc[j][0], sacc[j][1]));
            rm1 = fmaxf(rm1, fmaxf(sacc[j][2], sacc[j][3]));
        }
#pragma unroll
        for (int off = 1; off <= 2; off <<= 1) {
            rm0 = fmaxf(rm0, __shfl_xor_sync(0xffffffffu, rm0, off));
            rm1 = fmaxf(rm1, __shfl_xor_sync(0xffffffffu, rm1, off));
        }
        const float mn0 = fmaxf(m0, rm0);
        const float mn1 = fmaxf(m1, rm1);
        const float al0 = __expf(m0 - mn0);
        const float al1 = __expf(m1 - mn1);
        m0 = mn0; m1 = mn1;

        float rs0 = 0.f, rs1 = 0.f;
#pragma unroll
        for (int j = 0; j < 8; ++j) {
            sacc[j][0] = __expf(sacc[j][0] - mn0);
            sacc[j][1] = __expf(sacc[j][1] - mn0);
            sacc[j][2] = __expf(sacc[j][2] - mn1);
            sacc[j][3] = __expf(sacc[j][3] - mn1);
            rs0 += sacc[j][0] + sacc[j][1];
            rs1 += sacc[j][2] + sacc[j][3];
        }
#pragma unroll
        for (int off = 1; off <= 2; off <<= 1) {
            rs0 += __shfl_xor_sync(0xffffffffu, rs0, off);
            rs1 += __shfl_xor_sync(0xffffffffu, rs1, off);
        }
        l0 = l0 * al0 + rs0;
        l1 = l1 * al1 + rs1;

        // rescale O
#pragma unroll
        for (int n = 0; n < 16; ++n) {
            oacc[n][0] *= al0; oacc[n][1] *= al0;
            oacc[n][2] *= al1; oacc[n][3] *= al1;
        }

        // ---- pack P into A fragments (hi + residual lo)
        uint32_t pah[4][4], pal[4][4];
#pragma unroll
        for (int j2 = 0; j2 < 4; ++j2) {
            float p00 = sacc[2 * j2][0],     p01 = sacc[2 * j2][1];
            float p02 = sacc[2 * j2][2],     p03 = sacc[2 * j2][3];
            float p10 = sacc[2 * j2 + 1][0], p11 = sacc[2 * j2 + 1][1];
            float p12 = sacc[2 * j2 + 1][2], p13 = sacc[2 * j2 + 1][3];
            pah[j2][0] = pk2(p00, p01);
            pah[j2][1] = pk2(p02, p03);
            pah[j2][2] = pk2(p10, p11);
            pah[j2][3] = pk2(p12, p13);
            // residuals
            bf16 h;
            h = __float2bfloat16_rn(p00); p00 -= __bfloat162float(h);
            h = __float2bfloat16_rn(p01); p01 -= __bfloat162float(h);
            h = __float2bfloat16_rn(p02); p02 -= __bfloat162float(h);
            h = __float2bfloat16_rn(p03); p03 -= __bfloat162float(h);
            h = __float2bfloat16_rn(p10); p10 -= __bfloat162float(h);
            h = __float2bfloat16_rn(p11); p11 -= __bfloat162float(h);
            h = __float2bfloat16_rn(p12); p12 -= __bfloat162float(h);
            h = __float2bfloat16_rn(p13); p13 -= __bfloat162float(h);
            pal[j2][0] = pk2(p00, p01);
            pal[j2][1] = pk2(p02, p03);
            pal[j2][2] = pk2(p10, p11);
            pal[j2][3] = pk2(p12, p13);
        }

        // ---- O += P V   (V^T in smem: B rows = d, cols = kv)
#pragma unroll
        for (int nt = 0; nt < 8; ++nt) {
#pragma unroll
            for (int j2 = 0; j2 < 4; ++j2) {
                uint32_t vh[4], vl[4];
                const uint32_t boff = (uint32_t)(((nt * 16 + lrow) * VSTR + j2 * 16 + lkh) * 2);
                ldm_x4(vh, uVH + boff);
                ldm_x4(vl, uVL + boff);
                mma_bf16(oacc[2 * nt],     pah[j2], vh[0], vh[2]);
                mma_bf16(oacc[2 * nt],     pah[j2], vl[0], vl[2]);
                mma_bf16(oacc[2 * nt],     pal[j2], vh[0], vh[2]);
                mma_bf16(oacc[2 * nt + 1], pah[j2], vh[1], vh[3]);
                mma_bf16(oacc[2 * nt + 1], pah[j2], vl[1], vl[3]);
                mma_bf16(oacc[2 * nt + 1], pal[j2], vh[1], vh[3]);
            }
        }
        __syncthreads();
    }

    // ---- epilogue: normalize, split to bf16 hi/lo, write [token][HID]
    const float i0 = 1.0f / l0;
    const float i1 = 1.0f / l1;
    const size_t row0 = ((size_t)b * SEQ + r0g) * HID + h * HDIM;
    const size_t row1 = ((size_t)b * SEQ + r1g) * HID + h * HDIM;
#pragma unroll
    for (int n = 0; n < 16; ++n) {
        const int col = n * 8 + 2 * lam;
        float x0 = oacc[n][0] * i0, x1 = oacc[n][1] * i0;
        float y0 = oacc[n][2] * i1, y1 = oacc[n][3] * i1;
        *(uint32_t*)(attnH + row0 + col) = pk2(x0, x1);
        *(uint32_t*)(attnH + row1 + col) = pk2(y0, y1);
        bf16 hb;
        hb = __float2bfloat16_rn(x0); x0 -= __bfloat162float(hb);
        hb = __float2bfloat16_rn(x1); x1 -= __bfloat162float(hb);
        hb = __float2bfloat16_rn(y0); y0 -= __bfloat162float(hb);
        hb = __float2bfloat16_rn(y1); y1 -= __bfloat162float(hb);
        *(uint32_t*)(attnL + row0 + col) = pk2(x0, x1);
        *(uint32_t*)(attnL + row1 + col) = pk2(y0, y1);
    }
}

// ---------------------------------------------------------------------------
extern "C" void kernel_launch(void* const* d_in, const int* in_sizes, int n_in,
                              void* d_out, int out_size)
{
    (void)in_sizes; (void)n_in; (void)out_size;
    const float* hidden = (const float*)d_in[0];
    const float* w_qkv  = (const float*)d_in[1];
    const float* w_o    = (const float*)d_in[2];
    const int*   pos    = (const int*)d_in[3];
    float* out = (float*)d_out;

    float *qkv, *v;
    bf16 *hidH, *hidL, *wqkvtH, *wqkvtL, *wotH, *wotL;
    bf16 *QH, *QL, *KH, *KL, *VtH, *VtL, *attnH, *attnL;
    cudaGetSymbolAddress((void**)&qkv,    g_qkv);
    cudaGetSymbolAddress((void**)&v,      g_v);
    cudaGetSymbolAddress((void**)&hidH,   g_hidH);
    cudaGetSymbolAddress((void**)&hidL,   g_hidL);
    cudaGetSymbolAddress((void**)&wqkvtH, g_wqkvtH);
    cudaGetSymbolAddress((void**)&wqkvtL, g_wqkvtL);
    cudaGetSymbolAddress((void**)&wotH,   g_wotH);
    cudaGetSymbolAddress((void**)&wotL,   g_wotL);
    cudaGetSymbolAddress((void**)&QH,     g_QH);
    cudaGetSymbolAddress((void**)&QL,     g_QL);
    cudaGetSymbolAddress((void**)&KH,     g_KH);
    cudaGetSymbolAddress((void**)&KL,     g_KL);
    cudaGetSymbolAddress((void**)&VtH,    g_VtH);
    cudaGetSymbolAddress((void**)&VtL,    g_VtL);
    cudaGetSymbolAddress((void**)&attnH,  g_attnH);
    cudaGetSymbolAddress((void**)&attnL,  g_attnL);

    // 0) pre-split + transpose inputs
    split_f32<<<(TOKENS * HID) / 1024, 256>>>(hidden, hidH, hidL);
    transpose_split<<<dim3(QKVN / 32, HID / 32), dim3(32, 8)>>>(w_qkv, wqkvtH, wqkvtL, HID, QKVN);
    transpose_split<<<dim3(HID / 32, HID / 32), dim3(32, 8)>>>(w_o, wotH, wotL, HID, HID);

    const int gsmem = NSTG * STG_BYTES;
    cudaFuncSetAttribute(gemm_bf3, cudaFuncAttributeMaxDynamicSharedMemorySize, gsmem);

    // 1) QKV projection
    gemm_bf3<<<(TOKENS / 128) * (QKVN / 128), 256, gsmem>>>(
        hidH, hidL, wqkvtH, wqkvtL, qkv, TOKENS, QKVN, HID, TOKENS / 128);

    // 2) RoPE + split to head-major bf16; V fp32 head-major
    rope_split2<<<TOKENS, 128>>>(qkv, pos, QH, QL, KH, KL, v);

    // 3) V transpose + split per head
    vt_split<<<dim3(SEQ / 32, HDIM / 32, HEADS), dim3(32, 8)>>>(v, VtH, VtL);

    // 4) tensor-core causal flash attention -> pre-split attn
    cudaFuncSetAttribute(flash_mma, cudaFuncAttributeMaxDynamicSharedMemorySize, ATT_SMEM);
    flash_mma<<<dim3(SEQ / 128, NHEAD, BATCH), 256, ATT_SMEM>>>(
        QH, QL, KH, KL, VtH, VtL, attnH, attnL);

    // 5) output projection
    gemm_bf3<<<(TOKENS / 128) * (HID / 128), 256, gsmem>>>(
        attnH, attnL, wotH, wotL, out, TOKENS, HID, HID, TOKENS / 128);
}

// round 5
// speedup vs baseline: 3.0282x; 1.1060x over previous
#include <cuda_runtime.h>
#include <cuda_bf16.h>
#include <math.h>
#include <stdint.h>

#define BATCH 2
#define SEQ   2048
#define HID   4096
#define NHEAD 32
#define HDIM  128
#define TOKENS (BATCH * SEQ)     // 4096
#define QKVN  (3 * HID)          // 12288
#define HEADS (BATCH * NHEAD)    // 64

typedef __nv_bfloat16 bf16;

// ---------------- scratch (device globals; no allocation allowed) ----------
__device__ float g_qkv[(size_t)TOKENS * QKVN];                 // fp32 QKV
__device__ float g_v[(size_t)HEADS * SEQ * HDIM];              // fp32 V head-major
__device__ bf16  g_hidH[(size_t)TOKENS * HID];
__device__ bf16  g_hidL[(size_t)TOKENS * HID];
__device__ bf16  g_wqkvtH[(size_t)QKVN * HID];
__device__ bf16  g_wqkvtL[(size_t)QKVN * HID];
__device__ bf16  g_wotH[(size_t)HID * HID];
__device__ bf16  g_wotL[(size_t)HID * HID];
__device__ bf16  g_QH[(size_t)HEADS * SEQ * HDIM];
__device__ bf16  g_QL[(size_t)HEADS * SEQ * HDIM];
__device__ bf16  g_KH[(size_t)HEADS * SEQ * HDIM];
__device__ bf16  g_KL[(size_t)HEADS * SEQ * HDIM];
__device__ bf16  g_VtH[(size_t)HEADS * HDIM * SEQ];            // V^T per head [d][s]
__device__ bf16  g_VtL[(size_t)HEADS * HDIM * SEQ];
__device__ bf16  g_attnH[(size_t)TOKENS * HID];
__device__ bf16  g_attnL[(size_t)TOKENS * HID];

// ======================= helpers ==================================
__device__ __forceinline__ uint32_t smem_u32_of(const void* p) {
    uint32_t a;
    asm("{ .reg .u64 t; cvta.to.shared.u64 t, %1; cvt.u32.u64 %0, t; }" : "=r"(a) : "l"(p));
    return a;
}
__device__ __forceinline__ void ldm_x4(uint32_t* r, uint32_t addr) {
    asm volatile("ldmatrix.sync.aligned.m8n8.x4.shared.b16 {%0,%1,%2,%3}, [%4];"
                 : "=r"(r[0]), "=r"(r[1]), "=r"(r[2]), "=r"(r[3]) : "r"(addr));
}
__device__ __forceinline__ void mma_bf16(float* d, const uint32_t* a, uint32_t b0, uint32_t b1) {
    asm volatile(
        "mma.sync.aligned.m16n8k16.row.col.f32.bf16.bf16.f32 "
        "{%0,%1,%2,%3},{%4,%5,%6,%7},{%8,%9},{%0,%1,%2,%3};"
        : "+f"(d[0]), "+f"(d[1]), "+f"(d[2]), "+f"(d[3])
        : "r"(a[0]), "r"(a[1]), "r"(a[2]), "r"(a[3]), "r"(b0), "r"(b1));
}
__device__ __forceinline__ void bfsplit(float x, bf16& hi, bf16& lo) {
    hi = __float2bfloat16_rn(x);
    lo = __float2bfloat16_rn(x - __bfloat162float(hi));
}
__device__ __forceinline__ uint32_t pk2(float a, float b) {
    __nv_bfloat162 t = __floats2bfloat162_rn(a, b);
    return *(uint32_t*)&t;
}
__device__ __forceinline__ void cp16(uint32_t smem, const void* g) {
    asm volatile("cp.async.cg.shared.global [%0], [%1], 16;" :: "r"(smem), "l"(g) : "memory");
}
__device__ __forceinline__ void cp_commit() {
    asm volatile("cp.async.commit_group;" ::: "memory");
}
template <int N> __device__ __forceinline__ void cp_wait() {
    asm volatile("cp.async.wait_group %0;" :: "n"(N) : "memory");
}

// ============ pre-split bf16 tensor-core GEMM (3-term compensated) ==========
#define KC  32
#define KCP 40                       // padded smem row stride (bf16 elems)
#define STG_ARR (128 * KCP * 2)      // bytes per array per stage (10240)
#define STG_BYTES (4 * STG_ARR)      // 40960
#define NSTG 2

__global__ __launch_bounds__(256, 2) void gemm_bf3(const bf16* __restrict__ Ah,
                                                   const bf16* __restrict__ Al,
                                                   const bf16* __restrict__ Bh,
                                                   const bf16* __restrict__ Bl,
                                                   float* __restrict__ C,
                                                   int M, int N, int K, int Mtiles)
{
    extern __shared__ char gsm[];
    const uint32_t sbase = smem_u32_of(gsm);

    const int tid = threadIdx.x;
    const int warp = tid >> 5, lane = tid & 31;
    const int wm = warp & 3;
    const int wn = warp >> 2;

    const int bx = blockIdx.x;
    const int group = bx / (Mtiles * 8);
    const int rr = bx % (Mtiles * 8);
    const int bm = rr % Mtiles;
    const int bn = group * 8 + rr / Mtiles;

    const bf16* Aph = Ah + (size_t)bm * 128 * K;
    const bf16* Apl = Al + (size_t)bm * 128 * K;
    const bf16* Bph = Bh + (size_t)bn * 128 * K;
    const bf16* Bpl = Bl + (size_t)bn * 128 * K;

    const int lrow = lane & 15;
    const int lkh = (lane >> 4) << 3;

    float acc[2][8][4];
#pragma unroll
    for (int t = 0; t < 2; ++t)
#pragma unroll
        for (int n = 0; n < 8; ++n)
#pragma unroll
            for (int i = 0; i < 4; ++i) acc[t][n][i] = 0.f;

    const int nc = K / KC;   // 128

    auto issue = [&](int c, int st) {
        const int kc = c * KC;
        const uint32_t sb = sbase + st * STG_BYTES;
#pragma unroll
        for (int q = 0; q < 2; ++q) {
            const int i = tid + q * 256;
            const int row = i >> 2;
            const int seg = (i & 3) << 3;
            const uint32_t doff = (uint32_t)(row * KCP + seg) * 2;
            const size_t soff = (size_t)row * K + kc + seg;
            cp16(sb + 0 * STG_ARR + doff, Aph + soff);
            cp16(sb + 1 * STG_ARR + doff, Apl + soff);
            cp16(sb + 2 * STG_ARR + doff, Bph + soff);
            cp16(sb + 3 * STG_ARR + doff, Bpl + soff);
        }
    };

#pragma unroll
    for (int c = 0; c < NSTG; ++c) { issue(c, c); cp_commit(); }

    for (int c = 0; c < nc; ++c) {
        const int rem = nc - 1 - c;
        if (rem >= 1) cp_wait<1>();
        else cp_wait<0>();
        __syncthreads();

        const int st = c % NSTG;
        const uint32_t uAh = sbase + st * STG_BYTES;
        const uint32_t uAl = uAh + STG_ARR;
        const uint32_t uBh = uAh + 2 * STG_ARR;
        const uint32_t uBl = uAh + 3 * STG_ARR;

#pragma unroll
        for (int ks = 0; ks < 2; ++ks) {
            uint32_t ah[2][4], al[2][4];
#pragma unroll
            for (int t = 0; t < 2; ++t) {
                const uint32_t aoff =
                    (uint32_t)(((wm * 32 + t * 16 + lrow) * KCP + ks * 16 + lkh) * 2);
                ldm_x4(ah[t], uAh + aoff);
                ldm_x4(al[t], uAl + aoff);
            }
#pragma unroll
            for (int nt = 0; nt < 4; ++nt) {
                uint32_t bh[4], bl[4];
                const uint32_t boff =
                    (uint32_t)(((wn * 64 + nt * 16 + lrow) * KCP + ks * 16 + lkh) * 2);
                ldm_x4(bh, uBh + boff);
                ldm_x4(bl, uBl + boff);
                // interleaved: consecutive mma hit different accumulators
#pragma unroll
                for (int t = 0; t < 2; ++t) {
                    mma_bf16(acc[t][2 * nt],     ah[t], bh[0], bh[2]);
                    mma_bf16(acc[t][2 * nt + 1], ah[t], bh[1], bh[3]);
                    mma_bf16(acc[t][2 * nt],     ah[t], bl[0], bl[2]);
                    mma_bf16(acc[t][2 * nt + 1], ah[t], bl[1], bl[3]);
                    mma_bf16(acc[t][2 * nt],     al[t], bh[0], bh[2]);
                    mma_bf16(acc[t][2 * nt + 1], al[t], bh[1], bh[3]);
                }
            }
        }
        __syncthreads();
        if (c + NSTG < nc) { issue(c + NSTG, st); cp_commit(); }
    }

    const int g = lane >> 2;
    const int tc2 = (lane & 3) << 1;
#pragma unroll
    for (int t = 0; t < 2; ++t) {
        const int row0 = bm * 128 + wm * 32 + t * 16 + g;
#pragma unroll
        for (int n = 0; n < 8; ++n) {
            const int col = bn * 128 + wn * 64 + n * 8 + tc2;
            *(float2*)(C + (size_t)row0 * N + col) = make_float2(acc[t][n][0], acc[t][n][1]);
            *(float2*)(C + (size_t)(row0 + 8) * N + col) = make_float2(acc[t][n][2], acc[t][n][3]);
        }
    }
}

// ---------------- elementwise split fp32 -> bf16 hi/lo ----------------------
__global__ __launch_bounds__(256) void split_f32(const float* __restrict__ in,
                                                 bf16* __restrict__ hi,
                                                 bf16* __restrict__ lo)
{
    const size_t i4 = (size_t)blockIdx.x * 256 + threadIdx.x;
    float4 v = *(const float4*)(in + i4 * 4);
    bf16 h[4], l[4];
    bfsplit(v.x, h[0], l[0]); bfsplit(v.y, h[1], l[1]);
    bfsplit(v.z, h[2], l[2]); bfsplit(v.w, h[3], l[3]);
    *(uint2*)(hi + i4 * 4) = *(uint2*)h;
    *(uint2*)(lo + i4 * 4) = *(uint2*)l;
}

// ---------------- transpose + split: out[c][r] = split(in[r][c]) ------------
__global__ __launch_bounds__(256) void transpose_split(const float* __restrict__ in,
                                                       bf16* __restrict__ outH,
                                                       bf16* __restrict__ outL,
                                                       int R, int Cc)
{
    __shared__ float t[32][33];
    const int c = blockIdx.x * 32 + threadIdx.x;
    const int r0 = blockIdx.y * 32 + threadIdx.y;
#pragma unroll
    for (int i = 0; i < 4; ++i)
        t[threadIdx.y + i * 8][threadIdx.x] = in[(size_t)(r0 + i * 8) * Cc + c];
    __syncthreads();
    const int rc = blockIdx.y * 32 + threadIdx.x;
    const int c0 = blockIdx.x * 32 + threadIdx.y;
#pragma unroll
    for (int i = 0; i < 4; ++i) {
        float v = t[threadIdx.x][threadIdx.y + i * 8];
        bf16 h, l;
        bfsplit(v, h, l);
        outH[(size_t)(c0 + i * 8) * R + rc] = h;
        outL[(size_t)(c0 + i * 8) * R + rc] = l;
    }
}

// ---------------- V transpose + split: Vt[b,h,d,s] -------------------------
__global__ __launch_bounds__(256) void vt_split(const float* __restrict__ Vg,
                                                bf16* __restrict__ VtH,
                                                bf16* __restrict__ VtL)
{
    __shared__ float t[32][33];
    const int bh = blockIdx.z;
    const float* in = Vg + (size_t)bh * SEQ * HDIM;
    const int s0 = blockIdx.x * 32;
    const int d0 = blockIdx.y * 32;
#pragma unroll
    for (int i = 0; i < 4; ++i)
        t[threadIdx.y + i * 8][threadIdx.x] = in[(size_t)(s0 + threadIdx.y + i * 8) * HDIM + d0 + threadIdx.x];
    __syncthreads();
    bf16* oh = VtH + (size_t)bh * HDIM * SEQ;
    bf16* ol = VtL + (size_t)bh * HDIM * SEQ;
#pragma unroll
    for (int i = 0; i < 4; ++i) {
        float v = t[threadIdx.x][threadIdx.y + i * 8];
        bf16 h, l;
        bfsplit(v, h, l);
        oh[(size_t)(d0 + threadIdx.y + i * 8) * SEQ + s0 + threadIdx.x] = h;
        ol[(size_t)(d0 + threadIdx.y + i * 8) * SEQ + s0 + threadIdx.x] = l;
    }
}

// ---------------- RoPE (NeoX) + split to head-major bf16 hi/lo --------------
__global__ __launch_bounds__(128) void rope_split2(const float* __restrict__ qkv,
                                                   const int* __restrict__ pos_ids,
                                                   bf16* __restrict__ QH, bf16* __restrict__ QL,
                                                   bf16* __restrict__ KH, bf16* __restrict__ KL,
                                                   float* __restrict__ Vh)
{
    const int token = blockIdx.x;
    const int b = token / SEQ;
    const int s = token % SEQ;
    __shared__ float cs[64], sn[64];
    const int tid = threadIdx.x;
    if (tid < 64) {
        double inv = exp(-9.210340371976184 * ((double)(2 * tid) / 128.0));
        double ang = (double)pos_ids[token] * inv;
        cs[tid] = (float)cos(ang);
        sn[tid] = (float)sin(ang);
    }
    __syncthreads();
    const float* base = qkv + (size_t)token * QKVN;

    for (int p = tid; p < NHEAD * 64; p += 128) {
        int h = p >> 6;
        int i = p & 63;
        float c = cs[i], sv = sn[i];
        size_t ob = ((size_t)(b * NHEAD + h) * SEQ + s) * HDIM;
        float q1 = base[h * HDIM + i];
        float q2 = base[h * HDIM + 64 + i];
        float r1 = q1 * c - q2 * sv;
        float r2 = q2 * c + q1 * sv;
        bf16 hh, ll;
        bfsplit(r1, hh, ll); QH[ob + i] = hh;      QL[ob + i] = ll;
        bfsplit(r2, hh, ll); QH[ob + 64 + i] = hh; QL[ob + 64 + i] = ll;
        float k1 = base[HID + h * HDIM + i];
        float k2 = base[HID + h * HDIM + 64 + i];
        r1 = k1 * c - k2 * sv;
        r2 = k2 * c + k1 * sv;
        bfsplit(r1, hh, ll); KH[ob + i] = hh;      KL[ob + i] = ll;
        bfsplit(r2, hh, ll); KH[ob + 64 + i] = hh; KL[ob + 64 + i] = ll;
    }
    for (int p = tid; p < HID; p += 128) {
        int h = p >> 7;
        int d = p & 127;
        Vh[((size_t)(b * NHEAD + h) * SEQ + s) * HDIM + d] = base[2 * HID + p];
    }
}

// ---------------- tensor-core flash attention (causal) ----------------------
#define QSTR 136
#define VSTR 72
#define oQH 0
#define oQL (oQH + 128 * QSTR * 2)
#define oKH (oQL + 128 * QSTR * 2)
#define oKL (oKH + 2 * 64 * QSTR * 2)
#define oVH (oKL + 2 * 64 * QSTR * 2)
#define oVL (oVH + 2 * 128 * VSTR * 2)
#define ATT_SMEM (oVL + 2 * 128 * VSTR * 2)

__global__ __launch_bounds__(256, 1) void flash_mma(const bf16* __restrict__ QHg,
                                                    const bf16* __restrict__ QLg,
                                                    const bf16* __restrict__ KHg,
                                                    const bf16* __restrict__ KLg,
                                                    const bf16* __restrict__ VtHg,
                                                    const bf16* __restrict__ VtLg,
                                                    bf16* __restrict__ attnH,
                                                    bf16* __restrict__ attnL)
{
    extern __shared__ char asm_buf[];
    const uint32_t sb = smem_u32_of(asm_buf);

    const int tid = threadIdx.x;
    const int warp = tid >> 5, lane = tid & 31;
    const int g = lane >> 2;
    const int lam = lane & 3;
    const int lrow = lane & 15;
    const int lkh = (lane >> 4) << 3;

    const int qt = (int)(gridDim.x - 1 - blockIdx.x);
    const int h = blockIdx.y;
    const int b = blockIdx.z;
    const int qb = qt * 128;
    const size_t hoff = (size_t)(b * NHEAD + h) * SEQ * HDIM;
    const size_t voff = (size_t)(b * NHEAD + h) * HDIM * SEQ;

#pragma unroll
    for (int j = 0; j < 8; ++j) {
        const int i = tid + j * 256;
        const int row = i >> 4;
        const int seg = (i & 15) << 3;
        const uint32_t doff = (uint32_t)(row * QSTR + seg) * 2;
        const size_t soff = hoff + (size_t)(qb + row) * HDIM + seg;
        cp16(sb + oQH + doff, QHg + soff);
        cp16(sb + oQL + doff, QLg + soff);
    }
    cp_commit();

    const int ktmax = 2 * qt + 1;

    auto issueKV = [&](int kt, int buf) {
        const int kb = kt * 64;
#pragma unroll
        for (int j = 0; j < 4; ++j) {
            const int i = tid + j * 256;
            const int krow = i >> 4;
            const int kseg = (i & 15) << 3;
            const uint32_t kdoff = (uint32_t)(krow * QSTR + kseg) * 2;
            const size_t ksoff = hoff + (size_t)(kb + krow) * HDIM + kseg;
            cp16(sb + oKH + buf * (64 * QSTR * 2) + kdoff, KHg + ksoff);
            cp16(sb + oKL + buf * (64 * QSTR * 2) + kdoff, KLg + ksoff);
            const int vrow = i >> 3;
            const int vseg = (i & 7) << 3;
            const uint32_t vdoff = (uint32_t)(vrow * VSTR + vseg) * 2;
            const size_t vsoff = voff + (size_t)vrow * SEQ + kb + vseg;
            cp16(sb + oVH + buf * (128 * VSTR * 2) + vdoff, VtHg + vsoff);
            cp16(sb + oVL + buf * (128 * VSTR * 2) + vdoff, VtLg + vsoff);
        }
    };

    issueKV(0, 0);
    cp_commit();

    float oacc[16][4];
#pragma unroll
    for (int n = 0; n < 16; ++n)
#pragma unroll
        for (int i = 0; i < 4; ++i) oacc[n][i] = 0.f;
    float m0 = -1e30f, m1 = -1e30f, l0 = 0.f, l1 = 0.f;
    const float scale = 0.08838834764831845f;

    const int r0g = qb + warp * 16 + g;
    const int r1g = r0g + 8;

    for (int kt = 0; kt <= ktmax; ++kt) {
        const int kb = kt * 64;
        const int buf = kt & 1;
        if (kt + 1 <= ktmax) {
            issueKV(kt + 1, buf ^ 1);
            cp_commit();
            cp_wait<1>();
        } else {
            cp_wait<0>();
        }
        __syncthreads();

        const uint32_t uQH = sb + oQH, uQL = sb + oQL;
        const uint32_t uKH = sb + oKH + buf * (64 * QSTR * 2);
        const uint32_t uKL = sb + oKL + buf * (64 * QSTR * 2);
        const uint32_t uVH = sb + oVH + buf * (128 * VSTR * 2);
        const uint32_t uVL = sb + oVL + buf * (128 * VSTR * 2);

        float sacc[8][4];
#pragma unroll
        for (int n = 0; n < 8; ++n)
#pragma unroll
            for (int i = 0; i < 4; ++i) sacc[n][i] = 0.f;

#pragma unroll
        for (int ks = 0; ks < 8; ++ks) {
            uint32_t ah[4], al[4];
            const uint32_t aoff = (uint32_t)(((warp * 16 + lrow) * QSTR + ks * 16 + lkh) * 2);
            ldm_x4(ah, uQH + aoff);
            ldm_x4(al, uQL + aoff);
#pragma unroll
            for (int nt = 0; nt < 4; ++nt) {
                uint32_t bh[4], bl[4];
                const uint32_t boff = (uint32_t)(((nt * 16 + lrow) * QSTR + ks * 16 + lkh) * 2);
                ldm_x4(bh, uKH + boff);
                ldm_x4(bl, uKL + boff);
                mma_bf16(sacc[2 * nt],     ah, bh[0], bh[2]);
                mma_bf16(sacc[2 * nt + 1], ah, bh[1], bh[3]);
                mma_bf16(sacc[2 * nt],     ah, bl[0], bl[2]);
                mma_bf16(sacc[2 * nt + 1], ah, bl[1], bl[3]);
                mma_bf16(sacc[2 * nt],     al, bh[0], bh[2]);
                mma_bf16(sacc[2 * nt + 1], al, bh[1], bh[3]);
            }
        }

        const bool need_mask = (kt >= 2 * qt);
        float rm0 = -1e30f, rm1 = -1e30f;
#pragma unroll
        for (int j = 0; j < 8; ++j) {
            const int cg0 = kb + j * 8 + 2 * lam;
#pragma unroll
            for (int i = 0; i < 4; ++i) {
                float v = sacc[j][i] * scale;
                if (need_mask) {
                    const int cg = cg0 + (i & 1);
                    const int rg = (i < 2) ? r0g : r1g;
                    if (cg > rg) v = -1e30f;
                }
                sacc[j][i] = v;
            }
            rm0 = fmaxf(rm0, fmaxf(sacc[j][0], sacc[j][1]));
            rm1 = fmaxf(rm1, fmaxf(sacc[j][2], sacc[j][3]));
        }
#pragma unroll
        for (int off = 1; off <= 2; off <<= 1) {
            rm0 = fmaxf(rm0, __shfl_xor_sync(0xffffffffu, rm0, off));
            rm1 = fmaxf(rm1, __shfl_xor_sync(0xffffffffu, rm1, off));
        }
        const float mn0 = fmaxf(m0, rm0);
        const float mn1 = fmaxf(m1, rm1);
        const float al0 = __expf(m0 - mn0);
        const float al1 = __expf(m1 - mn1);
        m0 = mn0; m1 = mn1;

        float rs0 = 0.f, rs1 = 0.f;
#pragma unroll
        for (int j = 0; j < 8; ++j) {
            sacc[j][0] = __expf(sacc[j][0] - mn0);
            sacc[j][1] = __expf(sacc[j][1] - mn0);
            sacc[j][2] = __expf(sacc[j][2] - mn1);
            sacc[j][3] = __expf(sacc[j][3] - mn1);
            rs0 += sacc[j][0] + sacc[j][1];
            rs1 += sacc[j][2] + sacc[j][3];
        }
#pragma unroll
        for (int off = 1; off <= 2; off <<= 1) {
            rs0 += __shfl_xor_sync(0xffffffffu, rs0, off);
            rs1 += __shfl_xor_sync(0xffffffffu, rs1, off);
        }
        l0 = l0 * al0 + rs0;
        l1 = l1 * al1 + rs1;

#pragma unroll
        for (int n = 0; n < 16; ++n) {
            oacc[n][0] *= al0; oacc[n][1] *= al0;
            oacc[n][2] *= al1; oacc[n][3] *= al1;
        }

        uint32_t pah[4][4], pal[4][4];
#pragma unroll
        for (int j2 = 0; j2 < 4; ++j2) {
            float p00 = sacc[2 * j2][0],     p01 = sacc[2 * j2][1];
            float p02 = sacc[2 * j2][2],     p03 = sacc[2 * j2][3];
            float p10 = sacc[2 * j2 + 1][0], p11 = sacc[2 * j2 + 1][1];
            float p12 = sacc[2 * j2 + 1][2], p13 = sacc[2 * j2 + 1][3];
            pah[j2][0] = pk2(p00, p01);
            pah[j2][1] = pk2(p02, p03);
            pah[j2][2] = pk2(p10, p11);
            pah[j2][3] = pk2(p12, p13);
            bf16 h;
            h = __float2bfloat16_rn(p00); p00 -= __bfloat162float(h);
            h = __float2bfloat16_rn(p01); p01 -= __bfloat162float(h);
            h = __float2bfloat16_rn(p02); p02 -= __bfloat162float(h);
            h = __float2bfloat16_rn(p03); p03 -= __bfloat162float(h);
            h = __float2bfloat16_rn(p10); p10 -= __bfloat162float(h);
            h = __float2bfloat16_rn(p11); p11 -= __bfloat162float(h);
            h = __float2bfloat16_rn(p12); p12 -= __bfloat162float(h);
            h = __float2bfloat16_rn(p13); p13 -= __bfloat162float(h);
            pal[j2][0] = pk2(p00, p01);
            pal[j2][1] = pk2(p02, p03);
            pal[j2][2] = pk2(p10, p11);
            pal[j2][3] = pk2(p12, p13);
        }

#pragma unroll
        for (int nt = 0; nt < 8; ++nt) {
#pragma unroll
            for (int j2 = 0; j2 < 4; ++j2) {
                uint32_t vh[4], vl[4];
                const uint32_t boff = (uint32_t)(((nt * 16 + lrow) * VSTR + j2 * 16 + lkh) * 2);
                ldm_x4(vh, uVH + boff);
                ldm_x4(vl, uVL + boff);
                mma_bf16(oacc[2 * nt],     pah[j2], vh[0], vh[2]);
                mma_bf16(oacc[2 * nt + 1], pah[j2], vh[1], vh[3]);
                mma_bf16(oacc[2 * nt],     pah[j2], vl[0], vl[2]);
                mma_bf16(oacc[2 * nt + 1], pah[j2], vl[1], vl[3]);
                mma_bf16(oacc[2 * nt],     pal[j2], vh[0], vh[2]);
                mma_bf16(oacc[2 * nt + 1], pal[j2], vh[1], vh[3]);
            }
        }
        __syncthreads();
    }

    const float i0 = 1.0f / l0;
    const float i1 = 1.0f / l1;
    const size_t row0 = ((size_t)b * SEQ + r0g) * HID + h * HDIM;
    const size_t row1 = ((size_t)b * SEQ + r1g) * HID + h * HDIM;
#pragma unroll
    for (int n = 0; n < 16; ++n) {
        const int col = n * 8 + 2 * lam;
        float x0 = oacc[n][0] * i0, x1 = oacc[n][1] * i0;
        float y0 = oacc[n][2] * i1, y1 = oacc[n][3] * i1;
        *(uint32_t*)(attnH + row0 + col) = pk2(x0, x1);
        *(uint32_t*)(attnH + row1 + col) = pk2(y0, y1);
        bf16 hb;
        hb = __float2bfloat16_rn(x0); x0 -= __bfloat162float(hb);
        hb = __float2bfloat16_rn(x1); x1 -= __bfloat162float(hb);
        hb = __float2bfloat16_rn(y0); y0 -= __bfloat162float(hb);
        hb = __float2bfloat16_rn(y1); y1 -= __bfloat162float(hb);
        *(uint32_t*)(attnL + row0 + col) = pk2(x0, x1);
        *(uint32_t*)(attnL + row1 + col) = pk2(y0, y1);
    }
}

// ---------------------------------------------------------------------------
extern "C" void kernel_launch(void* const* d_in, const int* in_sizes, int n_in,
                              void* d_out, int out_size)
{
    (void)in_sizes; (void)n_in; (void)out_size;
    const float* hidden = (const float*)d_in[0];
    const float* w_qkv  = (const float*)d_in[1];
    const float* w_o    = (const float*)d_in[2];
    const int*   pos    = (const int*)d_in[3];
    float* out = (float*)d_out;

    float *qkv, *v;
    bf16 *hidH, *hidL, *wqkvtH, *wqkvtL, *wotH, *wotL;
    bf16 *QH, *QL, *KH, *KL, *VtH, *VtL, *attnH, *attnL;
    cudaGetSymbolAddress((void**)&qkv,    g_qkv);
    cudaGetSymbolAddress((void**)&v,      g_v);
    cudaGetSymbolAddress((void**)&hidH,   g_hidH);
    cudaGetSymbolAddress((void**)&hidL,   g_hidL);
    cudaGetSymbolAddress((void**)&wqkvtH, g_wqkvtH);
    cudaGetSymbolAddress((void**)&wqkvtL, g_wqkvtL);
    cudaGetSymbolAddress((void**)&wotH,   g_wotH);
    cudaGetSymbolAddress((void**)&wotL,   g_wotL);
    cudaGetSymbolAddress((void**)&QH,     g_QH);
    cudaGetSymbolAddress((void**)&QL,     g_QL);
    cudaGetSymbolAddress((void**)&KH,     g_KH);
    cudaGetSymbolAddress((void**)&KL,     g_KL);
    cudaGetSymbolAddress((void**)&VtH,    g_VtH);
    cudaGetSymbolAddress((void**)&VtL,    g_VtL);
    cudaGetSymbolAddress((void**)&attnH,  g_attnH);
    cudaGetSymbolAddress((void**)&attnL,  g_attnL);

    // 0) pre-split + transpose inputs
    split_f32<<<(TOKENS * HID) / 1024, 256>>>(hidden, hidH, hidL);
    transpose_split<<<dim3(QKVN / 32, HID / 32), dim3(32, 8)>>>(w_qkv, wqkvtH, wqkvtL, HID, QKVN);
    transpose_split<<<dim3(HID / 32, HID / 32), dim3(32, 8)>>>(w_o, wotH, wotL, HID, HID);

    const int gsmem = NSTG * STG_BYTES;   // 81920 -> 2 CTAs/SM
    cudaFuncSetAttribute(gemm_bf3, cudaFuncAttributeMaxDynamicSharedMemorySize, gsmem);

    // 1) QKV projection
    gemm_bf3<<<(TOKENS / 128) * (QKVN / 128), 256, gsmem>>>(
        hidH, hidL, wqkvtH, wqkvtL, qkv, TOKENS, QKVN, HID, TOKENS / 128);

    // 2) RoPE + split to head-major bf16; V fp32 head-major
    rope_split2<<<TOKENS, 128>>>(qkv, pos, QH, QL, KH, KL, v);

    // 3) V transpose + split per head
    vt_split<<<dim3(SEQ / 32, HDIM / 32, HEADS), dim3(32, 8)>>>(v, VtH, VtL);

    // 4) tensor-core causal flash attention -> pre-split attn
    cudaFuncSetAttribute(flash_mma, cudaFuncAttributeMaxDynamicSharedMemorySize, ATT_SMEM);
    flash_mma<<<dim3(SEQ / 128, NHEAD, BATCH), 256, ATT_SMEM>>>(
        QH, QL, KH, KL, VtH, VtL, attnH, attnL);

    // 5) output projection
    gemm_bf3<<<(TOKENS / 128) * (HID / 128), 256, gsmem>>>(
        attnH, attnL, wotH, wotL, out, TOKENS, HID, HID, TOKENS / 128);
}

// round 6
// speedup vs baseline: 3.5144x; 1.1605x over previous
#include <cuda_runtime.h>
#include <cuda_bf16.h>
#include <math.h>
#include <stdint.h>

#define BATCH 2
#define SEQ   2048
#define HID   4096
#define NHEAD 32
#define HDIM  128
#define TOKENS (BATCH * SEQ)     // 4096
#define QKVN  (3 * HID)          // 12288
#define HEADS (BATCH * NHEAD)    // 64

typedef __nv_bfloat16 bf16;

// ---------------- scratch (device globals; no allocation allowed) ----------
__device__ float g_qkv[(size_t)TOKENS * QKVN];
__device__ float g_v[(size_t)HEADS * SEQ * HDIM];
__device__ bf16  g_hidH[(size_t)TOKENS * HID];
__device__ bf16  g_hidL[(size_t)TOKENS * HID];
__device__ bf16  g_wqkvtH[(size_t)QKVN * HID];
__device__ bf16  g_wqkvtL[(size_t)QKVN * HID];
__device__ bf16  g_wotH[(size_t)HID * HID];
__device__ bf16  g_wotL[(size_t)HID * HID];
__device__ bf16  g_QH[(size_t)HEADS * SEQ * HDIM];
__device__ bf16  g_QL[(size_t)HEADS * SEQ * HDIM];
__device__ bf16  g_KH[(size_t)HEADS * SEQ * HDIM];
__device__ bf16  g_KL[(size_t)HEADS * SEQ * HDIM];
__device__ bf16  g_VtH[(size_t)HEADS * HDIM * SEQ];
__device__ bf16  g_VtL[(size_t)HEADS * HDIM * SEQ];
__device__ bf16  g_attnH[(size_t)TOKENS * HID];
__device__ bf16  g_attnL[(size_t)TOKENS * HID];

// ======================= helpers ==================================
__device__ __forceinline__ uint32_t smem_u32_of(const void* p) {
    uint32_t a;
    asm("{ .reg .u64 t; cvta.to.shared.u64 t, %1; cvt.u32.u64 %0, t; }" : "=r"(a) : "l"(p));
    return a;
}
__device__ __forceinline__ void ldm_x4(uint32_t* r, uint32_t addr) {
    asm volatile("ldmatrix.sync.aligned.m8n8.x4.shared.b16 {%0,%1,%2,%3}, [%4];"
                 : "=r"(r[0]), "=r"(r[1]), "=r"(r[2]), "=r"(r[3]) : "r"(addr));
}
__device__ __forceinline__ void mma_bf16(float* d, const uint32_t* a, uint32_t b0, uint32_t b1) {
    asm volatile(
        "mma.sync.aligned.m16n8k16.row.col.f32.bf16.bf16.f32 "
        "{%0,%1,%2,%3},{%4,%5,%6,%7},{%8,%9},{%0,%1,%2,%3};"
        : "+f"(d[0]), "+f"(d[1]), "+f"(d[2]), "+f"(d[3])
        : "r"(a[0]), "r"(a[1]), "r"(a[2]), "r"(a[3]), "r"(b0), "r"(b1));
}
__device__ __forceinline__ void bfsplit(float x, bf16& hi, bf16& lo) {
    hi = __float2bfloat16_rn(x);
    lo = __float2bfloat16_rn(x - __bfloat162float(hi));
}
__device__ __forceinline__ uint32_t pk2(float a, float b) {
    __nv_bfloat162 t = __floats2bfloat162_rn(a, b);
    return *(uint32_t*)&t;
}
__device__ __forceinline__ void cp16(uint32_t smem, const void* g) {
    asm volatile("cp.async.cg.shared.global [%0], [%1], 16;" :: "r"(smem), "l"(g) : "memory");
}
__device__ __forceinline__ void cp_commit() {
    asm volatile("cp.async.commit_group;" ::: "memory");
}
template <int N> __device__ __forceinline__ void cp_wait() {
    asm volatile("cp.async.wait_group %0;" :: "n"(N) : "memory");
}

// ============ pre-split bf16 tensor-core GEMM (3-term compensated) ==========
// KC=32, KCP=32 (no pad) with XOR swizzle: phys16Bchunk = chunk ^ ((row>>1)&3)
#define KC  32
#define KCP 32
#define STG_ARR (128 * KCP * 2)      // 8192 B
#define STG_BYTES (4 * STG_ARR)      // 32768 B
#define NSTG 3                        // 98304 B total -> 2 CTAs/SM

__global__ __launch_bounds__(256, 2) void gemm_bf3(const bf16* __restrict__ Ah,
                                                   const bf16* __restrict__ Al,
                                                   const bf16* __restrict__ Bh,
                                                   const bf16* __restrict__ Bl,
                                                   float* __restrict__ C,
                                                   int M, int N, int K, int Mtiles)
{
    extern __shared__ char gsm[];
    const uint32_t sbase = smem_u32_of(gsm);

    const int tid = threadIdx.x;
    const int warp = tid >> 5, lane = tid & 31;
    const int wm = warp & 3;
    const int wn = warp >> 2;

    const int bx = blockIdx.x;
    const int group = bx / (Mtiles * 8);
    const int rr = bx % (Mtiles * 8);
    const int bm = rr % Mtiles;
    const int bn = group * 8 + rr / Mtiles;

    const bf16* Aph = Ah + (size_t)bm * 128 * K;
    const bf16* Apl = Al + (size_t)bm * 128 * K;
    const bf16* Bph = Bh + (size_t)bn * 128 * K;
    const bf16* Bpl = Bl + (size_t)bn * 128 * K;

    const int lrow = lane & 15;
    const int lc_half = lane >> 4;    // 0/1 -> logical chunk low bit

    float acc[2][8][4];
#pragma unroll
    for (int t = 0; t < 2; ++t)
#pragma unroll
        for (int n = 0; n < 8; ++n)
#pragma unroll
            for (int i = 0; i < 4; ++i) acc[t][n][i] = 0.f;

    const int nc = K / KC;   // 128

    auto issue = [&](int c, int st) {
        const int kc = c * KC;
        const uint32_t sb = sbase + st * STG_BYTES;
#pragma unroll
        for (int q = 0; q < 2; ++q) {
            const int i = tid + q * 256;      // 0..511
            const int row = i >> 2;
            const int chunk = i & 3;
            const int pchunk = chunk ^ ((row >> 1) & 3);
            const uint32_t doff = (uint32_t)(row * 64 + pchunk * 16);
            const size_t soff = (size_t)row * K + kc + chunk * 8;
            cp16(sb + 0 * STG_ARR + doff, Aph + soff);
            cp16(sb + 1 * STG_ARR + doff, Apl + soff);
            cp16(sb + 2 * STG_ARR + doff, Bph + soff);
            cp16(sb + 3 * STG_ARR + doff, Bpl + soff);
        }
    };

    // prologue: chunks 0 and 1
    issue(0, 0); cp_commit();
    issue(1, 1); cp_commit();

    for (int c = 0; c < nc; ++c) {
        // drain chunk c (keep newest pending if it exists)
        if (c + 1 < nc) cp_wait<1>();
        else cp_wait<0>();
        __syncthreads();                     // the ONLY barrier per chunk

        if (c + 2 < nc) { issue(c + 2, (c + 2) % NSTG); cp_commit(); }

        const int st = c % NSTG;
        const uint32_t uAh = sbase + st * STG_BYTES;
        const uint32_t uAl = uAh + STG_ARR;
        const uint32_t uBh = uAh + 2 * STG_ARR;
        const uint32_t uBl = uAh + 3 * STG_ARR;

#pragma unroll
        for (int ks = 0; ks < 2; ++ks) {
            const int lc = ks * 2 + lc_half;
            uint32_t ah[2][4], al[2][4];
#pragma unroll
            for (int t = 0; t < 2; ++t) {
                const int ar = wm * 32 + t * 16 + lrow;
                const uint32_t aoff = (uint32_t)(ar * 64 + (lc ^ ((ar >> 1) & 3)) * 16);
                ldm_x4(ah[t], uAh + aoff);
                ldm_x4(al[t], uAl + aoff);
            }
#pragma unroll
            for (int nt = 0; nt < 4; ++nt) {
                const int br = wn * 64 + nt * 16 + lrow;
                const uint32_t boff = (uint32_t)(br * 64 + (lc ^ ((br >> 1) & 3)) * 16);
                uint32_t bh[4], bl[4];
                ldm_x4(bh, uBh + boff);
                ldm_x4(bl, uBl + boff);
#pragma unroll
                for (int t = 0; t < 2; ++t) {
                    mma_bf16(acc[t][2 * nt],     ah[t], bh[0], bh[2]);
                    mma_bf16(acc[t][2 * nt + 1], ah[t], bh[1], bh[3]);
                    mma_bf16(acc[t][2 * nt],     ah[t], bl[0], bl[2]);
                    mma_bf16(acc[t][2 * nt + 1], ah[t], bl[1], bl[3]);
                    mma_bf16(acc[t][2 * nt],     al[t], bh[0], bh[2]);
                    mma_bf16(acc[t][2 * nt + 1], al[t], bh[1], bh[3]);
                }
            }
        }
    }

    const int g = lane >> 2;
    const int tc2 = (lane & 3) << 1;
#pragma unroll
    for (int t = 0; t < 2; ++t) {
        const int row0 = bm * 128 + wm * 32 + t * 16 + g;
#pragma unroll
        for (int n = 0; n < 8; ++n) {
            const int col = bn * 128 + wn * 64 + n * 8 + tc2;
            *(float2*)(C + (size_t)row0 * N + col) = make_float2(acc[t][n][0], acc[t][n][1]);
            *(float2*)(C + (size_t)(row0 + 8) * N + col) = make_float2(acc[t][n][2], acc[t][n][3]);
        }
    }
}

// ---------------- elementwise split fp32 -> bf16 hi/lo ----------------------
__global__ __launch_bounds__(256) void split_f32(const float* __restrict__ in,
                                                 bf16* __restrict__ hi,
                                                 bf16* __restrict__ lo)
{
    const size_t i4 = (size_t)blockIdx.x * 256 + threadIdx.x;
    float4 v = *(const float4*)(in + i4 * 4);
    bf16 h[4], l[4];
    bfsplit(v.x, h[0], l[0]); bfsplit(v.y, h[1], l[1]);
    bfsplit(v.z, h[2], l[2]); bfsplit(v.w, h[3], l[3]);
    *(uint2*)(hi + i4 * 4) = *(uint2*)h;
    *(uint2*)(lo + i4 * 4) = *(uint2*)l;
}

// ---------------- transpose + split ------------------------------------------
__global__ __launch_bounds__(256) void transpose_split(const float* __restrict__ in,
                                                       bf16* __restrict__ outH,
                                                       bf16* __restrict__ outL,
                                                       int R, int Cc)
{
    __shared__ float t[32][33];
    const int c = blockIdx.x * 32 + threadIdx.x;
    const int r0 = blockIdx.y * 32 + threadIdx.y;
#pragma unroll
    for (int i = 0; i < 4; ++i)
        t[threadIdx.y + i * 8][threadIdx.x] = in[(size_t)(r0 + i * 8) * Cc + c];
    __syncthreads();
    const int rc = blockIdx.y * 32 + threadIdx.x;
    const int c0 = blockIdx.x * 32 + threadIdx.y;
#pragma unroll
    for (int i = 0; i < 4; ++i) {
        float v = t[threadIdx.x][threadIdx.y + i * 8];
        bf16 h, l;
        bfsplit(v, h, l);
        outH[(size_t)(c0 + i * 8) * R + rc] = h;
        outL[(size_t)(c0 + i * 8) * R + rc] = l;
    }
}

// ---------------- V transpose + split ----------------------------------------
__global__ __launch_bounds__(256) void vt_split(const float* __restrict__ Vg,
                                                bf16* __restrict__ VtH,
                                                bf16* __restrict__ VtL)
{
    __shared__ float t[32][33];
    const int bh = blockIdx.z;
    const float* in = Vg + (size_t)bh * SEQ * HDIM;
    const int s0 = blockIdx.x * 32;
    const int d0 = blockIdx.y * 32;
#pragma unroll
    for (int i = 0; i < 4; ++i)
        t[threadIdx.y + i * 8][threadIdx.x] = in[(size_t)(s0 + threadIdx.y + i * 8) * HDIM + d0 + threadIdx.x];
    __syncthreads();
    bf16* oh = VtH + (size_t)bh * HDIM * SEQ;
    bf16* ol = VtL + (size_t)bh * HDIM * SEQ;
#pragma unroll
    for (int i = 0; i < 4; ++i) {
        float v = t[threadIdx.x][threadIdx.y + i * 8];
        bf16 h, l;
        bfsplit(v, h, l);
        oh[(size_t)(d0 + threadIdx.y + i * 8) * SEQ + s0 + threadIdx.x] = h;
        ol[(size_t)(d0 + threadIdx.y + i * 8) * SEQ + s0 + threadIdx.x] = l;
    }
}

// ---------------- RoPE (NeoX) + split ----------------------------------------
__global__ __launch_bounds__(128) void rope_split2(const float* __restrict__ qkv,
                                                   const int* __restrict__ pos_ids,
                                                   bf16* __restrict__ QH, bf16* __restrict__ QL,
                                                   bf16* __restrict__ KH, bf16* __restrict__ KL,
                                                   float* __restrict__ Vh)
{
    const int token = blockIdx.x;
    const int b = token / SEQ;
    const int s = token % SEQ;
    __shared__ float cs[64], sn[64];
    const int tid = threadIdx.x;
    if (tid < 64) {
        double inv = exp(-9.210340371976184 * ((double)(2 * tid) / 128.0));
        double ang = (double)pos_ids[token] * inv;
        cs[tid] = (float)cos(ang);
        sn[tid] = (float)sin(ang);
    }
    __syncthreads();
    const float* base = qkv + (size_t)token * QKVN;

    for (int p = tid; p < NHEAD * 64; p += 128) {
        int h = p >> 6;
        int i = p & 63;
        float c = cs[i], sv = sn[i];
        size_t ob = ((size_t)(b * NHEAD + h) * SEQ + s) * HDIM;
        float q1 = base[h * HDIM + i];
        float q2 = base[h * HDIM + 64 + i];
        float r1 = q1 * c - q2 * sv;
        float r2 = q2 * c + q1 * sv;
        bf16 hh, ll;
        bfsplit(r1, hh, ll); QH[ob + i] = hh;      QL[ob + i] = ll;
        bfsplit(r2, hh, ll); QH[ob + 64 + i] = hh; QL[ob + 64 + i] = ll;
        float k1 = base[HID + h * HDIM + i];
        float k2 = base[HID + h * HDIM + 64 + i];
        r1 = k1 * c - k2 * sv;
        r2 = k2 * c + k1 * sv;
        bfsplit(r1, hh, ll); KH[ob + i] = hh;      KL[ob + i] = ll;
        bfsplit(r2, hh, ll); KH[ob + 64 + i] = hh; KL[ob + 64 + i] = ll;
    }
    for (int p = tid; p < HID; p += 128) {
        int h = p >> 7;
        int d = p & 127;
        Vh[((size_t)(b * NHEAD + h) * SEQ + s) * HDIM + d] = base[2 * HID + p];
    }
}

// ---------------- tensor-core flash attention (causal) ----------------------
#define QSTR 136
#define VSTR 72
#define oQH 0
#define oQL (oQH + 128 * QSTR * 2)
#define oKH (oQL + 128 * QSTR * 2)
#define oKL (oKH + 2 * 64 * QSTR * 2)
#define oVH (oKL + 2 * 64 * QSTR * 2)
#define oVL (oVH + 2 * 128 * VSTR * 2)
#define ATT_SMEM (oVL + 2 * 128 * VSTR * 2)

__global__ __launch_bounds__(256, 1) void flash_mma(const bf16* __restrict__ QHg,
                                                    const bf16* __restrict__ QLg,
                                                    const bf16* __restrict__ KHg,
                                                    const bf16* __restrict__ KLg,
                                                    const bf16* __restrict__ VtHg,
                                                    const bf16* __restrict__ VtLg,
                                                    bf16* __restrict__ attnH,
                                                    bf16* __restrict__ attnL)
{
    extern __shared__ char asm_buf[];
    const uint32_t sb = smem_u32_of(asm_buf);

    const int tid = threadIdx.x;
    const int warp = tid >> 5, lane = tid & 31;
    const int g = lane >> 2;
    const int lam = lane & 3;
    const int lrow = lane & 15;
    const int lkh = (lane >> 4) << 3;

    const int qt = (int)(gridDim.x - 1 - blockIdx.x);
    const int h = blockIdx.y;
    const int b = blockIdx.z;
    const int qb = qt * 128;
    const size_t hoff = (size_t)(b * NHEAD + h) * SEQ * HDIM;
    const size_t voff = (size_t)(b * NHEAD + h) * HDIM * SEQ;

#pragma unroll
    for (int j = 0; j < 8; ++j) {
        const int i = tid + j * 256;
        const int row = i >> 4;
        const int seg = (i & 15) << 3;
        const uint32_t doff = (uint32_t)(row * QSTR + seg) * 2;
        const size_t soff = hoff + (size_t)(qb + row) * HDIM + seg;
        cp16(sb + oQH + doff, QHg + soff);
        cp16(sb + oQL + doff, QLg + soff);
    }
    cp_commit();

    const int ktmax = 2 * qt + 1;

    auto issueKV = [&](int kt, int buf) {
        const int kb = kt * 64;
#pragma unroll
        for (int j = 0; j < 4; ++j) {
            const int i = tid + j * 256;
            const int krow = i >> 4;
            const int kseg = (i & 15) << 3;
            const uint32_t kdoff = (uint32_t)(krow * QSTR + kseg) * 2;
            const size_t ksoff = hoff + (size_t)(kb + krow) * HDIM + kseg;
            cp16(sb + oKH + buf * (64 * QSTR * 2) + kdoff, KHg + ksoff);
            cp16(sb + oKL + buf * (64 * QSTR * 2) + kdoff, KLg + ksoff);
            const int vrow = i >> 3;
            const int vseg = (i & 7) << 3;
            const uint32_t vdoff = (uint32_t)(vrow * VSTR + vseg) * 2;
            const size_t vsoff = voff + (size_t)vrow * SEQ + kb + vseg;
            cp16(sb + oVH + buf * (128 * VSTR * 2) + vdoff, VtHg + vsoff);
            cp16(sb + oVL + buf * (128 * VSTR * 2) + vdoff, VtLg + vsoff);
        }
    };

    issueKV(0, 0);
    cp_commit();

    float oacc[16][4];
#pragma unroll
    for (int n = 0; n < 16; ++n)
#pragma unroll
        for (int i = 0; i < 4; ++i) oacc[n][i] = 0.f;
    float m0 = -1e30f, m1 = -1e30f, l0 = 0.f, l1 = 0.f;
    const float scale2 = 0.1275174324f;   // (1/sqrt(128)) * log2(e)

    const int r0g = qb + warp * 16 + g;
    const int r1g = r0g + 8;

    for (int kt = 0; kt <= ktmax; ++kt) {
        const int kb = kt * 64;
        const int buf = kt & 1;

        cp_wait<0>();
        __syncthreads();                       // single barrier per k-tile
        if (kt < ktmax) { issueKV(kt + 1, buf ^ 1); cp_commit(); }

        const uint32_t uQH = sb + oQH, uQL = sb + oQL;
        const uint32_t uKH = sb + oKH + buf * (64 * QSTR * 2);
        const uint32_t uKL = sb + oKL + buf * (64 * QSTR * 2);
        const uint32_t uVH = sb + oVH + buf * (128 * VSTR * 2);
        const uint32_t uVL = sb + oVL + buf * (128 * VSTR * 2);

        float sacc[8][4];
#pragma unroll
        for (int n = 0; n < 8; ++n)
#pragma unroll
            for (int i = 0; i < 4; ++i) sacc[n][i] = 0.f;

#pragma unroll
        for (int ks = 0; ks < 8; ++ks) {
            uint32_t ah[4], al[4];
            const uint32_t aoff = (uint32_t)(((warp * 16 + lrow) * QSTR + ks * 16 + lkh) * 2);
            ldm_x4(ah, uQH + aoff);
            ldm_x4(al, uQL + aoff);
#pragma unroll
            for (int nt = 0; nt < 4; ++nt) {
                uint32_t bh[4], bl[4];
                const uint32_t boff = (uint32_t)(((nt * 16 + lrow) * QSTR + ks * 16 + lkh) * 2);
                ldm_x4(bh, uKH + boff);
                ldm_x4(bl, uKL + boff);
                mma_bf16(sacc[2 * nt],     ah, bh[0], bh[2]);
                mma_bf16(sacc[2 * nt + 1], ah, bh[1], bh[3]);
                mma_bf16(sacc[2 * nt],     ah, bl[0], bl[2]);
                mma_bf16(sacc[2 * nt + 1], ah, bl[1], bl[3]);
                mma_bf16(sacc[2 * nt],     al, bh[0], bh[2]);
                mma_bf16(sacc[2 * nt + 1], al, bh[1], bh[3]);
            }
        }

        const bool need_mask = (kt >= 2 * qt);
        float rm0 = -1e30f, rm1 = -1e30f;
#pragma unroll
        for (int j = 0; j < 8; ++j) {
            const int cg0 = kb + j * 8 + 2 * lam;
#pragma unroll
            for (int i = 0; i < 4; ++i) {
                float v = sacc[j][i] * scale2;      // log2 domain
                if (need_mask) {
                    const int cg = cg0 + (i & 1);
                    const int rg = (i < 2) ? r0g : r1g;
                    if (cg > rg) v = -1e30f;
                }
                sacc[j][i] = v;
            }
            rm0 = fmaxf(rm0, fmaxf(sacc[j][0], sacc[j][1]));
            rm1 = fmaxf(rm1, fmaxf(sacc[j][2], sacc[j][3]));
        }
#pragma unroll
        for (int off = 1; off <= 2; off <<= 1) {
            rm0 = fmaxf(rm0, __shfl_xor_sync(0xffffffffu, rm0, off));
            rm1 = fmaxf(rm1, __shfl_xor_sync(0xffffffffu, rm1, off));
        }
        const float mn0 = fmaxf(m0, rm0);
        const float mn1 = fmaxf(m1, rm1);
        const float al0 = exp2f(m0 - mn0);
        const float al1 = exp2f(m1 - mn1);
        m0 = mn0; m1 = mn1;

        float rs0 = 0.f, rs1 = 0.f;
#pragma unroll
        for (int j = 0; j < 8; ++j) {
            sacc[j][0] = exp2f(sacc[j][0] - mn0);
            sacc[j][1] = exp2f(sacc[j][1] - mn0);
            sacc[j][2] = exp2f(sacc[j][2] - mn1);
            sacc[j][3] = exp2f(sacc[j][3] - mn1);
            rs0 += sacc[j][0] + sacc[j][1];
            rs1 += sacc[j][2] + sacc[j][3];
        }
#pragma unroll
        for (int off = 1; off <= 2; off <<= 1) {
            rs0 += __shfl_xor_sync(0xffffffffu, rs0, off);
            rs1 += __shfl_xor_sync(0xffffffffu, rs1, off);
        }
        l0 = l0 * al0 + rs0;
        l1 = l1 * al1 + rs1;

#pragma unroll
        for (int n = 0; n < 16; ++n) {
            oacc[n][0] *= al0; oacc[n][1] *= al0;
            oacc[n][2] *= al1; oacc[n][3] *= al1;
        }

        uint32_t pah[4][4], pal[4][4];
#pragma unroll
        for (int j2 = 0; j2 < 4; ++j2) {
            float p00 = sacc[2 * j2][0],     p01 = sacc[2 * j2][1];
            float p02 = sacc[2 * j2][2],     p03 = sacc[2 * j2][3];
            float p10 = sacc[2 * j2 + 1][0], p11 = sacc[2 * j2 + 1][1];
            float p12 = sacc[2 * j2 + 1][2], p13 = sacc[2 * j2 + 1][3];
            pah[j2][0] = pk2(p00, p01);
            pah[j2][1] = pk2(p02, p03);
            pah[j2][2] = pk2(p10, p11);
            pah[j2][3] = pk2(p12, p13);
            bf16 hh;
            hh = __float2bfloat16_rn(p00); p00 -= __bfloat162float(hh);
            hh = __float2bfloat16_rn(p01); p01 -= __bfloat162float(hh);
            hh = __float2bfloat16_rn(p02); p02 -= __bfloat162float(hh);
            hh = __float2bfloat16_rn(p03); p03 -= __bfloat162float(hh);
            hh = __float2bfloat16_rn(p10); p10 -= __bfloat162float(hh);
            hh = __float2bfloat16_rn(p11); p11 -= __bfloat162float(hh);
            hh = __float2bfloat16_rn(p12); p12 -= __bfloat162float(hh);
            hh = __float2bfloat16_rn(p13); p13 -= __bfloat162float(hh);
            pal[j2][0] = pk2(p00, p01);
            pal[j2][1] = pk2(p02, p03);
            pal[j2][2] = pk2(p10, p11);
            pal[j2][3] = pk2(p12, p13);
        }

#pragma unroll
        for (int nt = 0; nt < 8; ++nt) {
#pragma unroll
            for (int j2 = 0; j2 < 4; ++j2) {
                uint32_t vh[4], vl[4];
                const uint32_t boff = (uint32_t)(((nt * 16 + lrow) * VSTR + j2 * 16 + lkh) * 2);
                ldm_x4(vh, uVH + boff);
                ldm_x4(vl, uVL + boff);
                mma_bf16(oacc[2 * nt],     pah[j2], vh[0], vh[2]);
                mma_bf16(oacc[2 * nt + 1], pah[j2], vh[1], vh[3]);
                mma_bf16(oacc[2 * nt],     pah[j2], vl[0], vl[2]);
                mma_bf16(oacc[2 * nt + 1], pah[j2], vl[1], vl[3]);
                mma_bf16(oacc[2 * nt],     pal[j2], vh[0], vh[2]);
                mma_bf16(oacc[2 * nt + 1], pal[j2], vh[1], vh[3]);
            }
        }
    }

    const float i0 = 1.0f / l0;
    const float i1 = 1.0f / l1;
    const size_t row0 = ((size_t)b * SEQ + r0g) * HID + h * HDIM;
    const size_t row1 = ((size_t)b * SEQ + r1g) * HID + h * HDIM;
#pragma unroll
    for (int n = 0; n < 16; ++n) {
        const int col = n * 8 + 2 * lam;
        float x0 = oacc[n][0] * i0, x1 = oacc[n][1] * i0;
        float y0 = oacc[n][2] * i1, y1 = oacc[n][3] * i1;
        *(uint32_t*)(attnH + row0 + col) = pk2(x0, x1);
        *(uint32_t*)(attnH + row1 + col) = pk2(y0, y1);
        bf16 hb;
        hb = __float2bfloat16_rn(x0); x0 -= __bfloat162float(hb);
        hb = __float2bfloat16_rn(x1); x1 -= __bfloat162float(hb);
        hb = __float2bfloat16_rn(y0); y0 -= __bfloat162float(hb);
        hb = __float2bfloat16_rn(y1); y1 -= __bfloat162float(hb);
        *(uint32_t*)(attnL + row0 + col) = pk2(x0, x1);
        *(uint32_t*)(attnL + row1 + col) = pk2(y0, y1);
    }
}

// ---------------------------------------------------------------------------
extern "C" void kernel_launch(void* const* d_in, const int* in_sizes, int n_in,
                              void* d_out, int out_size)
{
    (void)in_sizes; (void)n_in; (void)out_size;
    const float* hidden = (const float*)d_in[0];
    const float* w_qkv  = (const float*)d_in[1];
    const float* w_o    = (const float*)d_in[2];
    const int*   pos    = (const int*)d_in[3];
    float* out = (float*)d_out;

    float *qkv, *v;
    bf16 *hidH, *hidL, *wqkvtH, *wqkvtL, *wotH, *wotL;
    bf16 *QH, *QL, *KH, *KL, *VtH, *VtL, *attnH, *attnL;
    cudaGetSymbolAddress((void**)&qkv,    g_qkv);
    cudaGetSymbolAddress((void**)&v,      g_v);
    cudaGetSymbolAddress((void**)&hidH,   g_hidH);
    cudaGetSymbolAddress((void**)&hidL,   g_hidL);
    cudaGetSymbolAddress((void**)&wqkvtH, g_wqkvtH);
    cudaGetSymbolAddress((void**)&wqkvtL, g_wqkvtL);
    cudaGetSymbolAddress((void**)&wotH,   g_wotH);
    cudaGetSymbolAddress((void**)&wotL,   g_wotL);
    cudaGetSymbolAddress((void**)&QH,     g_QH);
    cudaGetSymbolAddress((void**)&QL,     g_QL);
    cudaGetSymbolAddress((void**)&KH,     g_KH);
    cudaGetSymbolAddress((void**)&KL,     g_KL);
    cudaGetSymbolAddress((void**)&VtH,    g_VtH);
    cudaGetSymbolAddress((void**)&VtL,    g_VtL);
    cudaGetSymbolAddress((void**)&attnH,  g_attnH);
    cudaGetSymbolAddress((void**)&attnL,  g_attnL);

    // 0) pre-split + transpose inputs
    split_f32<<<(TOKENS * HID) / 1024, 256>>>(hidden, hidH, hidL);
    transpose_split<<<dim3(QKVN / 32, HID / 32), dim3(32, 8)>>>(w_qkv, wqkvtH, wqkvtL, HID, QKVN);
    transpose_split<<<dim3(HID / 32, HID / 32), dim3(32, 8)>>>(w_o, wotH, wotL, HID, HID);

    const int gsmem = NSTG * STG_BYTES;   // 98304 -> 2 CTAs/SM
    cudaFuncSetAttribute(gemm_bf3, cudaFuncAttributeMaxDynamicSharedMemorySize, gsmem);

    // 1) QKV projection
    gemm_bf3<<<(TOKENS / 128) * (QKVN / 128), 256, gsmem>>>(
        hidH, hidL, wqkvtH, wqkvtL, qkv, TOKENS, QKVN, HID, TOKENS / 128);

    // 2) RoPE + split to head-major bf16; V fp32 head-major
    rope_split2<<<TOKENS, 128>>>(qkv, pos, QH, QL, KH, KL, v);

    // 3) V transpose + split per head
    vt_split<<<dim3(SEQ / 32, HDIM / 32, HEADS), dim3(32, 8)>>>(v, VtH, VtL);

    // 4) tensor-core causal flash attention -> pre-split attn
    cudaFuncSetAttribute(flash_mma, cudaFuncAttributeMaxDynamicSharedMemorySize, ATT_SMEM);
    flash_mma<<<dim3(SEQ / 128, NHEAD, BATCH), 256, ATT_SMEM>>>(
        QH, QL, KH, KL, VtH, VtL, attnH, attnL);

    // 5) output projection
    gemm_bf3<<<(TOKENS / 128) * (HID / 128), 256, gsmem>>>(
        attnH, attnL, wotH, wotL, out, TOKENS, HID, HID, TOKENS / 128);
}

// round 7
// speedup vs baseline: 3.5488x; 1.0098x over previous
#include <cuda_runtime.h>
#include <cuda_bf16.h>
#include <math.h>
#include <stdint.h>

#define BATCH 2
#define SEQ   2048
#define HID   4096
#define NHEAD 32
#define HDIM  128
#define TOKENS (BATCH * SEQ)     // 4096
#define QKVN  (3 * HID)          // 12288
#define HEADS (BATCH * NHEAD)    // 64

typedef __nv_bfloat16 bf16;

// ---------------- scratch (device globals; no allocation allowed) ----------
__device__ float g_qkv[(size_t)TOKENS * QKVN];
__device__ float g_v[(size_t)HEADS * SEQ * HDIM];
__device__ bf16  g_hidH[(size_t)TOKENS * HID];
__device__ bf16  g_hidL[(size_t)TOKENS * HID];
__device__ bf16  g_wqkvtH[(size_t)QKVN * HID];
__device__ bf16  g_wqkvtL[(size_t)QKVN * HID];
__device__ bf16  g_wotH[(size_t)HID * HID];
__device__ bf16  g_wotL[(size_t)HID * HID];
__device__ bf16  g_QH[(size_t)HEADS * SEQ * HDIM];
__device__ bf16  g_QL[(size_t)HEADS * SEQ * HDIM];
__device__ bf16  g_KH[(size_t)HEADS * SEQ * HDIM];
__device__ bf16  g_KL[(size_t)HEADS * SEQ * HDIM];
__device__ bf16  g_VtH[(size_t)HEADS * HDIM * SEQ];
__device__ bf16  g_VtL[(size_t)HEADS * HDIM * SEQ];
__device__ bf16  g_attnH[(size_t)TOKENS * HID];
__device__ bf16  g_attnL[(size_t)TOKENS * HID];

// ======================= helpers ==================================
__device__ __forceinline__ uint32_t smem_u32_of(const void* p) {
    uint32_t a;
    asm("{ .reg .u64 t; cvta.to.shared.u64 t, %1; cvt.u32.u64 %0, t; }" : "=r"(a) : "l"(p));
    return a;
}
__device__ __forceinline__ void ldm_x4(uint32_t* r, uint32_t addr) {
    asm volatile("ldmatrix.sync.aligned.m8n8.x4.shared.b16 {%0,%1,%2,%3}, [%4];"
                 : "=r"(r[0]), "=r"(r[1]), "=r"(r[2]), "=r"(r[3]) : "r"(addr));
}
__device__ __forceinline__ void mma_bf16(float* d, const uint32_t* a, uint32_t b0, uint32_t b1) {
    asm volatile(
        "mma.sync.aligned.m16n8k16.row.col.f32.bf16.bf16.f32 "
        "{%0,%1,%2,%3},{%4,%5,%6,%7},{%8,%9},{%0,%1,%2,%3};"
        : "+f"(d[0]), "+f"(d[1]), "+f"(d[2]), "+f"(d[3])
        : "r"(a[0]), "r"(a[1]), "r"(a[2]), "r"(a[3]), "r"(b0), "r"(b1));
}
__device__ __forceinline__ void bfsplit(float x, bf16& hi, bf16& lo) {
    hi = __float2bfloat16_rn(x);
    lo = __float2bfloat16_rn(x - __bfloat162float(hi));
}
__device__ __forceinline__ uint32_t pk2(float a, float b) {
    __nv_bfloat162 t = __floats2bfloat162_rn(a, b);
    return *(uint32_t*)&t;
}
__device__ __forceinline__ void cp16(uint32_t smem, const void* g) {
    asm volatile("cp.async.cg.shared.global [%0], [%1], 16;" :: "r"(smem), "l"(g) : "memory");
}
__device__ __forceinline__ void cp_commit() {
    asm volatile("cp.async.commit_group;" ::: "memory");
}
template <int N> __device__ __forceinline__ void cp_wait() {
    asm volatile("cp.async.wait_group %0;" :: "n"(N) : "memory");
}

// ============ pre-split bf16 tensor-core GEMM (3-term compensated) ==========
#define KC  32
#define KCP 32
#define STG_ARR (128 * KCP * 2)      // 8192 B
#define STG_BYTES (4 * STG_ARR)      // 32768 B
#define NSTG 3                        // 98304 B total -> 2 CTAs/SM

__global__ __launch_bounds__(256, 2) void gemm_bf3(const bf16* __restrict__ Ah,
                                                   const bf16* __restrict__ Al,
                                                   const bf16* __restrict__ Bh,
                                                   const bf16* __restrict__ Bl,
                                                   float* __restrict__ C,
                                                   int M, int N, int K, int Mtiles)
{
    extern __shared__ char gsm[];
    const uint32_t sbase = smem_u32_of(gsm);

    const int tid = threadIdx.x;
    const int warp = tid >> 5, lane = tid & 31;
    const int wm = warp & 3;
    const int wn = warp >> 2;

    const int bx = blockIdx.x;
    const int group = bx / (Mtiles * 8);
    const int rr = bx % (Mtiles * 8);
    const int bm = rr % Mtiles;
    const int bn = group * 8 + rr / Mtiles;

    const bf16* Aph = Ah + (size_t)bm * 128 * K;
    const bf16* Apl = Al + (size_t)bm * 128 * K;
    const bf16* Bph = Bh + (size_t)bn * 128 * K;
    const bf16* Bpl = Bl + (size_t)bn * 128 * K;

    const int lrow = lane & 15;
    const int lc_half = lane >> 4;

    float acc[2][8][4];
#pragma unroll
    for (int t = 0; t < 2; ++t)
#pragma unroll
        for (int n = 0; n < 8; ++n)
#pragma unroll
            for (int i = 0; i < 4; ++i) acc[t][n][i] = 0.f;

    const int nc = K / KC;   // 128

    auto issue = [&](int c, int st) {
        const int kc = c * KC;
        const uint32_t sb = sbase + st * STG_BYTES;
#pragma unroll
        for (int q = 0; q < 2; ++q) {
            const int i = tid + q * 256;
            const int row = i >> 2;
            const int chunk = i & 3;
            const int pchunk = chunk ^ ((row >> 1) & 3);
            const uint32_t doff = (uint32_t)(row * 64 + pchunk * 16);
            const size_t soff = (size_t)row * K + kc + chunk * 8;
            cp16(sb + 0 * STG_ARR + doff, Aph + soff);
            cp16(sb + 1 * STG_ARR + doff, Apl + soff);
            cp16(sb + 2 * STG_ARR + doff, Bph + soff);
            cp16(sb + 3 * STG_ARR + doff, Bpl + soff);
        }
    };

    issue(0, 0); cp_commit();
    issue(1, 1); cp_commit();

    for (int c = 0; c < nc; ++c) {
        if (c + 1 < nc) cp_wait<1>();
        else cp_wait<0>();
        __syncthreads();

        if (c + 2 < nc) { issue(c + 2, (c + 2) % NSTG); cp_commit(); }

        const int st = c % NSTG;
        const uint32_t uAh = sbase + st * STG_BYTES;
        const uint32_t uAl = uAh + STG_ARR;
        const uint32_t uBh = uAh + 2 * STG_ARR;
        const uint32_t uBl = uAh + 3 * STG_ARR;

#pragma unroll
        for (int ks = 0; ks < 2; ++ks) {
            const int lc = ks * 2 + lc_half;
            uint32_t ah[2][4], al[2][4];
#pragma unroll
            for (int t = 0; t < 2; ++t) {
                const int ar = wm * 32 + t * 16 + lrow;
                const uint32_t aoff = (uint32_t)(ar * 64 + (lc ^ ((ar >> 1) & 3)) * 16);
                ldm_x4(ah[t], uAh + aoff);
                ldm_x4(al[t], uAl + aoff);
            }
#pragma unroll
            for (int nt = 0; nt < 4; ++nt) {
                const int br = wn * 64 + nt * 16 + lrow;
                const uint32_t boff = (uint32_t)(br * 64 + (lc ^ ((br >> 1) & 3)) * 16);
                uint32_t bh[4], bl[4];
                ldm_x4(bh, uBh + boff);
                ldm_x4(bl, uBl + boff);
                // 4-wide accumulator rotation (reuse distance 4); per-acc order: hh, hl, lh
                mma_bf16(acc[0][2 * nt],     ah[0], bh[0], bh[2]);
                mma_bf16(acc[1][2 * nt],     ah[1], bh[0], bh[2]);
                mma_bf16(acc[0][2 * nt + 1], ah[0], bh[1], bh[3]);
                mma_bf16(acc[1][2 * nt + 1], ah[1], bh[1], bh[3]);
                mma_bf16(acc[0][2 * nt],     ah[0], bl[0], bl[2]);
                mma_bf16(acc[1][2 * nt],     ah[1], bl[0], bl[2]);
                mma_bf16(acc[0][2 * nt + 1], ah[0], bl[1], bl[3]);
                mma_bf16(acc[1][2 * nt + 1], ah[1], bl[1], bl[3]);
                mma_bf16(acc[0][2 * nt],     al[0], bh[0], bh[2]);
                mma_bf16(acc[1][2 * nt],     al[1], bh[0], bh[2]);
                mma_bf16(acc[0][2 * nt + 1], al[0], bh[1], bh[3]);
                mma_bf16(acc[1][2 * nt + 1], al[1], bh[1], bh[3]);
            }
        }
    }

    const int g = lane >> 2;
    const int tc2 = (lane & 3) << 1;
#pragma unroll
    for (int t = 0; t < 2; ++t) {
        const int row0 = bm * 128 + wm * 32 + t * 16 + g;
#pragma unroll
        for (int n = 0; n < 8; ++n) {
            const int col = bn * 128 + wn * 64 + n * 8 + tc2;
            *(float2*)(C + (size_t)row0 * N + col) = make_float2(acc[t][n][0], acc[t][n][1]);
            *(float2*)(C + (size_t)(row0 + 8) * N + col) = make_float2(acc[t][n][2], acc[t][n][3]);
        }
    }
}

// ---------------- elementwise split fp32 -> bf16 hi/lo ----------------------
__global__ __launch_bounds__(256) void split_f32(const float* __restrict__ in,
                                                 bf16* __restrict__ hi,
                                                 bf16* __restrict__ lo)
{
    const size_t i4 = (size_t)blockIdx.x * 256 + threadIdx.x;
    float4 v = *(const float4*)(in + i4 * 4);
    bf16 h[4], l[4];
    bfsplit(v.x, h[0], l[0]); bfsplit(v.y, h[1], l[1]);
    bfsplit(v.z, h[2], l[2]); bfsplit(v.w, h[3], l[3]);
    *(uint2*)(hi + i4 * 4) = *(uint2*)h;
    *(uint2*)(lo + i4 * 4) = *(uint2*)l;
}

// ---------------- transpose + split ------------------------------------------
__global__ __launch_bounds__(256) void transpose_split(const float* __restrict__ in,
                                                       bf16* __restrict__ outH,
                                                       bf16* __restrict__ outL,
                                                       int R, int Cc)
{
    __shared__ float t[32][33];
    const int c = blockIdx.x * 32 + threadIdx.x;
    const int r0 = blockIdx.y * 32 + threadIdx.y;
#pragma unroll
    for (int i = 0; i < 4; ++i)
        t[threadIdx.y + i * 8][threadIdx.x] = in[(size_t)(r0 + i * 8) * Cc + c];
    __syncthreads();
    const int rc = blockIdx.y * 32 + threadIdx.x;
    const int c0 = blockIdx.x * 32 + threadIdx.y;
#pragma unroll
    for (int i = 0; i < 4; ++i) {
        float v = t[threadIdx.x][threadIdx.y + i * 8];
        bf16 h, l;
        bfsplit(v, h, l);
        outH[(size_t)(c0 + i * 8) * R + rc] = h;
        outL[(size_t)(c0 + i * 8) * R + rc] = l;
    }
}

// ---------------- V transpose + split ----------------------------------------
__global__ __launch_bounds__(256) void vt_split(const float* __restrict__ Vg,
                                                bf16* __restrict__ VtH,
                                                bf16* __restrict__ VtL)
{
    __shared__ float t[32][33];
    const int bh = blockIdx.z;
    const float* in = Vg + (size_t)bh * SEQ * HDIM;
    const int s0 = blockIdx.x * 32;
    const int d0 = blockIdx.y * 32;
#pragma unroll
    for (int i = 0; i < 4; ++i)
        t[threadIdx.y + i * 8][threadIdx.x] = in[(size_t)(s0 + threadIdx.y + i * 8) * HDIM + d0 + threadIdx.x];
    __syncthreads();
    bf16* oh = VtH + (size_t)bh * HDIM * SEQ;
    bf16* ol = VtL + (size_t)bh * HDIM * SEQ;
#pragma unroll
    for (int i = 0; i < 4; ++i) {
        float v = t[threadIdx.x][threadIdx.y + i * 8];
        bf16 h, l;
        bfsplit(v, h, l);
        oh[(size_t)(d0 + threadIdx.y + i * 8) * SEQ + s0 + threadIdx.x] = h;
        ol[(size_t)(d0 + threadIdx.y + i * 8) * SEQ + s0 + threadIdx.x] = l;
    }
}

// ---------------- RoPE (NeoX) + split ----------------------------------------
__global__ __launch_bounds__(128) void rope_split2(const float* __restrict__ qkv,
                                                   const int* __restrict__ pos_ids,
                                                   bf16* __restrict__ QH, bf16* __restrict__ QL,
                                                   bf16* __restrict__ KH, bf16* __restrict__ KL,
                                                   float* __restrict__ Vh)
{
    const int token = blockIdx.x;
    const int b = token / SEQ;
    const int s = token % SEQ;
    __shared__ float cs[64], sn[64];
    const int tid = threadIdx.x;
    if (tid < 64) {
        double inv = exp(-9.210340371976184 * ((double)(2 * tid) / 128.0));
        double ang = (double)pos_ids[token] * inv;
        cs[tid] = (float)cos(ang);
        sn[tid] = (float)sin(ang);
    }
    __syncthreads();
    const float* base = qkv + (size_t)token * QKVN;

    for (int p = tid; p < NHEAD * 64; p += 128) {
        int h = p >> 6;
        int i = p & 63;
        float c = cs[i], sv = sn[i];
        size_t ob = ((size_t)(b * NHEAD + h) * SEQ + s) * HDIM;
        float q1 = base[h * HDIM + i];
        float q2 = base[h * HDIM + 64 + i];
        float r1 = q1 * c - q2 * sv;
        float r2 = q2 * c + q1 * sv;
        bf16 hh, ll;
        bfsplit(r1, hh, ll); QH[ob + i] = hh;      QL[ob + i] = ll;
        bfsplit(r2, hh, ll); QH[ob + 64 + i] = hh; QL[ob + 64 + i] = ll;
        float k1 = base[HID + h * HDIM + i];
        float k2 = base[HID + h * HDIM + 64 + i];
        r1 = k1 * c - k2 * sv;
        r2 = k2 * c + k1 * sv;
        bfsplit(r1, hh, ll); KH[ob + i] = hh;      KL[ob + i] = ll;
        bfsplit(r2, hh, ll); KH[ob + 64 + i] = hh; KL[ob + 64 + i] = ll;
    }
    for (int p = tid; p < HID; p += 128) {
        int h = p >> 7;
        int d = p & 127;
        Vh[((size_t)(b * NHEAD + h) * SEQ + s) * HDIM + d] = base[2 * HID + p];
    }
}

// ---------------- tensor-core flash attention (causal) ----------------------
#define QSTR 136
#define VSTR 72
#define oQH 0
#define oQL (oQH + 128 * QSTR * 2)
#define oKH (oQL + 128 * QSTR * 2)
#define oKL (oKH + 2 * 64 * QSTR * 2)
#define oVH (oKL + 2 * 64 * QSTR * 2)
#define oVL (oVH + 2 * 128 * VSTR * 2)
#define ATT_SMEM (oVL + 2 * 128 * VSTR * 2)

__global__ __launch_bounds__(256, 1) void flash_mma(const bf16* __restrict__ QHg,
                                                    const bf16* __restrict__ QLg,
                                                    const bf16* __restrict__ KHg,
                                                    const bf16* __restrict__ KLg,
                                                    const bf16* __restrict__ VtHg,
                                                    const bf16* __restrict__ VtLg,
                                                    bf16* __restrict__ attnH,
                                                    bf16* __restrict__ attnL)
{
    extern __shared__ char asm_buf[];
    const uint32_t sb = smem_u32_of(asm_buf);

    const int tid = threadIdx.x;
    const int warp = tid >> 5, lane = tid & 31;
    const int g = lane >> 2;
    const int lam = lane & 3;
    const int lrow = lane & 15;
    const int lkh = (lane >> 4) << 3;

    const int qt = (int)(gridDim.x - 1 - blockIdx.x);
    const int h = blockIdx.y;
    const int b = blockIdx.z;
    const int qb = qt * 128;
    const size_t hoff = (size_t)(b * NHEAD + h) * SEQ * HDIM;
    const size_t voff = (size_t)(b * NHEAD + h) * HDIM * SEQ;

#pragma unroll
    for (int j = 0; j < 8; ++j) {
        const int i = tid + j * 256;
        const int row = i >> 4;
        const int seg = (i & 15) << 3;
        const uint32_t doff = (uint32_t)(row * QSTR + seg) * 2;
        const size_t soff = hoff + (size_t)(qb + row) * HDIM + seg;
        cp16(sb + oQH + doff, QHg + soff);
        cp16(sb + oQL + doff, QLg + soff);
    }
    cp_commit();

    const int ktmax = 2 * qt + 1;

    auto issueKV = [&](int kt, int buf) {
        const int kb = kt * 64;
#pragma unroll
        for (int j = 0; j < 4; ++j) {
            const int i = tid + j * 256;
            const int krow = i >> 4;
            const int kseg = (i & 15) << 3;
            const uint32_t kdoff = (uint32_t)(krow * QSTR + kseg) * 2;
            const size_t ksoff = hoff + (size_t)(kb + krow) * HDIM + kseg;
            cp16(sb + oKH + buf * (64 * QSTR * 2) + kdoff, KHg + ksoff);
            cp16(sb + oKL + buf * (64 * QSTR * 2) + kdoff, KLg + ksoff);
            const int vrow = i >> 3;
            const int vseg = (i & 7) << 3;
            const uint32_t vdoff = (uint32_t)(vrow * VSTR + vseg) * 2;
            const size_t vsoff = voff + (size_t)vrow * SEQ + kb + vseg;
            cp16(sb + oVH + buf * (128 * VSTR * 2) + vdoff, VtHg + vsoff);
            cp16(sb + oVL + buf * (128 * VSTR * 2) + vdoff, VtLg + vsoff);
        }
    };

    issueKV(0, 0);
    cp_commit();

    float oacc[16][4];
#pragma unroll
    for (int n = 0; n < 16; ++n)
#pragma unroll
        for (int i = 0; i < 4; ++i) oacc[n][i] = 0.f;
    float m0 = -1e30f, m1 = -1e30f, l0 = 0.f, l1 = 0.f;
    const float scale2 = 0.1275174324f;   // (1/sqrt(128)) * log2(e)

    const int r0g = qb + warp * 16 + g;
    const int r1g = r0g + 8;

    for (int kt = 0; kt <= ktmax; ++kt) {
        const int kb = kt * 64;
        const int buf = kt & 1;

        cp_wait<0>();
        __syncthreads();
        if (kt < ktmax) { issueKV(kt + 1, buf ^ 1); cp_commit(); }

        const uint32_t uQH = sb + oQH, uQL = sb + oQL;
        const uint32_t uKH = sb + oKH + buf * (64 * QSTR * 2);
        const uint32_t uKL = sb + oKL + buf * (64 * QSTR * 2);
        const uint32_t uVH = sb + oVH + buf * (128 * VSTR * 2);
        const uint32_t uVL = sb + oVL + buf * (128 * VSTR * 2);

        float sacc[8][4];
#pragma unroll
        for (int n = 0; n < 8; ++n)
#pragma unroll
            for (int i = 0; i < 4; ++i) sacc[n][i] = 0.f;

#pragma unroll
        for (int ks = 0; ks < 8; ++ks) {
            uint32_t ah[4], al[4];
            const uint32_t aoff = (uint32_t)(((warp * 16 + lrow) * QSTR + ks * 16 + lkh) * 2);
            ldm_x4(ah, uQH + aoff);
            ldm_x4(al, uQL + aoff);
#pragma unroll
            for (int ntp = 0; ntp < 2; ++ntp) {
                const int nt0 = 2 * ntp, nt1 = 2 * ntp + 1;
                uint32_t bh0[4], bl0[4], bh1[4], bl1[4];
                const uint32_t b0off = (uint32_t)(((nt0 * 16 + lrow) * QSTR + ks * 16 + lkh) * 2);
                const uint32_t b1off = (uint32_t)(((nt1 * 16 + lrow) * QSTR + ks * 16 + lkh) * 2);
                ldm_x4(bh0, uKH + b0off);
                ldm_x4(bl0, uKL + b0off);
                ldm_x4(bh1, uKH + b1off);
                ldm_x4(bl1, uKL + b1off);
                // 4 accumulators rotating; per-acc order: hh, hl, lh
                mma_bf16(sacc[2 * nt0],     ah, bh0[0], bh0[2]);
                mma_bf16(sacc[2 * nt0 + 1], ah, bh0[1], bh0[3]);
                mma_bf16(sacc[2 * nt1],     ah, bh1[0], bh1[2]);
                mma_bf16(sacc[2 * nt1 + 1], ah, bh1[1], bh1[3]);
                mma_bf16(sacc[2 * nt0],     ah, bl0[0], bl0[2]);
                mma_bf16(sacc[2 * nt0 + 1], ah, bl0[1], bl0[3]);
                mma_bf16(sacc[2 * nt1],     ah, bl1[0], bl1[2]);
                mma_bf16(sacc[2 * nt1 + 1], ah, bl1[1], bl1[3]);
                mma_bf16(sacc[2 * nt0],     al, bh0[0], bh0[2]);
                mma_bf16(sacc[2 * nt0 + 1], al, bh0[1], bh0[3]);
                mma_bf16(sacc[2 * nt1],     al, bh1[0], bh1[2]);
                mma_bf16(sacc[2 * nt1 + 1], al, bh1[1], bh1[3]);
            }
        }

        const bool need_mask = (kt >= 2 * qt);
        float rm0 = -1e30f, rm1 = -1e30f;
#pragma unroll
        for (int j = 0; j < 8; ++j) {
            const int cg0 = kb + j * 8 + 2 * lam;
#pragma unroll
            for (int i = 0; i < 4; ++i) {
                float v = sacc[j][i] * scale2;
                if (need_mask) {
                    const int cg = cg0 + (i & 1);
                    const int rg = (i < 2) ? r0g : r1g;
                    if (cg > rg) v = -1e30f;
                }
                sacc[j][i] = v;
            }
            rm0 = fmaxf(rm0, fmaxf(sacc[j][0], sacc[j][1]));
            rm1 = fmaxf(rm1, fmaxf(sacc[j][2], sacc[j][3]));
        }
#pragma unroll
        for (int off = 1; off <= 2; off <<= 1) {
            rm0 = fmaxf(rm0, __shfl_xor_sync(0xffffffffu, rm0, off));
            rm1 = fmaxf(rm1, __shfl_xor_sync(0xffffffffu, rm1, off));
        }
        const float mn0 = fmaxf(m0, rm0);
        const float mn1 = fmaxf(m1, rm1);
        const float al0 = exp2f(m0 - mn0);
        const float al1 = exp2f(m1 - mn1);
        m0 = mn0; m1 = mn1;

        float rs0 = 0.f, rs1 = 0.f;
#pragma unroll
        for (int j = 0; j < 8; ++j) {
            sacc[j][0] = exp2f(sacc[j][0] - mn0);
            sacc[j][1] = exp2f(sacc[j][1] - mn0);
            sacc[j][2] = exp2f(sacc[j][2] - mn1);
            sacc[j][3] = exp2f(sacc[j][3] - mn1);
            rs0 += sacc[j][0] + sacc[j][1];
            rs1 += sacc[j][2] + sacc[j][3];
        }
#pragma unroll
        for (int off = 1; off <= 2; off <<= 1) {
            rs0 += __shfl_xor_sync(0xffffffffu, rs0, off);
            rs1 += __shfl_xor_sync(0xffffffffu, rs1, off);
        }
        l0 = l0 * al0 + rs0;
        l1 = l1 * al1 + rs1;

#pragma unroll
        for (int n = 0; n < 16; ++n) {
            oacc[n][0] *= al0; oacc[n][1] *= al0;
            oacc[n][2] *= al1; oacc[n][3] *= al1;
        }

        uint32_t pah[4][4], pal[4][4];
#pragma unroll
        for (int j2 = 0; j2 < 4; ++j2) {
            float p00 = sacc[2 * j2][0],     p01 = sacc[2 * j2][1];
            float p02 = sacc[2 * j2][2],     p03 = sacc[2 * j2][3];
            float p10 = sacc[2 * j2 + 1][0], p11 = sacc[2 * j2 + 1][1];
            float p12 = sacc[2 * j2 + 1][2], p13 = sacc[2 * j2 + 1][3];
            pah[j2][0] = pk2(p00, p01);
            pah[j2][1] = pk2(p02, p03);
            pah[j2][2] = pk2(p10, p11);
            pah[j2][3] = pk2(p12, p13);
            bf16 hh;
            hh = __float2bfloat16_rn(p00); p00 -= __bfloat162float(hh);
            hh = __float2bfloat16_rn(p01); p01 -= __bfloat162float(hh);
            hh = __float2bfloat16_rn(p02); p02 -= __bfloat162float(hh);
            hh = __float2bfloat16_rn(p03); p03 -= __bfloat162float(hh);
            hh = __float2bfloat16_rn(p10); p10 -= __bfloat162float(hh);
            hh = __float2bfloat16_rn(p11); p11 -= __bfloat162float(hh);
            hh = __float2bfloat16_rn(p12); p12 -= __bfloat162float(hh);
            hh = __float2bfloat16_rn(p13); p13 -= __bfloat162float(hh);
            pal[j2][0] = pk2(p00, p01);
            pal[j2][1] = pk2(p02, p03);
            pal[j2][2] = pk2(p10, p11);
            pal[j2][3] = pk2(p12, p13);
        }

        // O += P V: process nt in pairs -> 4 oacc tiles rotating
#pragma unroll
        for (int ntp = 0; ntp < 4; ++ntp) {
            const int nt0 = 2 * ntp, nt1 = 2 * ntp + 1;
#pragma unroll
            for (int j2 = 0; j2 < 4; ++j2) {
                uint32_t vh0[4], vl0[4], vh1[4], vl1[4];
                const uint32_t v0off = (uint32_t)(((nt0 * 16 + lrow) * VSTR + j2 * 16 + lkh) * 2);
                const uint32_t v1off = (uint32_t)(((nt1 * 16 + lrow) * VSTR + j2 * 16 + lkh) * 2);
                ldm_x4(vh0, uVH + v0off);
                ldm_x4(vl0, uVL + v0off);
                ldm_x4(vh1, uVH + v1off);
                ldm_x4(vl1, uVL + v1off);
                mma_bf16(oacc[2 * nt0],     pah[j2], vh0[0], vh0[2]);
                mma_bf16(oacc[2 * nt0 + 1], pah[j2], vh0[1], vh0[3]);
                mma_bf16(oacc[2 * nt1],     pah[j2], vh1[0], vh1[2]);
                mma_bf16(oacc[2 * nt1 + 1], pah[j2], vh1[1], vh1[3]);
                mma_bf16(oacc[2 * nt0],     pah[j2], vl0[0], vl0[2]);
                mma_bf16(oacc[2 * nt0 + 1], pah[j2], vl0[1], vl0[3]);
                mma_bf16(oacc[2 * nt1],     pah[j2], vl1[0], vl1[2]);
                mma_bf16(oacc[2 * nt1 + 1], pah[j2], vl1[1], vl1[3]);
                mma_bf16(oacc[2 * nt0],     pal[j2], vh0[0], vh0[2]);
                mma_bf16(oacc[2 * nt0 + 1], pal[j2], vh0[1], vh0[3]);
                mma_bf16(oacc[2 * nt1],     pal[j2], vh1[0], vh1[2]);
                mma_bf16(oacc[2 * nt1 + 1], pal[j2], vh1[1], vh1[3]);
            }
        }
    }

    const float i0 = 1.0f / l0;
    const float i1 = 1.0f / l1;
    const size_t row0 = ((size_t)b * SEQ + r0g) * HID + h * HDIM;
    const size_t row1 = ((size_t)b * SEQ + r1g) * HID + h * HDIM;
#pragma unroll
    for (int n = 0; n < 16; ++n) {
        const int col = n * 8 + 2 * lam;
        float x0 = oacc[n][0] * i0, x1 = oacc[n][1] * i0;
        float y0 = oacc[n][2] * i1, y1 = oacc[n][3] * i1;
        *(uint32_t*)(attnH + row0 + col) = pk2(x0, x1);
        *(uint32_t*)(attnH + row1 + col) = pk2(y0, y1);
        bf16 hb;
        hb = __float2bfloat16_rn(x0); x0 -= __bfloat162float(hb);
        hb = __float2bfloat16_rn(x1); x1 -= __bfloat162float(hb);
        hb = __float2bfloat16_rn(y0); y0 -= __bfloat162float(hb);
        hb = __float2bfloat16_rn(y1); y1 -= __bfloat162float(hb);
        *(uint32_t*)(attnL + row0 + col) = pk2(x0, x1);
        *(uint32_t*)(attnL + row1 + col) = pk2(y0, y1);
    }
}

// ---------------------------------------------------------------------------
extern "C" void kernel_launch(void* const* d_in, const int* in_sizes, int n_in,
                              void* d_out, int out_size)
{
    (void)in_sizes; (void)n_in; (void)out_size;
    const float* hidden = (const float*)d_in[0];
    const float* w_qkv  = (const float*)d_in[1];
    const float* w_o    = (const float*)d_in[2];
    const int*   pos    = (const int*)d_in[3];
    float* out = (float*)d_out;

    float *qkv, *v;
    bf16 *hidH, *hidL, *wqkvtH, *wqkvtL, *wotH, *wotL;
    bf16 *QH, *QL, *KH, *KL, *VtH, *VtL, *attnH, *attnL;
    cudaGetSymbolAddress((void**)&qkv,    g_qkv);
    cudaGetSymbolAddress((void**)&v,      g_v);
    cudaGetSymbolAddress((void**)&hidH,   g_hidH);
    cudaGetSymbolAddress((void**)&hidL,   g_hidL);
    cudaGetSymbolAddress((void**)&wqkvtH, g_wqkvtH);
    cudaGetSymbolAddress((void**)&wqkvtL, g_wqkvtL);
    cudaGetSymbolAddress((void**)&wotH,   g_wotH);
    cudaGetSymbolAddress((void**)&wotL,   g_wotL);
    cudaGetSymbolAddress((void**)&QH,     g_QH);
    cudaGetSymbolAddress((void**)&QL,     g_QL);
    cudaGetSymbolAddress((void**)&KH,     g_KH);
    cudaGetSymbolAddress((void**)&KL,     g_KL);
    cudaGetSymbolAddress((void**)&VtH,    g_VtH);
    cudaGetSymbolAddress((void**)&VtL,    g_VtL);
    cudaGetSymbolAddress((void**)&attnH,  g_attnH);
    cudaGetSymbolAddress((void**)&attnL,  g_attnL);

    // 0) pre-split + transpose inputs
    split_f32<<<(TOKENS * HID) / 1024, 256>>>(hidden, hidH, hidL);
    transpose_split<<<dim3(QKVN / 32, HID / 32), dim3(32, 8)>>>(w_qkv, wqkvtH, wqkvtL, HID, QKVN);
    transpose_split<<<dim3(HID / 32, HID / 32), dim3(32, 8)>>>(w_o, wotH, wotL, HID, HID);

    const int gsmem = NSTG * STG_BYTES;
    cudaFuncSetAttribute(gemm_bf3, cudaFuncAttributeMaxDynamicSharedMemorySize, gsmem);

    // 1) QKV projection
    gemm_bf3<<<(TOKENS / 128) * (QKVN / 128), 256, gsmem>>>(
        hidH, hidL, wqkvtH, wqkvtL, qkv, TOKENS, QKVN, HID, TOKENS / 128);

    // 2) RoPE + split to head-major bf16; V fp32 head-major
    rope_split2<<<TOKENS, 128>>>(qkv, pos, QH, QL, KH, KL, v);

    // 3) V transpose + split per head
    vt_split<<<dim3(SEQ / 32, HDIM / 32, HEADS), dim3(32, 8)>>>(v, VtH, VtL);

    // 4) tensor-core causal flash attention -> pre-split attn
    cudaFuncSetAttribute(flash_mma, cudaFuncAttributeMaxDynamicSharedMemorySize, ATT_SMEM);
    flash_mma<<<dim3(SEQ / 128, NHEAD, BATCH), 256, ATT_SMEM>>>(
        QH, QL, KH, KL, VtH, VtL, attnH, attnL);

    // 5) output projection
    gemm_bf3<<<(TOKENS / 128) * (HID / 128), 256, gsmem>>>(
        attnH, attnL, wotH, wotL, out, TOKENS, HID, HID, TOKENS / 128);
}

// round 8
// speedup vs baseline: 4.8029x; 1.3534x over previous
#include <cuda_runtime.h>
#include <cuda_bf16.h>
#include <cuda_fp16.h>
#include <math.h>
#include <stdint.h>

#define BATCH 2
#define SEQ   2048
#define HID   4096
#define NHEAD 32
#define HDIM  128
#define TOKENS (BATCH * SEQ)     // 4096
#define QKVN  (3 * HID)          // 12288
#define HEADS (BATCH * NHEAD)    // 64

typedef __nv_bfloat16 bf16;
typedef __half f16;

// ---------------- scratch (device globals; no allocation allowed) ----------
__device__ float g_qkv[(size_t)TOKENS * QKVN];
__device__ float g_v[(size_t)HEADS * SEQ * HDIM];
__device__ f16   g_hidH[(size_t)TOKENS * HID];
__device__ f16   g_hidL[(size_t)TOKENS * HID];
__device__ f16   g_wqkvt[(size_t)QKVN * HID];
__device__ f16   g_wot[(size_t)HID * HID];
__device__ bf16  g_QH[(size_t)HEADS * SEQ * HDIM];
__device__ bf16  g_QL[(size_t)HEADS * SEQ * HDIM];
__device__ bf16  g_KH[(size_t)HEADS * SEQ * HDIM];
__device__ bf16  g_KL[(size_t)HEADS * SEQ * HDIM];
__device__ bf16  g_VtH[(size_t)HEADS * HDIM * SEQ];
__device__ bf16  g_VtL[(size_t)HEADS * HDIM * SEQ];
__device__ f16   g_attnH[(size_t)TOKENS * HID];
__device__ f16   g_attnL[(size_t)TOKENS * HID];

// ======================= helpers ==================================
__device__ __forceinline__ uint32_t smem_u32_of(const void* p) {
    uint32_t a;
    asm("{ .reg .u64 t; cvta.to.shared.u64 t, %1; cvt.u32.u64 %0, t; }" : "=r"(a) : "l"(p));
    return a;
}
__device__ __forceinline__ void ldm_x4(uint32_t* r, uint32_t addr) {
    asm volatile("ldmatrix.sync.aligned.m8n8.x4.shared.b16 {%0,%1,%2,%3}, [%4];"
                 : "=r"(r[0]), "=r"(r[1]), "=r"(r[2]), "=r"(r[3]) : "r"(addr));
}
__device__ __forceinline__ void mma_bf16(float* d, const uint32_t* a, uint32_t b0, uint32_t b1) {
    asm volatile(
        "mma.sync.aligned.m16n8k16.row.col.f32.bf16.bf16.f32 "
        "{%0,%1,%2,%3},{%4,%5,%6,%7},{%8,%9},{%0,%1,%2,%3};"
        : "+f"(d[0]), "+f"(d[1]), "+f"(d[2]), "+f"(d[3])
        : "r"(a[0]), "r"(a[1]), "r"(a[2]), "r"(a[3]), "r"(b0), "r"(b1));
}
__device__ __forceinline__ void mma_f16(float* d, const uint32_t* a, uint32_t b0, uint32_t b1) {
    asm volatile(
        "mma.sync.aligned.m16n8k16.row.col.f32.f16.f16.f32 "
        "{%0,%1,%2,%3},{%4,%5,%6,%7},{%8,%9},{%0,%1,%2,%3};"
        : "+f"(d[0]), "+f"(d[1]), "+f"(d[2]), "+f"(d[3])
        : "r"(a[0]), "r"(a[1]), "r"(a[2]), "r"(a[3]), "r"(b0), "r"(b1));
}
__device__ __forceinline__ void bfsplit(float x, bf16& hi, bf16& lo) {
    hi = __float2bfloat16_rn(x);
    lo = __float2bfloat16_rn(x - __bfloat162float(hi));
}
__device__ __forceinline__ void hsplit(float x, f16& hi, f16& lo) {
    hi = __float2half_rn(x);
    lo = __float2half_rn(x - __half2float(hi));
}
__device__ __forceinline__ uint32_t pk2(float a, float b) {
    __nv_bfloat162 t = __floats2bfloat162_rn(a, b);
    return *(uint32_t*)&t;
}
__device__ __forceinline__ uint32_t pk2h(float a, float b) {
    __half2 t = __floats2half2_rn(a, b);
    return *(uint32_t*)&t;
}
__device__ __forceinline__ void cp16(uint32_t smem, const void* g) {
    asm volatile("cp.async.cg.shared.global [%0], [%1], 16;" :: "r"(smem), "l"(g) : "memory");
}
__device__ __forceinline__ void cp_commit() {
    asm volatile("cp.async.commit_group;" ::: "memory");
}
template <int N> __device__ __forceinline__ void cp_wait() {
    asm volatile("cp.async.wait_group %0;" :: "n"(N) : "memory");
}

// ============ fp16 2-term compensated tensor-core GEMM ======================
// C[M,N] = (Ah+Al)[M,K] @ Bh[N,K]^T  (A exact in 2 fp16 limbs; B single fp16)
#define KC  32
#define STG_ARR (128 * KC * 2)       // 8192 B per array per stage
#define STG_BYTES (3 * STG_ARR)      // 24576 B (Ah, Al, Bh)
#define NSTG 3                        // 73728 B -> 2 CTAs/SM

__global__ __launch_bounds__(256, 2) void gemm_f16x2(const f16* __restrict__ Ah,
                                                     const f16* __restrict__ Al,
                                                     const f16* __restrict__ Bh,
                                                     float* __restrict__ C,
                                                     int M, int N, int K, int Mtiles)
{
    extern __shared__ char gsm[];
    const uint32_t sbase = smem_u32_of(gsm);

    const int tid = threadIdx.x;
    const int warp = tid >> 5, lane = tid & 31;
    const int wm = warp & 3;
    const int wn = warp >> 2;

    const int bx = blockIdx.x;
    const int group = bx / (Mtiles * 8);
    const int rr = bx % (Mtiles * 8);
    const int bm = rr % Mtiles;
    const int bn = group * 8 + rr / Mtiles;

    const f16* Aph = Ah + (size_t)bm * 128 * K;
    const f16* Apl = Al + (size_t)bm * 128 * K;
    const f16* Bph = Bh + (size_t)bn * 128 * K;

    const int lrow = lane & 15;
    const int lc_half = lane >> 4;

    float acc[2][8][4];
#pragma unroll
    for (int t = 0; t < 2; ++t)
#pragma unroll
        for (int n = 0; n < 8; ++n)
#pragma unroll
            for (int i = 0; i < 4; ++i) acc[t][n][i] = 0.f;

    const int nc = K / KC;   // 128

    auto issue = [&](int c, int st) {
        const int kc = c * KC;
        const uint32_t sb = sbase + st * STG_BYTES;
#pragma unroll
        for (int q = 0; q < 2; ++q) {
            const int i = tid + q * 256;
            const int row = i >> 2;
            const int chunk = i & 3;
            const int pchunk = chunk ^ ((row >> 1) & 3);
            const uint32_t doff = (uint32_t)(row * 64 + pchunk * 16);
            const size_t soff = (size_t)row * K + kc + chunk * 8;
            cp16(sb + 0 * STG_ARR + doff, Aph + soff);
            cp16(sb + 1 * STG_ARR + doff, Apl + soff);
            cp16(sb + 2 * STG_ARR + doff, Bph + soff);
        }
    };

    issue(0, 0); cp_commit();
    issue(1, 1); cp_commit();

    for (int c = 0; c < nc; ++c) {
        if (c + 1 < nc) cp_wait<1>();
        else cp_wait<0>();
        __syncthreads();

        if (c + 2 < nc) { issue(c + 2, (c + 2) % NSTG); cp_commit(); }

        const int st = c % NSTG;
        const uint32_t uAh = sbase + st * STG_BYTES;
        const uint32_t uAl = uAh + STG_ARR;
        const uint32_t uBh = uAh + 2 * STG_ARR;

#pragma unroll
        for (int ks = 0; ks < 2; ++ks) {
            const int lc = ks * 2 + lc_half;
            uint32_t ah[2][4], al[2][4];
#pragma unroll
            for (int t = 0; t < 2; ++t) {
                const int ar = wm * 32 + t * 16 + lrow;
                const uint32_t aoff = (uint32_t)(ar * 64 + (lc ^ ((ar >> 1) & 3)) * 16);
                ldm_x4(ah[t], uAh + aoff);
                ldm_x4(al[t], uAl + aoff);
            }
#pragma unroll
            for (int nt = 0; nt < 4; ++nt) {
                const int br = wn * 64 + nt * 16 + lrow;
                const uint32_t boff = (uint32_t)(br * 64 + (lc ^ ((br >> 1) & 3)) * 16);
                uint32_t bh[4];
                ldm_x4(bh, uBh + boff);
                // per-acc order: Ah then Al; 4-wide rotation
                mma_f16(acc[0][2 * nt],     ah[0], bh[0], bh[2]);
                mma_f16(acc[1][2 * nt],     ah[1], bh[0], bh[2]);
                mma_f16(acc[0][2 * nt + 1], ah[0], bh[1], bh[3]);
                mma_f16(acc[1][2 * nt + 1], ah[1], bh[1], bh[3]);
                mma_f16(acc[0][2 * nt],     al[0], bh[0], bh[2]);
                mma_f16(acc[1][2 * nt],     al[1], bh[0], bh[2]);
                mma_f16(acc[0][2 * nt + 1], al[0], bh[1], bh[3]);
                mma_f16(acc[1][2 * nt + 1], al[1], bh[1], bh[3]);
            }
        }
    }

    const int g = lane >> 2;
    const int tc2 = (lane & 3) << 1;
#pragma unroll
    for (int t = 0; t < 2; ++t) {
        const int row0 = bm * 128 + wm * 32 + t * 16 + g;
#pragma unroll
        for (int n = 0; n < 8; ++n) {
            const int col = bn * 128 + wn * 64 + n * 8 + tc2;
            *(float2*)(C + (size_t)row0 * N + col) = make_float2(acc[t][n][0], acc[t][n][1]);
            *(float2*)(C + (size_t)(row0 + 8) * N + col) = make_float2(acc[t][n][2], acc[t][n][3]);
        }
    }
}

// ---------------- elementwise split fp32 -> fp16 hi/lo ----------------------
__global__ __launch_bounds__(256) void split_f32h(const float* __restrict__ in,
                                                  f16* __restrict__ hi,
                                                  f16* __restrict__ lo)
{
    const size_t i4 = (size_t)blockIdx.x * 256 + threadIdx.x;
    float4 v = *(const float4*)(in + i4 * 4);
    f16 h[4], l[4];
    hsplit(v.x, h[0], l[0]); hsplit(v.y, h[1], l[1]);
    hsplit(v.z, h[2], l[2]); hsplit(v.w, h[3], l[3]);
    *(uint2*)(hi + i4 * 4) = *(uint2*)h;
    *(uint2*)(lo + i4 * 4) = *(uint2*)l;
}

// ---------------- transpose + round to single fp16 --------------------------
__global__ __launch_bounds__(256) void transpose_f16(const float* __restrict__ in,
                                                     f16* __restrict__ out,
                                                     int R, int Cc)
{
    __shared__ float t[32][33];
    const int c = blockIdx.x * 32 + threadIdx.x;
    const int r0 = blockIdx.y * 32 + threadIdx.y;
#pragma unroll
    for (int i = 0; i < 4; ++i)
        t[threadIdx.y + i * 8][threadIdx.x] = in[(size_t)(r0 + i * 8) * Cc + c];
    __syncthreads();
    const int rc = blockIdx.y * 32 + threadIdx.x;
    const int c0 = blockIdx.x * 32 + threadIdx.y;
#pragma unroll
    for (int i = 0; i < 4; ++i)
        out[(size_t)(c0 + i * 8) * R + rc] = __float2half_rn(t[threadIdx.x][threadIdx.y + i * 8]);
}

// ---------------- V transpose + split (bf16, attention path) ----------------
__global__ __launch_bounds__(256) void vt_split(const float* __restrict__ Vg,
                                                bf16* __restrict__ VtH,
                                                bf16* __restrict__ VtL)
{
    __shared__ float t[32][33];
    const int bh = blockIdx.z;
    const float* in = Vg + (size_t)bh * SEQ * HDIM;
    const int s0 = blockIdx.x * 32;
    const int d0 = blockIdx.y * 32;
#pragma unroll
    for (int i = 0; i < 4; ++i)
        t[threadIdx.y + i * 8][threadIdx.x] = in[(size_t)(s0 + threadIdx.y + i * 8) * HDIM + d0 + threadIdx.x];
    __syncthreads();
    bf16* oh = VtH + (size_t)bh * HDIM * SEQ;
    bf16* ol = VtL + (size_t)bh * HDIM * SEQ;
#pragma unroll
    for (int i = 0; i < 4; ++i) {
        float v = t[threadIdx.x][threadIdx.y + i * 8];
        bf16 h, l;
        bfsplit(v, h, l);
        oh[(size_t)(d0 + threadIdx.y + i * 8) * SEQ + s0 + threadIdx.x] = h;
        ol[(size_t)(d0 + threadIdx.y + i * 8) * SEQ + s0 + threadIdx.x] = l;
    }
}

// ---------------- RoPE (NeoX) + split (bf16, attention path) ----------------
__global__ __launch_bounds__(128) void rope_split2(const float* __restrict__ qkv,
                                                   const int* __restrict__ pos_ids,
                                                   bf16* __restrict__ QH, bf16* __restrict__ QL,
                                                   bf16* __restrict__ KH, bf16* __restrict__ KL,
                                                   float* __restrict__ Vh)
{
    const int token = blockIdx.x;
    const int b = token / SEQ;
    const int s = token % SEQ;
    __shared__ float cs[64], sn[64];
    const int tid = threadIdx.x;
    if (tid < 64) {
        double inv = exp(-9.210340371976184 * ((double)(2 * tid) / 128.0));
        double ang = (double)pos_ids[token] * inv;
        cs[tid] = (float)cos(ang);
        sn[tid] = (float)sin(ang);
    }
    __syncthreads();
    const float* base = qkv + (size_t)token * QKVN;

    for (int p = tid; p < NHEAD * 64; p += 128) {
        int h = p >> 6;
        int i = p & 63;
        float c = cs[i], sv = sn[i];
        size_t ob = ((size_t)(b * NHEAD + h) * SEQ + s) * HDIM;
        float q1 = base[h * HDIM + i];
        float q2 = base[h * HDIM + 64 + i];
        float r1 = q1 * c - q2 * sv;
        float r2 = q2 * c + q1 * sv;
        bf16 hh, ll;
        bfsplit(r1, hh, ll); QH[ob + i] = hh;      QL[ob + i] = ll;
        bfsplit(r2, hh, ll); QH[ob + 64 + i] = hh; QL[ob + 64 + i] = ll;
        float k1 = base[HID + h * HDIM + i];
        float k2 = base[HID + h * HDIM + 64 + i];
        r1 = k1 * c - k2 * sv;
        r2 = k2 * c + k1 * sv;
        bfsplit(r1, hh, ll); KH[ob + i] = hh;      KL[ob + i] = ll;
        bfsplit(r2, hh, ll); KH[ob + 64 + i] = hh; KL[ob + 64 + i] = ll;
    }
    for (int p = tid; p < HID; p += 128) {
        int h = p >> 7;
        int d = p & 127;
        Vh[((size_t)(b * NHEAD + h) * SEQ + s) * HDIM + d] = base[2 * HID + p];
    }
}

// ---------------- tensor-core flash attention (causal, bf16x3) --------------
#define QSTR 136
#define VSTR 72
#define oQH 0
#define oQL (oQH + 128 * QSTR * 2)
#define oKH (oQL + 128 * QSTR * 2)
#define oKL (oKH + 2 * 64 * QSTR * 2)
#define oVH (oKL + 2 * 64 * QSTR * 2)
#define oVL (oVH + 2 * 128 * VSTR * 2)
#define ATT_SMEM (oVL + 2 * 128 * VSTR * 2)

__global__ __launch_bounds__(256, 1) void flash_mma(const bf16* __restrict__ QHg,
                                                    const bf16* __restrict__ QLg,
                                                    const bf16* __restrict__ KHg,
                                                    const bf16* __restrict__ KLg,
                                                    const bf16* __restrict__ VtHg,
                                                    const bf16* __restrict__ VtLg,
                                                    f16* __restrict__ attnH,
                                                    f16* __restrict__ attnL)
{
    extern __shared__ char asm_buf[];
    const uint32_t sb = smem_u32_of(asm_buf);

    const int tid = threadIdx.x;
    const int warp = tid >> 5, lane = tid & 31;
    const int g = lane >> 2;
    const int lam = lane & 3;
    const int lrow = lane & 15;
    const int lkh = (lane >> 4) << 3;

    const int qt = (int)(gridDim.x - 1 - blockIdx.x);
    const int h = blockIdx.y;
    const int b = blockIdx.z;
    const int qb = qt * 128;
    const size_t hoff = (size_t)(b * NHEAD + h) * SEQ * HDIM;
    const size_t voff = (size_t)(b * NHEAD + h) * HDIM * SEQ;

#pragma unroll
    for (int j = 0; j < 8; ++j) {
        const int i = tid + j * 256;
        const int row = i >> 4;
        const int seg = (i & 15) << 3;
        const uint32_t doff = (uint32_t)(row * QSTR + seg) * 2;
        const size_t soff = hoff + (size_t)(qb + row) * HDIM + seg;
        cp16(sb + oQH + doff, QHg + soff);
        cp16(sb + oQL + doff, QLg + soff);
    }
    cp_commit();

    const int ktmax = 2 * qt + 1;

    auto issueKV = [&](int kt, int buf) {
        const int kb = kt * 64;
#pragma unroll
        for (int j = 0; j < 4; ++j) {
            const int i = tid + j * 256;
            const int krow = i >> 4;
            const int kseg = (i & 15) << 3;
            const uint32_t kdoff = (uint32_t)(krow * QSTR + kseg) * 2;
            const size_t ksoff = hoff + (size_t)(kb + krow) * HDIM + kseg;
            cp16(sb + oKH + buf * (64 * QSTR * 2) + kdoff, KHg + ksoff);
            cp16(sb + oKL + buf * (64 * QSTR * 2) + kdoff, KLg + ksoff);
            const int vrow = i >> 3;
            const int vseg = (i & 7) << 3;
            const uint32_t vdoff = (uint32_t)(vrow * VSTR + vseg) * 2;
            const size_t vsoff = voff + (size_t)vrow * SEQ + kb + vseg;
            cp16(sb + oVH + buf * (128 * VSTR * 2) + vdoff, VtHg + vsoff);
            cp16(sb + oVL + buf * (128 * VSTR * 2) + vdoff, VtLg + vsoff);
        }
    };

    issueKV(0, 0);
    cp_commit();

    float oacc[16][4];
#pragma unroll
    for (int n = 0; n < 16; ++n)
#pragma unroll
        for (int i = 0; i < 4; ++i) oacc[n][i] = 0.f;
    float m0 = -1e30f, m1 = -1e30f, l0 = 0.f, l1 = 0.f;
    const float scale2 = 0.1275174324f;   // (1/sqrt(128)) * log2(e)

    const int r0g = qb + warp * 16 + g;
    const int r1g = r0g + 8;

    for (int kt = 0; kt <= ktmax; ++kt) {
        const int kb = kt * 64;
        const int buf = kt & 1;

        cp_wait<0>();
        __syncthreads();
        if (kt < ktmax) { issueKV(kt + 1, buf ^ 1); cp_commit(); }

        const uint32_t uQH = sb + oQH, uQL = sb + oQL;
        const uint32_t uKH = sb + oKH + buf * (64 * QSTR * 2);
        const uint32_t uKL = sb + oKL + buf * (64 * QSTR * 2);
        const uint32_t uVH = sb + oVH + buf * (128 * VSTR * 2);
        const uint32_t uVL = sb + oVL + buf * (128 * VSTR * 2);

        float sacc[8][4];
#pragma unroll
        for (int n = 0; n < 8; ++n)
#pragma unroll
            for (int i = 0; i < 4; ++i) sacc[n][i] = 0.f;

#pragma unroll
        for (int ks = 0; ks < 8; ++ks) {
            uint32_t ah[4], al[4];
            const uint32_t aoff = (uint32_t)(((warp * 16 + lrow) * QSTR + ks * 16 + lkh) * 2);
            ldm_x4(ah, uQH + aoff);
            ldm_x4(al, uQL + aoff);
#pragma unroll
            for (int ntp = 0; ntp < 2; ++ntp) {
                const int nt0 = 2 * ntp, nt1 = 2 * ntp + 1;
                uint32_t bh0[4], bl0[4], bh1[4], bl1[4];
                const uint32_t b0off = (uint32_t)(((nt0 * 16 + lrow) * QSTR + ks * 16 + lkh) * 2);
                const uint32_t b1off = (uint32_t)(((nt1 * 16 + lrow) * QSTR + ks * 16 + lkh) * 2);
                ldm_x4(bh0, uKH + b0off);
                ldm_x4(bl0, uKL + b0off);
                ldm_x4(bh1, uKH + b1off);
                ldm_x4(bl1, uKL + b1off);
                mma_bf16(sacc[2 * nt0],     ah, bh0[0], bh0[2]);
                mma_bf16(sacc[2 * nt0 + 1], ah, bh0[1], bh0[3]);
                mma_bf16(sacc[2 * nt1],     ah, bh1[0], bh1[2]);
                mma_bf16(sacc[2 * nt1 + 1], ah, bh1[1], bh1[3]);
                mma_bf16(sacc[2 * nt0],     ah, bl0[0], bl0[2]);
                mma_bf16(sacc[2 * nt0 + 1], ah, bl0[1], bl0[3]);
                mma_bf16(sacc[2 * nt1],     ah, bl1[0], bl1[2]);
                mma_bf16(sacc[2 * nt1 + 1], ah, bl1[1], bl1[3]);
                mma_bf16(sacc[2 * nt0],     al, bh0[0], bh0[2]);
                mma_bf16(sacc[2 * nt0 + 1], al, bh0[1], bh0[3]);
                mma_bf16(sacc[2 * nt1],     al, bh1[0], bh1[2]);
                mma_bf16(sacc[2 * nt1 + 1], al, bh1[1], bh1[3]);
            }
        }

        const bool need_mask = (kt >= 2 * qt);
        float rm0 = -1e30f, rm1 = -1e30f;
#pragma unroll
        for (int j = 0; j < 8; ++j) {
            const int cg0 = kb + j * 8 + 2 * lam;
#pragma unroll
            for (int i = 0; i < 4; ++i) {
                float v = sacc[j][i] * scale2;
                if (need_mask) {
                    const int cg = cg0 + (i & 1);
                    const int rg = (i < 2) ? r0g : r1g;
                    if (cg > rg) v = -1e30f;
                }
                sacc[j][i] = v;
            }
            rm0 = fmaxf(rm0, fmaxf(sacc[j][0], sacc[j][1]));
            rm1 = fmaxf(rm1, fmaxf(sacc[j][2], sacc[j][3]));
        }
#pragma unroll
        for (int off = 1; off <= 2; off <<= 1) {
            rm0 = fmaxf(rm0, __shfl_xor_sync(0xffffffffu, rm0, off));
            rm1 = fmaxf(rm1, __shfl_xor_sync(0xffffffffu, rm1, off));
        }
        const float mn0 = fmaxf(m0, rm0);
        const float mn1 = fmaxf(m1, rm1);
        const float al0 = exp2f(m0 - mn0);
        const float al1 = exp2f(m1 - mn1);
        m0 = mn0; m1 = mn1;

        float rs0 = 0.f, rs1 = 0.f;
#pragma unroll
        for (int j = 0; j < 8; ++j) {
            sacc[j][0] = exp2f(sacc[j][0] - mn0);
            sacc[j][1] = exp2f(sacc[j][1] - mn0);
            sacc[j][2] = exp2f(sacc[j][2] - mn1);
            sacc[j][3] = exp2f(sacc[j][3] - mn1);
            rs0 += sacc[j][0] + sacc[j][1];
            rs1 += sacc[j][2] + sacc[j][3];
        }
#pragma unroll
        for (int off = 1; off <= 2; off <<= 1) {
            rs0 += __shfl_xor_sync(0xffffffffu, rs0, off);
            rs1 += __shfl_xor_sync(0xffffffffu, rs1, off);
        }
        l0 = l0 * al0 + rs0;
        l1 = l1 * al1 + rs1;

#pragma unroll
        for (int n = 0; n < 16; ++n) {
            oacc[n][0] *= al0; oacc[n][1] *= al0;
            oacc[n][2] *= al1; oacc[n][3] *= al1;
        }

        uint32_t pah[4][4], pal[4][4];
#pragma unroll
        for (int j2 = 0; j2 < 4; ++j2) {
            float p00 = sacc[2 * j2][0],     p01 = sacc[2 * j2][1];
            float p02 = sacc[2 * j2][2],     p03 = sacc[2 * j2][3];
            float p10 = sacc[2 * j2 + 1][0], p11 = sacc[2 * j2 + 1][1];
            float p12 = sacc[2 * j2 + 1][2], p13 = sacc[2 * j2 + 1][3];
            pah[j2][0] = pk2(p00, p01);
            pah[j2][1] = pk2(p02, p03);
            pah[j2][2] = pk2(p10, p11);
            pah[j2][3] = pk2(p12, p13);
            bf16 hh;
            hh = __float2bfloat16_rn(p00); p00 -= __bfloat162float(hh);
            hh = __float2bfloat16_rn(p01); p01 -= __bfloat162float(hh);
            hh = __float2bfloat16_rn(p02); p02 -= __bfloat162float(hh);
            hh = __float2bfloat16_rn(p03); p03 -= __bfloat162float(hh);
            hh = __float2bfloat16_rn(p10); p10 -= __bfloat162float(hh);
            hh = __float2bfloat16_rn(p11); p11 -= __bfloat162float(hh);
            hh = __float2bfloat16_rn(p12); p12 -= __bfloat162float(hh);
            hh = __float2bfloat16_rn(p13); p13 -= __bfloat162float(hh);
            pal[j2][0] = pk2(p00, p01);
            pal[j2][1] = pk2(p02, p03);
            pal[j2][2] = pk2(p10, p11);
            pal[j2][3] = pk2(p12, p13);
        }

#pragma unroll
        for (int ntp = 0; ntp < 4; ++ntp) {
            const int nt0 = 2 * ntp, nt1 = 2 * ntp + 1;
#pragma unroll
            for (int j2 = 0; j2 < 4; ++j2) {
                uint32_t vh0[4], vl0[4], vh1[4], vl1[4];
                const uint32_t v0off = (uint32_t)(((nt0 * 16 + lrow) * VSTR + j2 * 16 + lkh) * 2);
                const uint32_t v1off = (uint32_t)(((nt1 * 16 + lrow) * VSTR + j2 * 16 + lkh) * 2);
                ldm_x4(vh0, uVH + v0off);
                ldm_x4(vl0, uVL + v0off);
                ldm_x4(vh1, uVH + v1off);
                ldm_x4(vl1, uVL + v1off);
                mma_bf16(oacc[2 * nt0],     pah[j2], vh0[0], vh0[2]);
                mma_bf16(oacc[2 * nt0 + 1], pah[j2], vh0[1], vh0[3]);
                mma_bf16(oacc[2 * nt1],     pah[j2], vh1[0], vh1[2]);
                mma_bf16(oacc[2 * nt1 + 1], pah[j2], vh1[1], vh1[3]);
                mma_bf16(oacc[2 * nt0],     pah[j2], vl0[0], vl0[2]);
                mma_bf16(oacc[2 * nt0 + 1], pah[j2], vl0[1], vl0[3]);
                mma_bf16(oacc[2 * nt1],     pah[j2], vl1[0], vl1[2]);
                mma_bf16(oacc[2 * nt1 + 1], pah[j2], vl1[1], vl1[3]);
                mma_bf16(oacc[2 * nt0],     pal[j2], vh0[0], vh0[2]);
                mma_bf16(oacc[2 * nt0 + 1], pal[j2], vh0[1], vh0[3]);
                mma_bf16(oacc[2 * nt1],     pal[j2], vh1[0], vh1[2]);
                mma_bf16(oacc[2 * nt1 + 1], pal[j2], vh1[1], vh1[3]);
            }
        }
    }

    // epilogue: normalize, split to fp16 hi/lo for the O-proj
    const float i0 = 1.0f / l0;
    const float i1 = 1.0f / l1;
    const size_t row0 = ((size_t)b * SEQ + r0g) * HID + h * HDIM;
    const size_t row1 = ((size_t)b * SEQ + r1g) * HID + h * HDIM;
#pragma unroll
    for (int n = 0; n < 16; ++n) {
        const int col = n * 8 + 2 * lam;
        float x0 = oacc[n][0] * i0, x1 = oacc[n][1] * i0;
        float y0 = oacc[n][2] * i1, y1 = oacc[n][3] * i1;
        *(uint32_t*)(attnH + row0 + col) = pk2h(x0, x1);
        *(uint32_t*)(attnH + row1 + col) = pk2h(y0, y1);
        f16 hb;
        hb = __float2half_rn(x0); x0 -= __half2float(hb);
        hb = __float2half_rn(x1); x1 -= __half2float(hb);
        hb = __float2half_rn(y0); y0 -= __half2float(hb);
        hb = __float2half_rn(y1); y1 -= __half2float(hb);
        *(uint32_t*)(attnL + row0 + col) = pk2h(x0, x1);
        *(uint32_t*)(attnL + row1 + col) = pk2h(y0, y1);
    }
}

// ---------------------------------------------------------------------------
extern "C" void kernel_launch(void* const* d_in, const int* in_sizes, int n_in,
                              void* d_out, int out_size)
{
    (void)in_sizes; (void)n_in; (void)out_size;
    const float* hidden = (const float*)d_in[0];
    const float* w_qkv  = (const float*)d_in[1];
    const float* w_o    = (const float*)d_in[2];
    const int*   pos    = (const int*)d_in[3];
    float* out = (float*)d_out;

    float *qkv, *v;
    f16 *hidH, *hidL, *wqkvt, *wot, *attnH, *attnL;
    bf16 *QH, *QL, *KH, *KL, *VtH, *VtL;
    cudaGetSymbolAddress((void**)&qkv,   g_qkv);
    cudaGetSymbolAddress((void**)&v,     g_v);
    cudaGetSymbolAddress((void**)&hidH,  g_hidH);
    cudaGetSymbolAddress((void**)&hidL,  g_hidL);
    cudaGetSymbolAddress((void**)&wqkvt, g_wqkvt);
    cudaGetSymbolAddress((void**)&wot,   g_wot);
    cudaGetSymbolAddress((void**)&QH,    g_QH);
    cudaGetSymbolAddress((void**)&QL,    g_QL);
    cudaGetSymbolAddress((void**)&KH,    g_KH);
    cudaGetSymbolAddress((void**)&KL,    g_KL);
    cudaGetSymbolAddress((void**)&VtH,   g_VtH);
    cudaGetSymbolAddress((void**)&VtL,   g_VtL);
    cudaGetSymbolAddress((void**)&attnH, g_attnH);
    cudaGetSymbolAddress((void**)&attnL, g_attnL);

    // 0) pre-split activations (fp16 hi/lo) + transpose weights (single fp16)
    split_f32h<<<(TOKENS * HID) / 1024, 256>>>(hidden, hidH, hidL);
    transpose_f16<<<dim3(QKVN / 32, HID / 32), dim3(32, 8)>>>(w_qkv, wqkvt, HID, QKVN);
    transpose_f16<<<dim3(HID / 32, HID / 32), dim3(32, 8)>>>(w_o, wot, HID, HID);

    const int gsmem = NSTG * STG_BYTES;   // 73728 -> 2 CTAs/SM
    cudaFuncSetAttribute(gemm_f16x2, cudaFuncAttributeMaxDynamicSharedMemorySize, gsmem);

    // 1) QKV projection (fp16 2-term)
    gemm_f16x2<<<(TOKENS / 128) * (QKVN / 128), 256, gsmem>>>(
        hidH, hidL, wqkvt, qkv, TOKENS, QKVN, HID, TOKENS / 128);

    // 2) RoPE + split to head-major bf16; V fp32 head-major
    rope_split2<<<TOKENS, 128>>>(qkv, pos, QH, QL, KH, KL, v);

    // 3) V transpose + split per head
    vt_split<<<dim3(SEQ / 32, HDIM / 32, HEADS), dim3(32, 8)>>>(v, VtH, VtL);

    // 4) tensor-core causal flash attention -> fp16-split attn
    cudaFuncSetAttribute(flash_mma, cudaFuncAttributeMaxDynamicSharedMemorySize, ATT_SMEM);
    flash_mma<<<dim3(SEQ / 128, NHEAD, BATCH), 256, ATT_SMEM>>>(
        QH, QL, KH, KL, VtH, VtL, attnH, attnL);

    // 5) output projection (fp16 2-term)
    gemm_f16x2<<<(TOKENS / 128) * (HID / 128), 256, gsmem>>>(
        attnH, attnL, wot, out, TOKENS, HID, HID, TOKENS / 128);
}

// round 9
// speedup vs baseline: 5.1489x; 1.0721x over previous
#include <cuda_runtime.h>
#include <cuda_bf16.h>
#include <cuda_fp16.h>
#include <math.h>
#include <stdint.h>

#define BATCH 2
#define SEQ   2048
#define HID   4096
#define NHEAD 32
#define HDIM  128
#define TOKENS (BATCH * SEQ)     // 4096
#define QKVN  (3 * HID)          // 12288
#define HEADS (BATCH * NHEAD)    // 64

typedef __nv_bfloat16 bf16;
typedef __half f16;

// ---------------- scratch (device globals; no allocation allowed) ----------
__device__ float g_qkv[(size_t)TOKENS * QKVN];
__device__ float g_v[(size_t)HEADS * SEQ * HDIM];
__device__ f16   g_hidH[(size_t)TOKENS * HID];
__device__ f16   g_hidL[(size_t)TOKENS * HID];
__device__ f16   g_wqkvt[(size_t)QKVN * HID];
__device__ f16   g_wot[(size_t)HID * HID];
__device__ bf16  g_QH[(size_t)HEADS * SEQ * HDIM];
__device__ bf16  g_QL[(size_t)HEADS * SEQ * HDIM];
__device__ bf16  g_KH[(size_t)HEADS * SEQ * HDIM];
__device__ bf16  g_KL[(size_t)HEADS * SEQ * HDIM];
__device__ bf16  g_VtH[(size_t)HEADS * HDIM * SEQ];
__device__ bf16  g_VtL[(size_t)HEADS * HDIM * SEQ];
__device__ f16   g_attnH[(size_t)TOKENS * HID];
__device__ f16   g_attnL[(size_t)TOKENS * HID];

// ======================= helpers ==================================
__device__ __forceinline__ uint32_t smem_u32_of(const void* p) {
    uint32_t a;
    asm("{ .reg .u64 t; cvta.to.shared.u64 t, %1; cvt.u32.u64 %0, t; }" : "=r"(a) : "l"(p));
    return a;
}
__device__ __forceinline__ void ldm_x4(uint32_t* r, uint32_t addr) {
    asm volatile("ldmatrix.sync.aligned.m8n8.x4.shared.b16 {%0,%1,%2,%3}, [%4];"
                 : "=r"(r[0]), "=r"(r[1]), "=r"(r[2]), "=r"(r[3]) : "r"(addr));
}
__device__ __forceinline__ void mma_bf16(float* d, const uint32_t* a, uint32_t b0, uint32_t b1) {
    asm volatile(
        "mma.sync.aligned.m16n8k16.row.col.f32.bf16.bf16.f32 "
        "{%0,%1,%2,%3},{%4,%5,%6,%7},{%8,%9},{%0,%1,%2,%3};"
        : "+f"(d[0]), "+f"(d[1]), "+f"(d[2]), "+f"(d[3])
        : "r"(a[0]), "r"(a[1]), "r"(a[2]), "r"(a[3]), "r"(b0), "r"(b1));
}
__device__ __forceinline__ void mma_f16(float* d, const uint32_t* a, uint32_t b0, uint32_t b1) {
    asm volatile(
        "mma.sync.aligned.m16n8k16.row.col.f32.f16.f16.f32 "
        "{%0,%1,%2,%3},{%4,%5,%6,%7},{%8,%9},{%0,%1,%2,%3};"
        : "+f"(d[0]), "+f"(d[1]), "+f"(d[2]), "+f"(d[3])
        : "r"(a[0]), "r"(a[1]), "r"(a[2]), "r"(a[3]), "r"(b0), "r"(b1));
}
__device__ __forceinline__ void bfsplit(float x, bf16& hi, bf16& lo) {
    hi = __float2bfloat16_rn(x);
    lo = __float2bfloat16_rn(x - __bfloat162float(hi));
}
__device__ __forceinline__ void hsplit(float x, f16& hi, f16& lo) {
    hi = __float2half_rn(x);
    lo = __float2half_rn(x - __half2float(hi));
}
__device__ __forceinline__ uint32_t pk2(float a, float b) {
    __nv_bfloat162 t = __floats2bfloat162_rn(a, b);
    return *(uint32_t*)&t;
}
__device__ __forceinline__ uint32_t pk2h(float a, float b) {
    __half2 t = __floats2half2_rn(a, b);
    return *(uint32_t*)&t;
}
__device__ __forceinline__ void cp16(uint32_t smem, const void* g) {
    asm volatile("cp.async.cg.shared.global [%0], [%1], 16;" :: "r"(smem), "l"(g) : "memory");
}
__device__ __forceinline__ void cp_commit() {
    asm volatile("cp.async.commit_group;" ::: "memory");
}
template <int N> __device__ __forceinline__ void cp_wait() {
    asm volatile("cp.async.wait_group %0;" :: "n"(N) : "memory");
}

// ============ fp16 2-term compensated tensor-core GEMM ======================
// KC=64 (8 x 16B chunks/row), swizzle phys_chunk = chunk ^ (row & 7).
#define KC  64
#define STG_ARR (128 * KC * 2)       // 16384 B per array per stage
#define STG_BYTES (3 * STG_ARR)      // 49152 B (Ah, Al, Bh)
#define NSTG 2                        // 98304 B -> 2 CTAs/SM

__global__ __launch_bounds__(256, 2) void gemm_f16x2(const f16* __restrict__ Ah,
                                                     const f16* __restrict__ Al,
                                                     const f16* __restrict__ Bh,
                                                     float* __restrict__ C,
                                                     int M, int N, int K, int Mtiles)
{
    extern __shared__ char gsm[];
    const uint32_t sbase = smem_u32_of(gsm);

    const int tid = threadIdx.x;
    const int warp = tid >> 5, lane = tid & 31;
    const int wm = warp & 3;
    const int wn = warp >> 2;

    const int bx = blockIdx.x;
    const int group = bx / (Mtiles * 8);
    const int rr = bx % (Mtiles * 8);
    const int bm = rr % Mtiles;
    const int bn = group * 8 + rr / Mtiles;

    const f16* Aph = Ah + (size_t)bm * 128 * K;
    const f16* Apl = Al + (size_t)bm * 128 * K;
    const f16* Bph = Bh + (size_t)bn * 128 * K;

    const int lrow = lane & 15;
    const int lc_half = lane >> 4;

    float acc[2][8][4];
#pragma unroll
    for (int t = 0; t < 2; ++t)
#pragma unroll
        for (int n = 0; n < 8; ++n)
#pragma unroll
            for (int i = 0; i < 4; ++i) acc[t][n][i] = 0.f;

    const int nc = K / KC;   // 64

    auto issue = [&](int c, int st) {
        const int kc = c * KC;
        const uint32_t sb = sbase + st * STG_BYTES;
#pragma unroll
        for (int q = 0; q < 4; ++q) {
            const int i = tid + q * 256;      // 0..1023
            const int row = i >> 3;
            const int chunk = i & 7;
            const int pchunk = chunk ^ (row & 7);
            const uint32_t doff = (uint32_t)(row * 128 + pchunk * 16);
            const size_t soff = (size_t)row * K + kc + chunk * 8;
            cp16(sb + 0 * STG_ARR + doff, Aph + soff);
            cp16(sb + 1 * STG_ARR + doff, Apl + soff);
            cp16(sb + 2 * STG_ARR + doff, Bph + soff);
        }
    };

    issue(0, 0); cp_commit();

    for (int c = 0; c < nc; ++c) {
        cp_wait<0>();
        __syncthreads();                       // the ONLY barrier per chunk
        if (c + 1 < nc) { issue(c + 1, (c + 1) & 1); cp_commit(); }

        const int st = c & 1;
        const uint32_t uAh = sbase + st * STG_BYTES;
        const uint32_t uAl = uAh + STG_ARR;
        const uint32_t uBh = uAh + 2 * STG_ARR;

#pragma unroll
        for (int ks = 0; ks < 4; ++ks) {
            const int lc = ks * 2 + lc_half;   // 16B chunk index 0..7
            uint32_t ah[2][4], al[2][4];
#pragma unroll
            for (int t = 0; t < 2; ++t) {
                const int ar = wm * 32 + t * 16 + lrow;
                const uint32_t aoff = (uint32_t)(ar * 128 + (lc ^ (ar & 7)) * 16);
                ldm_x4(ah[t], uAh + aoff);
                ldm_x4(al[t], uAl + aoff);
            }
#pragma unroll
            for (int nt = 0; nt < 4; ++nt) {
                const int br = wn * 64 + nt * 16 + lrow;
                const uint32_t boff = (uint32_t)(br * 128 + (lc ^ (br & 7)) * 16);
                uint32_t bh[4];
                ldm_x4(bh, uBh + boff);
                // per-acc order: Ah then Al; 4-wide rotation
                mma_f16(acc[0][2 * nt],     ah[0], bh[0], bh[2]);
                mma_f16(acc[1][2 * nt],     ah[1], bh[0], bh[2]);
                mma_f16(acc[0][2 * nt + 1], ah[0], bh[1], bh[3]);
                mma_f16(acc[1][2 * nt + 1], ah[1], bh[1], bh[3]);
                mma_f16(acc[0][2 * nt],     al[0], bh[0], bh[2]);
                mma_f16(acc[1][2 * nt],     al[1], bh[0], bh[2]);
                mma_f16(acc[0][2 * nt + 1], al[0], bh[1], bh[3]);
                mma_f16(acc[1][2 * nt + 1], al[1], bh[1], bh[3]);
            }
        }
    }

    const int g = lane >> 2;
    const int tc2 = (lane & 3) << 1;
#pragma unroll
    for (int t = 0; t < 2; ++t) {
        const int row0 = bm * 128 + wm * 32 + t * 16 + g;
#pragma unroll
        for (int n = 0; n < 8; ++n) {
            const int col = bn * 128 + wn * 64 + n * 8 + tc2;
            *(float2*)(C + (size_t)row0 * N + col) = make_float2(acc[t][n][0], acc[t][n][1]);
            *(float2*)(C + (size_t)(row0 + 8) * N + col) = make_float2(acc[t][n][2], acc[t][n][3]);
        }
    }
}

// ---------------- elementwise split fp32 -> fp16 hi/lo ----------------------
__global__ __launch_bounds__(256) void split_f32h(const float* __restrict__ in,
                                                  f16* __restrict__ hi,
                                                  f16* __restrict__ lo)
{
    const size_t i4 = (size_t)blockIdx.x * 256 + threadIdx.x;
    float4 v = *(const float4*)(in + i4 * 4);
    f16 h[4], l[4];
    hsplit(v.x, h[0], l[0]); hsplit(v.y, h[1], l[1]);
    hsplit(v.z, h[2], l[2]); hsplit(v.w, h[3], l[3]);
    *(uint2*)(hi + i4 * 4) = *(uint2*)h;
    *(uint2*)(lo + i4 * 4) = *(uint2*)l;
}

// ---------------- transpose + round to single fp16 --------------------------
__global__ __launch_bounds__(256) void transpose_f16(const float* __restrict__ in,
                                                     f16* __restrict__ out,
                                                     int R, int Cc)
{
    __shared__ float t[32][33];
    const int c = blockIdx.x * 32 + threadIdx.x;
    const int r0 = blockIdx.y * 32 + threadIdx.y;
#pragma unroll
    for (int i = 0; i < 4; ++i)
        t[threadIdx.y + i * 8][threadIdx.x] = in[(size_t)(r0 + i * 8) * Cc + c];
    __syncthreads();
    const int rc = blockIdx.y * 32 + threadIdx.x;
    const int c0 = blockIdx.x * 32 + threadIdx.y;
#pragma unroll
    for (int i = 0; i < 4; ++i)
        out[(size_t)(c0 + i * 8) * R + rc] = __float2half_rn(t[threadIdx.x][threadIdx.y + i * 8]);
}

// ---------------- V transpose + split (bf16, attention path) ----------------
__global__ __launch_bounds__(256) void vt_split(const float* __restrict__ Vg,
                                                bf16* __restrict__ VtH,
                                                bf16* __restrict__ VtL)
{
    __shared__ float t[32][33];
    const int bh = blockIdx.z;
    const float* in = Vg + (size_t)bh * SEQ * HDIM;
    const int s0 = blockIdx.x * 32;
    const int d0 = blockIdx.y * 32;
#pragma unroll
    for (int i = 0; i < 4; ++i)
        t[threadIdx.y + i * 8][threadIdx.x] = in[(size_t)(s0 + threadIdx.y + i * 8) * HDIM + d0 + threadIdx.x];
    __syncthreads();
    bf16* oh = VtH + (size_t)bh * HDIM * SEQ;
    bf16* ol = VtL + (size_t)bh * HDIM * SEQ;
#pragma unroll
    for (int i = 0; i < 4; ++i) {
        float v = t[threadIdx.x][threadIdx.y + i * 8];
        bf16 h, l;
        bfsplit(v, h, l);
        oh[(size_t)(d0 + threadIdx.y + i * 8) * SEQ + s0 + threadIdx.x] = h;
        ol[(size_t)(d0 + threadIdx.y + i * 8) * SEQ + s0 + threadIdx.x] = l;
    }
}

// ---------------- RoPE (NeoX) + split (bf16, attention path) ----------------
__global__ __launch_bounds__(128) void rope_split2(const float* __restrict__ qkv,
                                                   const int* __restrict__ pos_ids,
                                                   bf16* __restrict__ QH, bf16* __restrict__ QL,
                                                   bf16* __restrict__ KH, bf16* __restrict__ KL,
                                                   float* __restrict__ Vh)
{
    const int token = blockIdx.x;
    const int b = token / SEQ;
    const int s = token % SEQ;
    __shared__ float cs[64], sn[64];
    const int tid = threadIdx.x;
    if (tid < 64) {
        double inv = exp(-9.210340371976184 * ((double)(2 * tid) / 128.0));
        double ang = (double)pos_ids[token] * inv;
        cs[tid] = (float)cos(ang);
        sn[tid] = (float)sin(ang);
    }
    __syncthreads();
    const float* base = qkv + (size_t)token * QKVN;

    for (int p = tid; p < NHEAD * 64; p += 128) {
        int h = p >> 6;
        int i = p & 63;
        float c = cs[i], sv = sn[i];
        size_t ob = ((size_t)(b * NHEAD + h) * SEQ + s) * HDIM;
        float q1 = base[h * HDIM + i];
        float q2 = base[h * HDIM + 64 + i];
        float r1 = q1 * c - q2 * sv;
        float r2 = q2 * c + q1 * sv;
        bf16 hh, ll;
        bfsplit(r1, hh, ll); QH[ob + i] = hh;      QL[ob + i] = ll;
        bfsplit(r2, hh, ll); QH[ob + 64 + i] = hh; QL[ob + 64 + i] = ll;
        float k1 = base[HID + h * HDIM + i];
        float k2 = base[HID + h * HDIM + 64 + i];
        r1 = k1 * c - k2 * sv;
        r2 = k2 * c + k1 * sv;
        bfsplit(r1, hh, ll); KH[ob + i] = hh;      KL[ob + i] = ll;
        bfsplit(r2, hh, ll); KH[ob + 64 + i] = hh; KL[ob + 64 + i] = ll;
    }
    for (int p = tid; p < HID; p += 128) {
        int h = p >> 7;
        int d = p & 127;
        Vh[((size_t)(b * NHEAD + h) * SEQ + s) * HDIM + d] = base[2 * HID + p];
    }
}

// ---------------- tensor-core flash attention (causal, bf16x3) --------------
#define QSTR 136
#define VSTR 72
#define oQH 0
#define oQL (oQH + 128 * QSTR * 2)
#define oKH (oQL + 128 * QSTR * 2)
#define oKL (oKH + 2 * 64 * QSTR * 2)
#define oVH (oKL + 2 * 64 * QSTR * 2)
#define oVL (oVH + 2 * 128 * VSTR * 2)
#define ATT_SMEM (oVL + 2 * 128 * VSTR * 2)

__global__ __launch_bounds__(256, 1) void flash_mma(const bf16* __restrict__ QHg,
                                                    const bf16* __restrict__ QLg,
                                                    const bf16* __restrict__ KHg,
                                                    const bf16* __restrict__ KLg,
                                                    const bf16* __restrict__ VtHg,
                                                    const bf16* __restrict__ VtLg,
                                                    f16* __restrict__ attnH,
                                                    f16* __restrict__ attnL)
{
    extern __shared__ char asm_buf[];
    const uint32_t sb = smem_u32_of(asm_buf);

    const int tid = threadIdx.x;
    const int warp = tid >> 5, lane = tid & 31;
    const int g = lane >> 2;
    const int lam = lane & 3;
    const int lrow = lane & 15;
    const int lkh = (lane >> 4) << 3;

    const int qt = (int)(gridDim.x - 1 - blockIdx.x);
    const int h = blockIdx.y;
    const int b = blockIdx.z;
    const int qb = qt * 128;
    const size_t hoff = (size_t)(b * NHEAD + h) * SEQ * HDIM;
    const size_t voff = (size_t)(b * NHEAD + h) * HDIM * SEQ;

#pragma unroll
    for (int j = 0; j < 8; ++j) {
        const int i = tid + j * 256;
        const int row = i >> 4;
        const int seg = (i & 15) << 3;
        const uint32_t doff = (uint32_t)(row * QSTR + seg) * 2;
        const size_t soff = hoff + (size_t)(qb + row) * HDIM + seg;
        cp16(sb + oQH + doff, QHg + soff);
        cp16(sb + oQL + doff, QLg + soff);
    }
    cp_commit();

    const int ktmax = 2 * qt + 1;

    auto issueKV = [&](int kt, int buf) {
        const int kb = kt * 64;
#pragma unroll
        for (int j = 0; j < 4; ++j) {
            const int i = tid + j * 256;
            const int krow = i >> 4;
            const int kseg = (i & 15) << 3;
            const uint32_t kdoff = (uint32_t)(krow * QSTR + kseg) * 2;
            const size_t ksoff = hoff + (size_t)(kb + krow) * HDIM + kseg;
            cp16(sb + oKH + buf * (64 * QSTR * 2) + kdoff, KHg + ksoff);
            cp16(sb + oKL + buf * (64 * QSTR * 2) + kdoff, KLg + ksoff);
            const int vrow = i >> 3;
            const int vseg = (i & 7) << 3;
            const uint32_t vdoff = (uint32_t)(vrow * VSTR + vseg) * 2;
            const size_t vsoff = voff + (size_t)vrow * SEQ + kb + vseg;
            cp16(sb + oVH + buf * (128 * VSTR * 2) + vdoff, VtHg + vsoff);
            cp16(sb + oVL + buf * (128 * VSTR * 2) + vdoff, VtLg + vsoff);
        }
    };

    issueKV(0, 0);
    cp_commit();

    float oacc[16][4];
#pragma unroll
    for (int n = 0; n < 16; ++n)
#pragma unroll
        for (int i = 0; i < 4; ++i) oacc[n][i] = 0.f;
    float m0 = -1e30f, m1 = -1e30f, l0 = 0.f, l1 = 0.f;
    const float scale2 = 0.1275174324f;   // (1/sqrt(128)) * log2(e)

    const int r0g = qb + warp * 16 + g;
    const int r1g = r0g + 8;

    for (int kt = 0; kt <= ktmax; ++kt) {
        const int kb = kt * 64;
        const int buf = kt & 1;

        cp_wait<0>();
        __syncthreads();
        if (kt < ktmax) { issueKV(kt + 1, buf ^ 1); cp_commit(); }

        const uint32_t uQH = sb + oQH, uQL = sb + oQL;
        const uint32_t uKH = sb + oKH + buf * (64 * QSTR * 2);
        const uint32_t uKL = sb + oKL + buf * (64 * QSTR * 2);
        const uint32_t uVH = sb + oVH + buf * (128 * VSTR * 2);
        const uint32_t uVL = sb + oVL + buf * (128 * VSTR * 2);

        float sacc[8][4];
#pragma unroll
        for (int n = 0; n < 8; ++n)
#pragma unroll
            for (int i = 0; i < 4; ++i) sacc[n][i] = 0.f;

#pragma unroll
        for (int ks = 0; ks < 8; ++ks) {
            uint32_t ah[4], al[4];
            const uint32_t aoff = (uint32_t)(((warp * 16 + lrow) * QSTR + ks * 16 + lkh) * 2);
            ldm_x4(ah, uQH + aoff);
            ldm_x4(al, uQL + aoff);
#pragma unroll
            for (int ntp = 0; ntp < 2; ++ntp) {
                const int nt0 = 2 * ntp, nt1 = 2 * ntp + 1;
                uint32_t bh0[4], bl0[4], bh1[4], bl1[4];
                const uint32_t b0off = (uint32_t)(((nt0 * 16 + lrow) * QSTR + ks * 16 + lkh) * 2);
                const uint32_t b1off = (uint32_t)(((nt1 * 16 + lrow) * QSTR + ks * 16 + lkh) * 2);
                ldm_x4(bh0, uKH + b0off);
                ldm_x4(bl0, uKL + b0off);
                ldm_x4(bh1, uKH + b1off);
                ldm_x4(bl1, uKL + b1off);
                mma_bf16(sacc[2 * nt0],     ah, bh0[0], bh0[2]);
                mma_bf16(sacc[2 * nt0 + 1], ah, bh0[1], bh0[3]);
                mma_bf16(sacc[2 * nt1],     ah, bh1[0], bh1[2]);
                mma_bf16(sacc[2 * nt1 + 1], ah, bh1[1], bh1[3]);
                mma_bf16(sacc[2 * nt0],     ah, bl0[0], bl0[2]);
                mma_bf16(sacc[2 * nt0 + 1], ah, bl0[1], bl0[3]);
                mma_bf16(sacc[2 * nt1],     ah, bl1[0], bl1[2]);
                mma_bf16(sacc[2 * nt1 + 1], ah, bl1[1], bl1[3]);
                mma_bf16(sacc[2 * nt0],     al, bh0[0], bh0[2]);
                mma_bf16(sacc[2 * nt0 + 1], al, bh0[1], bh0[3]);
                mma_bf16(sacc[2 * nt1],     al, bh1[0], bh1[2]);
                mma_bf16(sacc[2 * nt1 + 1], al, bh1[1], bh1[3]);
            }
        }

        const bool need_mask = (kt >= 2 * qt);
        float rm0 = -1e30f, rm1 = -1e30f;
#pragma unroll
        for (int j = 0; j < 8; ++j) {
            const int cg0 = kb + j * 8 + 2 * lam;
#pragma unroll
            for (int i = 0; i < 4; ++i) {
                float v = sacc[j][i] * scale2;
                if (need_mask) {
                    const int cg = cg0 + (i & 1);
                    const int rg = (i < 2) ? r0g : r1g;
                    if (cg > rg) v = -1e30f;
                }
                sacc[j][i] = v;
            }
            rm0 = fmaxf(rm0, fmaxf(sacc[j][0], sacc[j][1]));
            rm1 = fmaxf(rm1, fmaxf(sacc[j][2], sacc[j][3]));
        }
#pragma unroll
        for (int off = 1; off <= 2; off <<= 1) {
            rm0 = fmaxf(rm0, __shfl_xor_sync(0xffffffffu, rm0, off));
            rm1 = fmaxf(rm1, __shfl_xor_sync(0xffffffffu, rm1, off));
        }
        const float mn0 = fmaxf(m0, rm0);
        const float mn1 = fmaxf(m1, rm1);
        const float al0 = exp2f(m0 - mn0);
        const float al1 = exp2f(m1 - mn1);
        m0 = mn0; m1 = mn1;

        float rs0 = 0.f, rs1 = 0.f;
#pragma unroll
        for (int j = 0; j < 8; ++j) {
            sacc[j][0] = exp2f(sacc[j][0] - mn0);
            sacc[j][1] = exp2f(sacc[j][1] - mn0);
            sacc[j][2] = exp2f(sacc[j][2] - mn1);
            sacc[j][3] = exp2f(sacc[j][3] - mn1);
            rs0 += sacc[j][0] + sacc[j][1];
            rs1 += sacc[j][2] + sacc[j][3];
        }
#pragma unroll
        for (int off = 1; off <= 2; off <<= 1) {
            rs0 += __shfl_xor_sync(0xffffffffu, rs0, off);
            rs1 += __shfl_xor_sync(0xffffffffu, rs1, off);
        }
        l0 = l0 * al0 + rs0;
        l1 = l1 * al1 + rs1;

#pragma unroll
        for (int n = 0; n < 16; ++n) {
            oacc[n][0] *= al0; oacc[n][1] *= al0;
            oacc[n][2] *= al1; oacc[n][3] *= al1;
        }

        uint32_t pah[4][4], pal[4][4];
#pragma unroll
        for (int j2 = 0; j2 < 4; ++j2) {
            float p00 = sacc[2 * j2][0],     p01 = sacc[2 * j2][1];
            float p02 = sacc[2 * j2][2],     p03 = sacc[2 * j2][3];
            float p10 = sacc[2 * j2 + 1][0], p11 = sacc[2 * j2 + 1][1];
            float p12 = sacc[2 * j2 + 1][2], p13 = sacc[2 * j2 + 1][3];
            pah[j2][0] = pk2(p00, p01);
            pah[j2][1] = pk2(p02, p03);
            pah[j2][2] = pk2(p10, p11);
            pah[j2][3] = pk2(p12, p13);
            bf16 hh;
            hh = __float2bfloat16_rn(p00); p00 -= __bfloat162float(hh);
            hh = __float2bfloat16_rn(p01); p01 -= __bfloat162float(hh);
            hh = __float2bfloat16_rn(p02); p02 -= __bfloat162float(hh);
            hh = __float2bfloat16_rn(p03); p03 -= __bfloat162float(hh);
            hh = __float2bfloat16_rn(p10); p10 -= __bfloat162float(hh);
            hh = __float2bfloat16_rn(p11); p11 -= __bfloat162float(hh);
            hh = __float2bfloat16_rn(p12); p12 -= __bfloat162float(hh);
            hh = __float2bfloat16_rn(p13); p13 -= __bfloat162float(hh);
            pal[j2][0] = pk2(p00, p01);
            pal[j2][1] = pk2(p02, p03);
            pal[j2][2] = pk2(p10, p11);
            pal[j2][3] = pk2(p12, p13);
        }

#pragma unroll
        for (int ntp = 0; ntp < 4; ++ntp) {
            const int nt0 = 2 * ntp, nt1 = 2 * ntp + 1;
#pragma unroll
            for (int j2 = 0; j2 < 4; ++j2) {
                uint32_t vh0[4], vl0[4], vh1[4], vl1[4];
                const uint32_t v0off = (uint32_t)(((nt0 * 16 + lrow) * VSTR + j2 * 16 + lkh) * 2);
                const uint32_t v1off = (uint32_t)(((nt1 * 16 + lrow) * VSTR + j2 * 16 + lkh) * 2);
                ldm_x4(vh0, uVH + v0off);
                ldm_x4(vl0, uVL + v0off);
                ldm_x4(vh1, uVH + v1off);
                ldm_x4(vl1, uVL + v1off);
                mma_bf16(oacc[2 * nt0],     pah[j2], vh0[0], vh0[2]);
                mma_bf16(oacc[2 * nt0 + 1], pah[j2], vh0[1], vh0[3]);
                mma_bf16(oacc[2 * nt1],     pah[j2], vh1[0], vh1[2]);
                mma_bf16(oacc[2 * nt1 + 1], pah[j2], vh1[1], vh1[3]);
                mma_bf16(oacc[2 * nt0],     pah[j2], vl0[0], vl0[2]);
                mma_bf16(oacc[2 * nt0 + 1], pah[j2], vl0[1], vl0[3]);
                mma_bf16(oacc[2 * nt1],     pah[j2], vl1[0], vl1[2]);
                mma_bf16(oacc[2 * nt1 + 1], pah[j2], vl1[1], vl1[3]);
                mma_bf16(oacc[2 * nt0],     pal[j2], vh0[0], vh0[2]);
                mma_bf16(oacc[2 * nt0 + 1], pal[j2], vh0[1], vh0[3]);
                mma_bf16(oacc[2 * nt1],     pal[j2], vh1[0], vh1[2]);
                mma_bf16(oacc[2 * nt1 + 1], pal[j2], vh1[1], vh1[3]);
            }
        }
    }

    // epilogue: normalize, split to fp16 hi/lo for the O-proj
    const float i0 = 1.0f / l0;
    const float i1 = 1.0f / l1;
    const size_t row0 = ((size_t)b * SEQ + r0g) * HID + h * HDIM;
    const size_t row1 = ((size_t)b * SEQ + r1g) * HID + h * HDIM;
#pragma unroll
    for (int n = 0; n < 16; ++n) {
        const int col = n * 8 + 2 * lam;
        float x0 = oacc[n][0] * i0, x1 = oacc[n][1] * i0;
        float y0 = oacc[n][2] * i1, y1 = oacc[n][3] * i1;
        *(uint32_t*)(attnH + row0 + col) = pk2h(x0, x1);
        *(uint32_t*)(attnH + row1 + col) = pk2h(y0, y1);
        f16 hb;
        hb = __float2half_rn(x0); x0 -= __half2float(hb);
        hb = __float2half_rn(x1); x1 -= __half2float(hb);
        hb = __float2half_rn(y0); y0 -= __half2float(hb);
        hb = __float2half_rn(y1); y1 -= __half2float(hb);
        *(uint32_t*)(attnL + row0 + col) = pk2h(x0, x1);
        *(uint32_t*)(attnL + row1 + col) = pk2h(y0, y1);
    }
}

// ---------------------------------------------------------------------------
extern "C" void kernel_launch(void* const* d_in, const int* in_sizes, int n_in,
                              void* d_out, int out_size)
{
    (void)in_sizes; (void)n_in; (void)out_size;
    const float* hidden = (const float*)d_in[0];
    const float* w_qkv  = (const float*)d_in[1];
    const float* w_o    = (const float*)d_in[2];
    const int*   pos    = (const int*)d_in[3];
    float* out = (float*)d_out;

    float *qkv, *v;
    f16 *hidH, *hidL, *wqkvt, *wot, *attnH, *attnL;
    bf16 *QH, *QL, *KH, *KL, *VtH, *VtL;
    cudaGetSymbolAddress((void**)&qkv,   g_qkv);
    cudaGetSymbolAddress((void**)&v,     g_v);
    cudaGetSymbolAddress((void**)&hidH,  g_hidH);
    cudaGetSymbolAddress((void**)&hidL,  g_hidL);
    cudaGetSymbolAddress((void**)&wqkvt, g_wqkvt);
    cudaGetSymbolAddress((void**)&wot,   g_wot);
    cudaGetSymbolAddress((void**)&QH,    g_QH);
    cudaGetSymbolAddress((void**)&QL,    g_QL);
    cudaGetSymbolAddress((void**)&KH,    g_KH);
    cudaGetSymbolAddress((void**)&KL,    g_KL);
    cudaGetSymbolAddress((void**)&VtH,   g_VtH);
    cudaGetSymbolAddress((void**)&VtL,   g_VtL);
    cudaGetSymbolAddress((void**)&attnH, g_attnH);
    cudaGetSymbolAddress((void**)&attnL, g_attnL);

    // 0) pre-split activations (fp16 hi/lo) + transpose weights (single fp16)
    split_f32h<<<(TOKENS * HID) / 1024, 256>>>(hidden, hidH, hidL);
    transpose_f16<<<dim3(QKVN / 32, HID / 32), dim3(32, 8)>>>(w_qkv, wqkvt, HID, QKVN);
    transpose_f16<<<dim3(HID / 32, HID / 32), dim3(32, 8)>>>(w_o, wot, HID, HID);

    const int gsmem = NSTG * STG_BYTES;   // 98304 -> 2 CTAs/SM
    cudaFuncSetAttribute(gemm_f16x2, cudaFuncAttributeMaxDynamicSharedMemorySize, gsmem);

    // 1) QKV projection (fp16 2-term)
    gemm_f16x2<<<(TOKENS / 128) * (QKVN / 128), 256, gsmem>>>(
        hidH, hidL, wqkvt, qkv, TOKENS, QKVN, HID, TOKENS / 128);

    // 2) RoPE + split to head-major bf16; V fp32 head-major
    rope_split2<<<TOKENS, 128>>>(qkv, pos, QH, QL, KH, KL, v);

    // 3) V transpose + split per head
    vt_split<<<dim3(SEQ / 32, HDIM / 32, HEADS), dim3(32, 8)>>>(v, VtH, VtL);

    // 4) tensor-core causal flash attention -> fp16-split attn
    cudaFuncSetAttribute(flash_mma, cudaFuncAttributeMaxDynamicSharedMemorySize, ATT_SMEM);
    flash_mma<<<dim3(SEQ / 128, NHEAD, BATCH), 256, ATT_SMEM>>>(
        QH, QL, KH, KL, VtH, VtL, attnH, attnL);

    // 5) output projection (fp16 2-term)
    gemm_f16x2<<<(TOKENS / 128) * (HID / 128), 256, gsmem>>>(
        attnH, attnL, wot, out, TOKENS, HID, HID, TOKENS / 128);
}